// round 1
// baseline (speedup 1.0000x reference)
#include <cuda_runtime.h>
#include <cuda_bf16.h>
#include <math.h>

// ---------------- static config ----------------
#define BQ 8
#define FD 128
#define PW 16
#define NHW 8
#define NTOK 256
#define HH 8
#define AD 32
#define CC 32
#define INNER 128
#define NWIN (BQ*NHW*NHW)       // 512 windows
#define NTOKENS (BQ*FD*FD)      // 131072 tokens

// ---------------- scratch (device globals; no allocation) ----------------
__device__ float g_hwin[NWIN*NTOK*CC];          // 16.8 MB
__device__ float g_oheads[(size_t)NWIN*NTOK*HH*AD]; // 134 MB
__device__ float g_xres[(size_t)NTOKENS*CC];    // 16.8 MB
__device__ float g_y1[(size_t)NTOKENS*INNER];   // 67 MB
__device__ float g_y2[(size_t)NTOKENS*INNER];   // 67 MB

__device__ __forceinline__ float gelu_exact(float x) {
    return 0.5f * x * (1.0f + erff(x * 0.70710678118654752440f));
}

// ================= Kernel 1: LN1 + shift + window partition + modulator ==
__global__ void k_ln1(const float* __restrict__ x, const float* __restrict__ g1,
                      const float* __restrict__ b1, const float* __restrict__ modw) {
    int w = blockIdx.x;          // 0..511
    int n = threadIdx.x;         // 0..255
    int b = w >> 6, ww = w & 63;
    int wy = ww >> 3, wx = ww & 7;
    int iy = n >> 4, ix = n & 15;
    int ry = wy * 16 + iy, rx = wx * 16 + ix;
    int y = (ry + 8) & 127, xx = (rx + 8) & 127;   // roll(-8,-8): rolled[r] = orig[r+8]
    const float* xp = x + ((size_t)b * 16384 + (size_t)y * 128 + xx) * CC;

    float v[CC];
#pragma unroll
    for (int i = 0; i < 8; i++) {
        float4 t = ((const float4*)xp)[i];
        v[4*i] = t.x; v[4*i+1] = t.y; v[4*i+2] = t.z; v[4*i+3] = t.w;
    }
    float mean = 0.f;
#pragma unroll
    for (int c = 0; c < CC; c++) mean += v[c];
    mean *= (1.0f / CC);
    float var = 0.f;
#pragma unroll
    for (int c = 0; c < CC; c++) { float d = v[c] - mean; var += d * d; }
    var *= (1.0f / CC);
    float rstd = rsqrtf(var + 1e-5f);

    float* op = g_hwin + ((size_t)w * NTOK + n) * CC;
#pragma unroll
    for (int i = 0; i < 8; i++) {
        float4 o;
        int c = 4 * i;
        o.x = (v[c+0]-mean)*rstd*g1[c+0] + b1[c+0] + modw[n*CC + c+0];
        o.y = (v[c+1]-mean)*rstd*g1[c+1] + b1[c+1] + modw[n*CC + c+1];
        o.z = (v[c+2]-mean)*rstd*g1[c+2] + b1[c+2] + modw[n*CC + c+2];
        o.w = (v[c+3]-mean)*rstd*g1[c+3] + b1[c+3] + modw[n*CC + c+3];
        ((float4*)op)[i] = o;
    }
}

// ================= Kernel 2: fused QKV + flash window attention ==========
// One block per (window, head). 256 threads, thread = query token.
#define KV_STRIDE 36   // padded row stride (floats), 16B aligned, conflict-mitigating
__global__ void __launch_bounds__(256) k_attn(const float* __restrict__ qkvw,
                                              const float* __restrict__ qkvb,
                                              const float* __restrict__ rpbt) {
    extern __shared__ float sm[];
    float* sh_k   = sm;                        // 256*36
    float* sh_v   = sh_k + NTOK * KV_STRIDE;   // 256*36
    float* sh_wq  = sh_v + NTOK * KV_STRIDE;   // 1024
    float* sh_wk  = sh_wq + 1024;              // 1024
    float* sh_wv  = sh_wk + 1024;              // 1024
    float* sh_b   = sh_wv + 1024;              // 96
    float* sh_rpb = sh_b + 96;                 // 964 (961 used)
    int*   sh_rid = (int*)(sh_rpb + 964);      // 256

    int w  = blockIdx.x >> 3;
    int hh = blockIdx.x & 7;
    int tid = threadIdx.x;

    // weights slices for this head
    for (int i = tid; i < 1024; i += 256) {
        int c = i >> 5, a = i & 31;
        sh_wq[i] = qkvw[c * 768 +       hh * 32 + a];
        sh_wk[i] = qkvw[c * 768 + 256 + hh * 32 + a];
        sh_wv[i] = qkvw[c * 768 + 512 + hh * 32 + a];
    }
    if (tid < 32) {
        sh_b[tid]      = qkvb[      hh * 32 + tid];
        sh_b[32 + tid] = qkvb[256 + hh * 32 + tid];
        sh_b[64 + tid] = qkvb[512 + hh * 32 + tid];
    }
    for (int i = tid; i < 961; i += 256) sh_rpb[i] = rpbt[i * 8 + hh];
    {
        int n = tid;
        int ww = w & 63;
        int ry = (ww >> 3) * 16 + (n >> 4);
        int rx = (ww & 7)  * 16 + (n & 15);
        int hr = ry < 112 ? 0 : (ry < 120 ? 1 : 2);
        int wr = rx < 112 ? 0 : (rx < 120 ? 1 : 2);
        sh_rid[n] = hr * 3 + wr;
    }

    // my h row (registers)
    float hreg[CC];
    {
        const float4* hp = (const float4*)(g_hwin + ((size_t)w * NTOK + tid) * CC);
#pragma unroll
        for (int i = 0; i < 8; i++) {
            float4 t = hp[i];
            hreg[4*i] = t.x; hreg[4*i+1] = t.y; hreg[4*i+2] = t.z; hreg[4*i+3] = t.w;
        }
    }
    __syncthreads();

    // Q (regs, scaled)
    float q[AD];
#pragma unroll
    for (int a = 0; a < AD; a++) q[a] = sh_b[a];
#pragma unroll
    for (int c = 0; c < CC; c++) {
        float hc = hreg[c];
#pragma unroll
        for (int a = 0; a < AD; a++) q[a] += hc * sh_wq[c * 32 + a];
    }
#pragma unroll
    for (int a = 0; a < AD; a++) q[a] *= 0.17677669529663688f; // 1/sqrt(32)

    // K, V into smem
    {
        float tmp[AD];
#pragma unroll
        for (int a = 0; a < AD; a++) tmp[a] = sh_b[32 + a];
#pragma unroll
        for (int c = 0; c < CC; c++) {
            float hc = hreg[c];
#pragma unroll
            for (int a = 0; a < AD; a++) tmp[a] += hc * sh_wk[c * 32 + a];
        }
#pragma unroll
        for (int a = 0; a < AD; a++) sh_k[tid * KV_STRIDE + a] = tmp[a];

#pragma unroll
        for (int a = 0; a < AD; a++) tmp[a] = sh_b[64 + a];
#pragma unroll
        for (int c = 0; c < CC; c++) {
            float hc = hreg[c];
#pragma unroll
            for (int a = 0; a < AD; a++) tmp[a] += hc * sh_wv[c * 32 + a];
        }
#pragma unroll
        for (int a = 0; a < AD; a++) sh_v[tid * KV_STRIDE + a] = tmp[a];
    }
    __syncthreads();

    // streaming softmax over keys
    int iy = tid >> 4, ix = tid & 15;
    int myrid = sh_rid[tid];
    int rbase = (iy + 15) * 31 + (ix + 15);
    float rmax = -1e30f, rsum = 0.f;
    float acc[AD];
#pragma unroll
    for (int a = 0; a < AD; a++) acc[a] = 0.f;

    for (int m = 0; m < NTOK; ++m) {
        const float4* kr = (const float4*)(sh_k + m * KV_STRIDE);
        float s0 = 0.f, s1 = 0.f;
#pragma unroll
        for (int i = 0; i < 8; i += 2) {
            float4 k0 = kr[i], k1 = kr[i+1];
            s0 += q[4*i+0]*k0.x + q[4*i+1]*k0.y + q[4*i+2]*k0.z + q[4*i+3]*k0.w;
            s1 += q[4*i+4]*k1.x + q[4*i+5]*k1.y + q[4*i+6]*k1.z + q[4*i+7]*k1.w;
        }
        float s = s0 + s1;
        int my = m >> 4, mx = m & 15;
        s += sh_rpb[rbase - my * 31 - mx];
        if (myrid != sh_rid[m]) s -= 100.0f;

        if (s > rmax) {
            float f = __expf(rmax - s);
            rsum *= f;
#pragma unroll
            for (int a = 0; a < AD; a++) acc[a] *= f;
            rmax = s;
        }
        float p = __expf(s - rmax);
        rsum += p;
        const float4* vr = (const float4*)(sh_v + m * KV_STRIDE);
#pragma unroll
        for (int i = 0; i < 8; i++) {
            float4 vv = vr[i];
            acc[4*i+0] += p * vv.x; acc[4*i+1] += p * vv.y;
            acc[4*i+2] += p * vv.z; acc[4*i+3] += p * vv.w;
        }
    }

    float inv = 1.0f / rsum;
    float* op = g_oheads + ((size_t)w * NTOK + tid) * (HH * AD) + hh * AD;
#pragma unroll
    for (int i = 0; i < 8; i++) {
        float4 o;
        o.x = acc[4*i+0]*inv; o.y = acc[4*i+1]*inv;
        o.z = acc[4*i+2]*inv; o.w = acc[4*i+3]*inv;
        ((float4*)op)[i] = o;
    }
}

// ================= Kernel 3: rev projection + window reverse + residual ==
__global__ void k_rev(const float* __restrict__ x, const float* __restrict__ revw,
                      const float* __restrict__ revb) {
    __shared__ float sh_w[256 * 32];  // 32 KB
    __shared__ float sh_o[8][256];    // 8 KB
    int tid = threadIdx.x;
    for (int i = tid; i < 8192; i += 256) sh_w[i] = revw[i];

    int warp = tid >> 5, lane = tid & 31;
    long t = (long)blockIdx.x * 8 + warp;
    {
        int b = (int)(t >> 14), p = (int)(t & 16383);
        int y = p >> 7, xx = p & 127;
        int ry = (y + 120) & 127, rx = (xx + 120) & 127;   // reverse roll(+8,+8)
        int w = b * 64 + (ry >> 4) * 8 + (rx >> 4);
        int n = (ry & 15) * 16 + (rx & 15);
        const float4* op4 = (const float4*)(g_oheads + ((size_t)w * NTOK + n) * 256);
        ((float4*)sh_o[warp])[lane]      = op4[lane];
        ((float4*)sh_o[warp])[lane + 32] = op4[lane + 32];
    }
    __syncthreads();

    float accv = revb[lane];
    const float* orow = sh_o[warp];
#pragma unroll 8
    for (int k = 0; k < 256; k++) accv += orow[k] * sh_w[k * 32 + lane];
    g_xres[(size_t)t * 32 + lane] = x[(size_t)t * 32 + lane] + accv;
}

// ================= Kernel 4: LN2 + lp1 (32->128) + GELU ==================
__global__ void k_lp1(const float* __restrict__ n2g, const float* __restrict__ n2b,
                      const float* __restrict__ w1, const float* __restrict__ bb1) {
    __shared__ float sh_w[32 * 128]; // 16 KB
    __shared__ float sh_b[128];
    int tid = threadIdx.x;
    for (int i = tid; i < 4096; i += 256) sh_w[i] = w1[i];
    if (tid < 128) sh_b[tid] = bb1[tid];
    __syncthreads();

    int warp = tid >> 5, lane = tid & 31;
    long t = (long)blockIdx.x * 8 + warp;
    float v = g_xres[(size_t)t * 32 + lane];

    float s = v;
#pragma unroll
    for (int o = 16; o; o >>= 1) s += __shfl_xor_sync(0xffffffffu, s, o);
    float mean = s * (1.0f / 32.0f);
    float d = v - mean;
    float ss = d * d;
#pragma unroll
    for (int o = 16; o; o >>= 1) ss += __shfl_xor_sync(0xffffffffu, ss, o);
    float rstd = rsqrtf(ss * (1.0f / 32.0f) + 1e-5f);
    float hn = d * rstd * n2g[lane] + n2b[lane];

    float4 acc = ((const float4*)sh_b)[lane];
#pragma unroll
    for (int c = 0; c < 32; c++) {
        float hc = __shfl_sync(0xffffffffu, hn, c);
        float4 wv = ((const float4*)sh_w)[c * 32 + lane];
        acc.x += hc * wv.x; acc.y += hc * wv.y;
        acc.z += hc * wv.z; acc.w += hc * wv.w;
    }
    float4 r;
    r.x = gelu_exact(acc.x); r.y = gelu_exact(acc.y);
    r.z = gelu_exact(acc.z); r.w = gelu_exact(acc.w);
    ((float4*)(g_y1 + (size_t)t * 128))[lane] = r;
}

// ================= Kernel 5: 3x3 conv 128->128 SAME + bias + GELU ========
// Block: 8x8 spatial x 128 co. warp = 16-co group (weight reads broadcast).
#define CONV_IN_STRIDE 100
__global__ void __launch_bounds__(256) k_conv(const float* __restrict__ cw,
                                              const float* __restrict__ cb) {
    extern __shared__ float sm[];
    float* sh_in = sm;                 // 16 * 100 floats, layout [cc][pixel]
    float* sh_w  = sm + 16 * CONV_IN_STRIDE; // [tap*16+cc][128]

    int bz = blockIdx.x;
    int b  = bz >> 8;
    int ty0 = ((bz >> 4) & 15) * 8;
    int tx0 = (bz & 15) * 8;
    int tid = threadIdx.x;
    int cg = tid >> 5, lane = tid & 31;
    int co0 = cg * 16;

    float acc[2][16];
#pragma unroll
    for (int s = 0; s < 2; s++)
#pragma unroll
        for (int j = 0; j < 16; j++) acc[s][j] = 0.f;

    int p0 = 2 * lane;
    int py0_ = p0 >> 3, px0_ = p0 & 7;
    int py1_ = (p0 + 1) >> 3, px1_ = (p0 + 1) & 7;

    for (int ci0 = 0; ci0 < 128; ci0 += 16) {
        __syncthreads();
        // input tile 10x10x16 (zero-padded), cc-major
        for (int i = tid; i < 400; i += 256) {
            int pix = i >> 2, qq = i & 3;
            int py = pix / 10, px = pix - py * 10;
            int gy = ty0 - 1 + py, gx = tx0 - 1 + px;
            float4 val = make_float4(0.f, 0.f, 0.f, 0.f);
            if ((unsigned)gy < 128u && (unsigned)gx < 128u)
                val = *(const float4*)(g_y1 + (((size_t)b * 16384 + (size_t)gy * 128 + gx) * 128 + ci0 + qq * 4));
            sh_in[(qq*4+0) * CONV_IN_STRIDE + pix] = val.x;
            sh_in[(qq*4+1) * CONV_IN_STRIDE + pix] = val.y;
            sh_in[(qq*4+2) * CONV_IN_STRIDE + pix] = val.z;
            sh_in[(qq*4+3) * CONV_IN_STRIDE + pix] = val.w;
        }
        // weights chunk: 9 taps x 16 ci x 128 co
        for (int i = tid; i < 4608; i += 256) {
            int row = i >> 5, f4 = i & 31;
            int tap = row >> 4, ccx = row & 15;
            ((float4*)sh_w)[row * 32 + f4] =
                ((const float4*)cw)[((size_t)tap * 128 + ci0 + ccx) * 32 + f4];
        }
        __syncthreads();

#pragma unroll
        for (int ky = 0; ky < 3; ky++)
#pragma unroll
        for (int kx = 0; kx < 3; kx++) {
            int L0 = (py0_ + ky) * 10 + px0_ + kx;
            int L1 = (py1_ + ky) * 10 + px1_ + kx;
            int tap = ky * 3 + kx;
#pragma unroll
            for (int ccx = 0; ccx < 16; ccx++) {
                float i0 = sh_in[ccx * CONV_IN_STRIDE + L0];
                float i1 = sh_in[ccx * CONV_IN_STRIDE + L1];
                const float4* wr = (const float4*)(sh_w + (tap * 16 + ccx) * 128 + co0);
#pragma unroll
                for (int j = 0; j < 4; j++) {
                    float4 wv = wr[j];
                    acc[0][4*j+0] += i0 * wv.x; acc[0][4*j+1] += i0 * wv.y;
                    acc[0][4*j+2] += i0 * wv.z; acc[0][4*j+3] += i0 * wv.w;
                    acc[1][4*j+0] += i1 * wv.x; acc[1][4*j+1] += i1 * wv.y;
                    acc[1][4*j+2] += i1 * wv.z; acc[1][4*j+3] += i1 * wv.w;
                }
            }
        }
    }

#pragma unroll
    for (int s = 0; s < 2; s++) {
        int pix = 2 * lane + s;
        int gy = ty0 + (pix >> 3), gx = tx0 + (pix & 7);
        float* op = g_y2 + (((size_t)b * 16384 + (size_t)gy * 128 + gx) * 128 + co0);
#pragma unroll
        for (int j = 0; j < 16; j += 4) {
            float4 r;
            r.x = gelu_exact(acc[s][j+0] + cb[co0+j+0]);
            r.y = gelu_exact(acc[s][j+1] + cb[co0+j+1]);
            r.z = gelu_exact(acc[s][j+2] + cb[co0+j+2]);
            r.w = gelu_exact(acc[s][j+3] + cb[co0+j+3]);
            *(float4*)(op + j) = r;
        }
    }
}

// ================= Kernel 6: lp2 (128->32) + GELU + residual =============
__global__ void k_lp2(const float* __restrict__ w2, const float* __restrict__ b2,
                      float* __restrict__ out) {
    __shared__ float sh_w[128 * 32];   // 16 KB
    __shared__ float sh_row[8][132];
    int tid = threadIdx.x;
    for (int i = tid; i < 4096; i += 256) sh_w[i] = w2[i];

    int warp = tid >> 5, lane = tid & 31;
    long t = (long)blockIdx.x * 8 + warp;
    float4 v = ((const float4*)(g_y2 + (size_t)t * 128))[lane];
    sh_row[warp][lane*4+0] = v.x; sh_row[warp][lane*4+1] = v.y;
    sh_row[warp][lane*4+2] = v.z; sh_row[warp][lane*4+3] = v.w;
    __syncthreads();

    float accv = b2[lane];
    const float* row = sh_row[warp];
#pragma unroll 16
    for (int c = 0; c < 128; c++) accv += row[c] * sh_w[c * 32 + lane];
    float g = gelu_exact(accv);
    out[(size_t)t * 32 + lane] = g + g_xres[(size_t)t * 32 + lane];
}

// ================= launch =================================================
#define ATTN_SMEM ((NTOK*KV_STRIDE*2 + 3*1024 + 96 + 964 + 256) * 4)
#define CONV_SMEM ((16*CONV_IN_STRIDE + 9*16*128) * 4)

extern "C" void kernel_launch(void* const* d_in, const int* in_sizes, int n_in,
                              void* d_out, int out_size) {
    const float* x      = (const float*)d_in[0];
    const float* n1g    = (const float*)d_in[1];
    const float* n1b    = (const float*)d_in[2];
    const float* modw   = (const float*)d_in[3];
    const float* qkvw   = (const float*)d_in[4];
    const float* qkvb   = (const float*)d_in[5];
    const float* rpbt   = (const float*)d_in[6];
    const float* revw   = (const float*)d_in[7];
    const float* revb   = (const float*)d_in[8];
    const float* n2g    = (const float*)d_in[9];
    const float* n2b    = (const float*)d_in[10];
    const float* lp1w   = (const float*)d_in[11];
    const float* lp1b   = (const float*)d_in[12];
    const float* convw  = (const float*)d_in[13];
    const float* convb  = (const float*)d_in[14];
    const float* lp2w   = (const float*)d_in[15];
    const float* lp2b   = (const float*)d_in[16];
    float* out = (float*)d_out;

    cudaFuncSetAttribute(k_attn, cudaFuncAttributeMaxDynamicSharedMemorySize, ATTN_SMEM);
    cudaFuncSetAttribute(k_conv, cudaFuncAttributeMaxDynamicSharedMemorySize, CONV_SMEM);

    k_ln1 <<<NWIN, 256>>>(x, n1g, n1b, modw);
    k_attn<<<NWIN * HH, 256, ATTN_SMEM>>>(qkvw, qkvb, rpbt);
    k_rev <<<NTOKENS / 8, 256>>>(x, revw, revb);
    k_lp1 <<<NTOKENS / 8, 256>>>(n2g, n2b, lp1w, lp1b);
    k_conv<<<BQ * 16 * 16, 256, CONV_SMEM>>>(convw, convb);
    k_lp2 <<<NTOKENS / 8, 256>>>(lp2w, lp2b, out);
}

// round 2
// speedup vs baseline: 1.0004x; 1.0004x over previous
#include <cuda_runtime.h>
#include <cuda_bf16.h>
#include <math.h>

// ---------------- static config ----------------
#define BQ 8
#define FD 128
#define PW 16
#define NHW 8
#define NTOK 256
#define HH 8
#define AD 32
#define CC 32
#define INNER 128
#define NWIN (BQ*NHW*NHW)       // 512 windows
#define NTOKENS (BQ*FD*FD)      // 131072 tokens

// ---------------- scratch (device globals; no allocation) ----------------
__device__ float g_hwin[NWIN*NTOK*CC];          // 16.8 MB
__device__ float g_oheads[(size_t)NWIN*NTOK*HH*AD]; // 134 MB
__device__ float g_xres[(size_t)NTOKENS*CC];    // 16.8 MB
__device__ float g_y1[(size_t)NTOKENS*INNER];   // 67 MB
__device__ float g_y2[(size_t)NTOKENS*INNER];   // 67 MB

__device__ __forceinline__ float gelu_exact(float x) {
    return 0.5f * x * (1.0f + erff(x * 0.70710678118654752440f));
}

// ================= Kernel 1: LN1 + shift + window partition + modulator ==
__global__ void k_ln1(const float* __restrict__ x, const float* __restrict__ g1,
                      const float* __restrict__ b1, const float* __restrict__ modw) {
    int w = blockIdx.x;          // 0..511
    int n = threadIdx.x;         // 0..255
    int b = w >> 6, ww = w & 63;
    int wy = ww >> 3, wx = ww & 7;
    int iy = n >> 4, ix = n & 15;
    int ry = wy * 16 + iy, rx = wx * 16 + ix;
    int y = (ry + 8) & 127, xx = (rx + 8) & 127;   // roll(-8,-8): rolled[r] = orig[r+8]
    const float* xp = x + ((size_t)b * 16384 + (size_t)y * 128 + xx) * CC;

    float v[CC];
#pragma unroll
    for (int i = 0; i < 8; i++) {
        float4 t = ((const float4*)xp)[i];
        v[4*i] = t.x; v[4*i+1] = t.y; v[4*i+2] = t.z; v[4*i+3] = t.w;
    }
    float mean = 0.f;
#pragma unroll
    for (int c = 0; c < CC; c++) mean += v[c];
    mean *= (1.0f / CC);
    float var = 0.f;
#pragma unroll
    for (int c = 0; c < CC; c++) { float d = v[c] - mean; var += d * d; }
    var *= (1.0f / CC);
    float rstd = rsqrtf(var + 1e-5f);

    float* op = g_hwin + ((size_t)w * NTOK + n) * CC;
#pragma unroll
    for (int i = 0; i < 8; i++) {
        float4 o;
        int c = 4 * i;
        o.x = (v[c+0]-mean)*rstd*g1[c+0] + b1[c+0] + modw[n*CC + c+0];
        o.y = (v[c+1]-mean)*rstd*g1[c+1] + b1[c+1] + modw[n*CC + c+1];
        o.z = (v[c+2]-mean)*rstd*g1[c+2] + b1[c+2] + modw[n*CC + c+2];
        o.w = (v[c+3]-mean)*rstd*g1[c+3] + b1[c+3] + modw[n*CC + c+3];
        ((float4*)op)[i] = o;
    }
}

// ================= Kernel 2: fused QKV + flash window attention ==========
// One block per (window, head). 256 threads, thread = query token.
#define KV_STRIDE 36   // padded row stride (floats), 16B aligned, conflict-mitigating
__global__ void __launch_bounds__(256) k_attn(const float* __restrict__ qkvw,
                                              const float* __restrict__ qkvb,
                                              const float* __restrict__ rpbt) {
    extern __shared__ float sm[];
    float* sh_k   = sm;                        // 256*36
    float* sh_v   = sh_k + NTOK * KV_STRIDE;   // 256*36
    float* sh_wq  = sh_v + NTOK * KV_STRIDE;   // 1024
    float* sh_wk  = sh_wq + 1024;              // 1024
    float* sh_wv  = sh_wk + 1024;              // 1024
    float* sh_b   = sh_wv + 1024;              // 96
    float* sh_rpb = sh_b + 96;                 // 964 (961 used)
    int*   sh_rid = (int*)(sh_rpb + 964);      // 256

    int w  = blockIdx.x >> 3;
    int hh = blockIdx.x & 7;
    int tid = threadIdx.x;

    // weights slices for this head
    for (int i = tid; i < 1024; i += 256) {
        int c = i >> 5, a = i & 31;
        sh_wq[i] = qkvw[c * 768 +       hh * 32 + a];
        sh_wk[i] = qkvw[c * 768 + 256 + hh * 32 + a];
        sh_wv[i] = qkvw[c * 768 + 512 + hh * 32 + a];
    }
    if (tid < 32) {
        sh_b[tid]      = qkvb[      hh * 32 + tid];
        sh_b[32 + tid] = qkvb[256 + hh * 32 + tid];
        sh_b[64 + tid] = qkvb[512 + hh * 32 + tid];
    }
    for (int i = tid; i < 961; i += 256) sh_rpb[i] = rpbt[i * 8 + hh];
    {
        int n = tid;
        int ww = w & 63;
        int ry = (ww >> 3) * 16 + (n >> 4);
        int rx = (ww & 7)  * 16 + (n & 15);
        int hr = ry < 112 ? 0 : (ry < 120 ? 1 : 2);
        int wr = rx < 112 ? 0 : (rx < 120 ? 1 : 2);
        sh_rid[n] = hr * 3 + wr;
    }

    // my h row (registers)
    float hreg[CC];
    {
        const float4* hp = (const float4*)(g_hwin + ((size_t)w * NTOK + tid) * CC);
#pragma unroll
        for (int i = 0; i < 8; i++) {
            float4 t = hp[i];
            hreg[4*i] = t.x; hreg[4*i+1] = t.y; hreg[4*i+2] = t.z; hreg[4*i+3] = t.w;
        }
    }
    __syncthreads();

    // Q (regs, scaled)
    float q[AD];
#pragma unroll
    for (int a = 0; a < AD; a++) q[a] = sh_b[a];
#pragma unroll
    for (int c = 0; c < CC; c++) {
        float hc = hreg[c];
#pragma unroll
        for (int a = 0; a < AD; a++) q[a] += hc * sh_wq[c * 32 + a];
    }
#pragma unroll
    for (int a = 0; a < AD; a++) q[a] *= 0.17677669529663688f; // 1/sqrt(32)

    // K, V into smem
    {
        float tmp[AD];
#pragma unroll
        for (int a = 0; a < AD; a++) tmp[a] = sh_b[32 + a];
#pragma unroll
        for (int c = 0; c < CC; c++) {
            float hc = hreg[c];
#pragma unroll
            for (int a = 0; a < AD; a++) tmp[a] += hc * sh_wk[c * 32 + a];
        }
#pragma unroll
        for (int a = 0; a < AD; a++) sh_k[tid * KV_STRIDE + a] = tmp[a];

#pragma unroll
        for (int a = 0; a < AD; a++) tmp[a] = sh_b[64 + a];
#pragma unroll
        for (int c = 0; c < CC; c++) {
            float hc = hreg[c];
#pragma unroll
            for (int a = 0; a < AD; a++) tmp[a] += hc * sh_wv[c * 32 + a];
        }
#pragma unroll
        for (int a = 0; a < AD; a++) sh_v[tid * KV_STRIDE + a] = tmp[a];
    }
    __syncthreads();

    // streaming softmax over keys
    int iy = tid >> 4, ix = tid & 15;
    int myrid = sh_rid[tid];
    int rbase = (iy + 15) * 31 + (ix + 15);
    float rmax = -1e30f, rsum = 0.f;
    float acc[AD];
#pragma unroll
    for (int a = 0; a < AD; a++) acc[a] = 0.f;

    for (int m = 0; m < NTOK; ++m) {
        const float4* kr = (const float4*)(sh_k + m * KV_STRIDE);
        float s0 = 0.f, s1 = 0.f;
#pragma unroll
        for (int i = 0; i < 8; i += 2) {
            float4 k0 = kr[i], k1 = kr[i+1];
            s0 += q[4*i+0]*k0.x + q[4*i+1]*k0.y + q[4*i+2]*k0.z + q[4*i+3]*k0.w;
            s1 += q[4*i+4]*k1.x + q[4*i+5]*k1.y + q[4*i+6]*k1.z + q[4*i+7]*k1.w;
        }
        float s = s0 + s1;
        int my = m >> 4, mx = m & 15;
        s += sh_rpb[rbase - my * 31 - mx];
        if (myrid != sh_rid[m]) s -= 100.0f;

        if (s > rmax) {
            float f = __expf(rmax - s);
            rsum *= f;
#pragma unroll
            for (int a = 0; a < AD; a++) acc[a] *= f;
            rmax = s;
        }
        float p = __expf(s - rmax);
        rsum += p;
        const float4* vr = (const float4*)(sh_v + m * KV_STRIDE);
#pragma unroll
        for (int i = 0; i < 8; i++) {
            float4 vv = vr[i];
            acc[4*i+0] += p * vv.x; acc[4*i+1] += p * vv.y;
            acc[4*i+2] += p * vv.z; acc[4*i+3] += p * vv.w;
        }
    }

    float inv = 1.0f / rsum;
    float* op = g_oheads + ((size_t)w * NTOK + tid) * (HH * AD) + hh * AD;
#pragma unroll
    for (int i = 0; i < 8; i++) {
        float4 o;
        o.x = acc[4*i+0]*inv; o.y = acc[4*i+1]*inv;
        o.z = acc[4*i+2]*inv; o.w = acc[4*i+3]*inv;
        ((float4*)op)[i] = o;
    }
}

// ================= Kernel 3: rev projection + window reverse + residual ==
__global__ void k_rev(const float* __restrict__ x, const float* __restrict__ revw,
                      const float* __restrict__ revb) {
    __shared__ float sh_w[256 * 32];  // 32 KB
    __shared__ float sh_o[8][256];    // 8 KB
    int tid = threadIdx.x;
    for (int i = tid; i < 8192; i += 256) sh_w[i] = revw[i];

    int warp = tid >> 5, lane = tid & 31;
    long t = (long)blockIdx.x * 8 + warp;
    {
        int b = (int)(t >> 14), p = (int)(t & 16383);
        int y = p >> 7, xx = p & 127;
        int ry = (y + 120) & 127, rx = (xx + 120) & 127;   // reverse roll(+8,+8)
        int w = b * 64 + (ry >> 4) * 8 + (rx >> 4);
        int n = (ry & 15) * 16 + (rx & 15);
        const float4* op4 = (const float4*)(g_oheads + ((size_t)w * NTOK + n) * 256);
        ((float4*)sh_o[warp])[lane]      = op4[lane];
        ((float4*)sh_o[warp])[lane + 32] = op4[lane + 32];
    }
    __syncthreads();

    float accv = revb[lane];
    const float* orow = sh_o[warp];
#pragma unroll 8
    for (int k = 0; k < 256; k++) accv += orow[k] * sh_w[k * 32 + lane];
    g_xres[(size_t)t * 32 + lane] = x[(size_t)t * 32 + lane] + accv;
}

// ================= Kernel 4: LN2 + lp1 (32->128) + GELU ==================
__global__ void k_lp1(const float* __restrict__ n2g, const float* __restrict__ n2b,
                      const float* __restrict__ w1, const float* __restrict__ bb1) {
    __shared__ float sh_w[32 * 128]; // 16 KB
    __shared__ float sh_b[128];
    int tid = threadIdx.x;
    for (int i = tid; i < 4096; i += 256) sh_w[i] = w1[i];
    if (tid < 128) sh_b[tid] = bb1[tid];
    __syncthreads();

    int warp = tid >> 5, lane = tid & 31;
    long t = (long)blockIdx.x * 8 + warp;
    float v = g_xres[(size_t)t * 32 + lane];

    float s = v;
#pragma unroll
    for (int o = 16; o; o >>= 1) s += __shfl_xor_sync(0xffffffffu, s, o);
    float mean = s * (1.0f / 32.0f);
    float d = v - mean;
    float ss = d * d;
#pragma unroll
    for (int o = 16; o; o >>= 1) ss += __shfl_xor_sync(0xffffffffu, ss, o);
    float rstd = rsqrtf(ss * (1.0f / 32.0f) + 1e-5f);
    float hn = d * rstd * n2g[lane] + n2b[lane];

    float4 acc = ((const float4*)sh_b)[lane];
#pragma unroll
    for (int c = 0; c < 32; c++) {
        float hc = __shfl_sync(0xffffffffu, hn, c);
        float4 wv = ((const float4*)sh_w)[c * 32 + lane];
        acc.x += hc * wv.x; acc.y += hc * wv.y;
        acc.z += hc * wv.z; acc.w += hc * wv.w;
    }
    float4 r;
    r.x = gelu_exact(acc.x); r.y = gelu_exact(acc.y);
    r.z = gelu_exact(acc.z); r.w = gelu_exact(acc.w);
    ((float4*)(g_y1 + (size_t)t * 128))[lane] = r;
}

// ================= Kernel 5: 3x3 conv 128->128 SAME + bias + GELU ========
// Block: 8x8 spatial x 128 co. warp = 16-co group (weight reads broadcast).
#define CONV_IN_STRIDE 100
__global__ void __launch_bounds__(256) k_conv(const float* __restrict__ cw,
                                              const float* __restrict__ cb) {
    extern __shared__ float sm[];
    float* sh_in = sm;                 // 16 * 100 floats, layout [cc][pixel]
    float* sh_w  = sm + 16 * CONV_IN_STRIDE; // [tap*16+cc][128]

    int bz = blockIdx.x;
    int b  = bz >> 8;
    int ty0 = ((bz >> 4) & 15) * 8;
    int tx0 = (bz & 15) * 8;
    int tid = threadIdx.x;
    int cg = tid >> 5, lane = tid & 31;
    int co0 = cg * 16;

    float acc[2][16];
#pragma unroll
    for (int s = 0; s < 2; s++)
#pragma unroll
        for (int j = 0; j < 16; j++) acc[s][j] = 0.f;

    int p0 = 2 * lane;
    int py0_ = p0 >> 3, px0_ = p0 & 7;
    int py1_ = (p0 + 1) >> 3, px1_ = (p0 + 1) & 7;

    for (int ci0 = 0; ci0 < 128; ci0 += 16) {
        __syncthreads();
        // input tile 10x10x16 (zero-padded), cc-major
        for (int i = tid; i < 400; i += 256) {
            int pix = i >> 2, qq = i & 3;
            int py = pix / 10, px = pix - py * 10;
            int gy = ty0 - 1 + py, gx = tx0 - 1 + px;
            float4 val = make_float4(0.f, 0.f, 0.f, 0.f);
            if ((unsigned)gy < 128u && (unsigned)gx < 128u)
                val = *(const float4*)(g_y1 + (((size_t)b * 16384 + (size_t)gy * 128 + gx) * 128 + ci0 + qq * 4));
            sh_in[(qq*4+0) * CONV_IN_STRIDE + pix] = val.x;
            sh_in[(qq*4+1) * CONV_IN_STRIDE + pix] = val.y;
            sh_in[(qq*4+2) * CONV_IN_STRIDE + pix] = val.z;
            sh_in[(qq*4+3) * CONV_IN_STRIDE + pix] = val.w;
        }
        // weights chunk: 9 taps x 16 ci x 128 co
        for (int i = tid; i < 4608; i += 256) {
            int row = i >> 5, f4 = i & 31;
            int tap = row >> 4, ccx = row & 15;
            ((float4*)sh_w)[row * 32 + f4] =
                ((const float4*)cw)[((size_t)tap * 128 + ci0 + ccx) * 32 + f4];
        }
        __syncthreads();

#pragma unroll
        for (int ky = 0; ky < 3; ky++)
#pragma unroll
        for (int kx = 0; kx < 3; kx++) {
            int L0 = (py0_ + ky) * 10 + px0_ + kx;
            int L1 = (py1_ + ky) * 10 + px1_ + kx;
            int tap = ky * 3 + kx;
#pragma unroll
            for (int ccx = 0; ccx < 16; ccx++) {
                float i0 = sh_in[ccx * CONV_IN_STRIDE + L0];
                float i1 = sh_in[ccx * CONV_IN_STRIDE + L1];
                const float4* wr = (const float4*)(sh_w + (tap * 16 + ccx) * 128 + co0);
#pragma unroll
                for (int j = 0; j < 4; j++) {
                    float4 wv = wr[j];
                    acc[0][4*j+0] += i0 * wv.x; acc[0][4*j+1] += i0 * wv.y;
                    acc[0][4*j+2] += i0 * wv.z; acc[0][4*j+3] += i0 * wv.w;
                    acc[1][4*j+0] += i1 * wv.x; acc[1][4*j+1] += i1 * wv.y;
                    acc[1][4*j+2] += i1 * wv.z; acc[1][4*j+3] += i1 * wv.w;
                }
            }
        }
    }

#pragma unroll
    for (int s = 0; s < 2; s++) {
        int pix = 2 * lane + s;
        int gy = ty0 + (pix >> 3), gx = tx0 + (pix & 7);
        float* op = g_y2 + (((size_t)b * 16384 + (size_t)gy * 128 + gx) * 128 + co0);
#pragma unroll
        for (int j = 0; j < 16; j += 4) {
            float4 r;
            r.x = gelu_exact(acc[s][j+0] + cb[co0+j+0]);
            r.y = gelu_exact(acc[s][j+1] + cb[co0+j+1]);
            r.z = gelu_exact(acc[s][j+2] + cb[co0+j+2]);
            r.w = gelu_exact(acc[s][j+3] + cb[co0+j+3]);
            *(float4*)(op + j) = r;
        }
    }
}

// ================= Kernel 6: lp2 (128->32) + GELU + residual =============
__global__ void k_lp2(const float* __restrict__ w2, const float* __restrict__ b2,
                      float* __restrict__ out) {
    __shared__ float sh_w[128 * 32];   // 16 KB
    __shared__ float sh_row[8][132];
    int tid = threadIdx.x;
    for (int i = tid; i < 4096; i += 256) sh_w[i] = w2[i];

    int warp = tid >> 5, lane = tid & 31;
    long t = (long)blockIdx.x * 8 + warp;
    float4 v = ((const float4*)(g_y2 + (size_t)t * 128))[lane];
    sh_row[warp][lane*4+0] = v.x; sh_row[warp][lane*4+1] = v.y;
    sh_row[warp][lane*4+2] = v.z; sh_row[warp][lane*4+3] = v.w;
    __syncthreads();

    float accv = b2[lane];
    const float* row = sh_row[warp];
#pragma unroll 16
    for (int c = 0; c < 128; c++) accv += row[c] * sh_w[c * 32 + lane];
    float g = gelu_exact(accv);
    out[(size_t)t * 32 + lane] = g + g_xres[(size_t)t * 32 + lane];
}

// ================= launch =================================================
#define ATTN_SMEM ((NTOK*KV_STRIDE*2 + 3*1024 + 96 + 964 + 256) * 4)
#define CONV_SMEM ((16*CONV_IN_STRIDE + 9*16*128) * 4)

extern "C" void kernel_launch(void* const* d_in, const int* in_sizes, int n_in,
                              void* d_out, int out_size) {
    const float* x      = (const float*)d_in[0];
    const float* n1g    = (const float*)d_in[1];
    const float* n1b    = (const float*)d_in[2];
    const float* modw   = (const float*)d_in[3];
    const float* qkvw   = (const float*)d_in[4];
    const float* qkvb   = (const float*)d_in[5];
    const float* rpbt   = (const float*)d_in[6];
    const float* revw   = (const float*)d_in[7];
    const float* revb   = (const float*)d_in[8];
    const float* n2g    = (const float*)d_in[9];
    const float* n2b    = (const float*)d_in[10];
    const float* lp1w   = (const float*)d_in[11];
    const float* lp1b   = (const float*)d_in[12];
    const float* convw  = (const float*)d_in[13];
    const float* convb  = (const float*)d_in[14];
    const float* lp2w   = (const float*)d_in[15];
    const float* lp2b   = (const float*)d_in[16];
    float* out = (float*)d_out;

    cudaFuncSetAttribute(k_attn, cudaFuncAttributeMaxDynamicSharedMemorySize, ATTN_SMEM);
    cudaFuncSetAttribute(k_conv, cudaFuncAttributeMaxDynamicSharedMemorySize, CONV_SMEM);

    k_ln1 <<<NWIN, 256>>>(x, n1g, n1b, modw);
    k_attn<<<NWIN * HH, 256, ATTN_SMEM>>>(qkvw, qkvb, rpbt);
    k_rev <<<NTOKENS / 8, 256>>>(x, revw, revb);
    k_lp1 <<<NTOKENS / 8, 256>>>(n2g, n2b, lp1w, lp1b);
    k_conv<<<BQ * 16 * 16, 256, CONV_SMEM>>>(convw, convb);
    k_lp2 <<<NTOKENS / 8, 256>>>(lp2w, lp2b, out);
}

// round 3
// speedup vs baseline: 2.2063x; 2.2054x over previous
#include <cuda_runtime.h>
#include <cuda_bf16.h>
#include <math.h>

#define BQ 8
#define NTOK 256
#define HH 8
#define CC 32
#define INNER 128
#define NWIN 512
#define NTOKENS (BQ*128*128)

__device__ float g_hwin[NWIN*NTOK*CC];
__device__ float g_oheads[(size_t)NWIN*NTOK*HH*32];
__device__ float g_xres[(size_t)NTOKENS*CC];
__device__ float g_y1[(size_t)NTOKENS*INNER];
__device__ float g_y2[(size_t)NTOKENS*INNER];

__device__ __forceinline__ float gelu_exact(float x) {
    return 0.5f * x * (1.0f + erff(x * 0.70710678118654752440f));
}
__device__ __forceinline__ float tf32r(float x) {
    unsigned u; asm("cvt.rna.tf32.f32 %0, %1;" : "=r"(u) : "f"(x));
    return __uint_as_float(u);
}
__device__ __forceinline__ void mma_tf32(float* c, const unsigned* a, const unsigned* b) {
    asm volatile("mma.sync.aligned.m16n8k8.row.col.f32.tf32.tf32.f32 "
        "{%0,%1,%2,%3},{%4,%5,%6,%7},{%8,%9},{%0,%1,%2,%3};"
        : "+f"(c[0]), "+f"(c[1]), "+f"(c[2]), "+f"(c[3])
        : "r"(a[0]), "r"(a[1]), "r"(a[2]), "r"(a[3]), "r"(b[0]), "r"(b[1]));
}

// ============ K1: LN1 + shift + window partition + modulator ============
__global__ void k_ln1(const float* __restrict__ x, const float* __restrict__ g1,
                      const float* __restrict__ b1, const float* __restrict__ modw) {
    int w = blockIdx.x, n = threadIdx.x;
    int b = w >> 6, ww = w & 63;
    int ry = (ww >> 3) * 16 + (n >> 4), rx = (ww & 7) * 16 + (n & 15);
    int y = (ry + 8) & 127, xx = (rx + 8) & 127;
    const float* xp = x + ((size_t)b * 16384 + (size_t)y * 128 + xx) * CC;
    float v[CC];
#pragma unroll
    for (int i = 0; i < 8; i++) {
        float4 t = ((const float4*)xp)[i];
        v[4*i]=t.x; v[4*i+1]=t.y; v[4*i+2]=t.z; v[4*i+3]=t.w;
    }
    float mean = 0.f;
#pragma unroll
    for (int c = 0; c < CC; c++) mean += v[c];
    mean *= (1.0f/CC);
    float var = 0.f;
#pragma unroll
    for (int c = 0; c < CC; c++) { float d = v[c]-mean; var += d*d; }
    float rstd = rsqrtf(var*(1.0f/CC) + 1e-5f);
    float* op = g_hwin + ((size_t)w * NTOK + n) * CC;
#pragma unroll
    for (int i = 0; i < 8; i++) {
        float4 o; int c = 4*i;
        o.x=(v[c+0]-mean)*rstd*g1[c+0]+b1[c+0]+modw[n*CC+c+0];
        o.y=(v[c+1]-mean)*rstd*g1[c+1]+b1[c+1]+modw[n*CC+c+1];
        o.z=(v[c+2]-mean)*rstd*g1[c+2]+b1[c+2]+modw[n*CC+c+2];
        o.w=(v[c+3]-mean)*rstd*g1[c+3]+b1[c+3]+modw[n*CC+c+3];
        ((float4*)op)[i] = o;
    }
}

// ============ K2: QKV mma + flash window attention (tf32) ===============
#define QS 36
#define VS 40
#define WSS 104
#define ATTN_SMEM (42529*4)
__global__ void __launch_bounds__(256) k_attn(const float* __restrict__ qkvw,
                                              const float* __restrict__ qkvb,
                                              const float* __restrict__ rpbt) {
    extern __shared__ float sm[];
    float* sh_h   = sm;                 // 256*36 (later: per-warp P buffers)
    float* sh_q   = sh_h + 9216;
    float* sh_k   = sh_q + 9216;
    float* sh_v   = sh_k + 9216;        // 256*40
    float* sh_w   = sh_v + 10240;       // 32*104
    float* sh_b   = sh_w + 3328;        // 96
    float* sh_rpb = sh_b + 96;          // 961
    int*   sh_meta= (int*)(sh_rpb + 961); // 256

    int w = blockIdx.x >> 3, hh = blockIdx.x & 7;
    int tid = threadIdx.x, lane = tid & 31, warp = tid >> 5;
    int tg = lane >> 2, tq = lane & 3;
    int qb = warp * 32;

    for (int i = tid; i < 32*96; i += 256) {
        int c = i / 96, j = i - c * 96;
        sh_w[c*WSS + j] = qkvw[c*768 + (j>>5)*256 + hh*32 + (j&31)];
    }
    if (tid < 96) sh_b[tid] = qkvb[(tid>>5)*256 + hh*32 + (tid&31)];
    for (int i = tid; i < 961; i += 256) sh_rpb[i] = rpbt[i*8 + hh];
    {
        int n = tid, ww = w & 63;
        int ry = (ww>>3)*16 + (n>>4), rx = (ww&7)*16 + (n&15);
        int hr = ry < 112 ? 0 : (ry < 120 ? 1 : 2);
        int wr = rx < 112 ? 0 : (rx < 120 ? 1 : 2);
        sh_meta[n] = ((n>>4)*31 + (n&15)) | ((hr*3+wr) << 16);
    }
    {
        const float4* hp = (const float4*)(g_hwin + ((size_t)w*NTOK + tid)*32);
#pragma unroll
        for (int i = 0; i < 8; i++) {
            float4 t = hp[i];
            sh_h[tid*QS+4*i+0]=tf32r(t.x); sh_h[tid*QS+4*i+1]=tf32r(t.y);
            sh_h[tid*QS+4*i+2]=tf32r(t.z); sh_h[tid*QS+4*i+3]=tf32r(t.w);
        }
    }
    __syncthreads();

    // ---- QKV projection: 32 rows (this warp) x 96 cols, K=32 ----
    {
        float acc[2][12][4];
#pragma unroll
        for (int mt=0; mt<2; mt++)
#pragma unroll
            for (int nt=0; nt<12; nt++)
#pragma unroll
                for (int r=0; r<4; r++) acc[mt][nt][r] = 0.f;
#pragma unroll
        for (int k0 = 0; k0 < 32; k0 += 8) {
            unsigned A[2][4];
#pragma unroll
            for (int mt=0; mt<2; mt++) {
                int r = qb + mt*16 + tg;
                A[mt][0]=__float_as_uint(sh_h[r*QS+k0+tq]);
                A[mt][1]=__float_as_uint(sh_h[(r+8)*QS+k0+tq]);
                A[mt][2]=__float_as_uint(sh_h[r*QS+k0+tq+4]);
                A[mt][3]=__float_as_uint(sh_h[(r+8)*QS+k0+tq+4]);
            }
#pragma unroll
            for (int nt=0; nt<12; nt++) {
                unsigned B[2];
                B[0]=__float_as_uint(sh_w[(k0+tq)*WSS + nt*8+tg]);
                B[1]=__float_as_uint(sh_w[(k0+tq+4)*WSS + nt*8+tg]);
                mma_tf32(acc[0][nt], A[0], B);
                mma_tf32(acc[1][nt], A[1], B);
            }
        }
#pragma unroll
        for (int mt=0; mt<2; mt++)
#pragma unroll
        for (int nt=0; nt<12; nt++) {
            int sec = nt >> 2, col = (nt&3)*8 + 2*tq;
            int r0 = qb + mt*16 + tg;
            float bb0 = sh_b[sec*32+col], bb1 = sh_b[sec*32+col+1];
            float v0=acc[mt][nt][0]+bb0, v1=acc[mt][nt][1]+bb1;
            float v2=acc[mt][nt][2]+bb0, v3=acc[mt][nt][3]+bb1;
            if (sec == 0) {
                const float SC = 0.17677669529663688f;
                sh_q[r0*QS+col]=tf32r(v0*SC); sh_q[r0*QS+col+1]=tf32r(v1*SC);
                sh_q[(r0+8)*QS+col]=tf32r(v2*SC); sh_q[(r0+8)*QS+col+1]=tf32r(v3*SC);
            } else if (sec == 1) {
                sh_k[r0*QS+col]=tf32r(v0); sh_k[r0*QS+col+1]=tf32r(v1);
                sh_k[(r0+8)*QS+col]=tf32r(v2); sh_k[(r0+8)*QS+col+1]=tf32r(v3);
            } else {
                sh_v[r0*VS+col]=tf32r(v0); sh_v[r0*VS+col+1]=tf32r(v1);
                sh_v[(r0+8)*VS+col]=tf32r(v2); sh_v[(r0+8)*VS+col+1]=tf32r(v3);
            }
        }
    }
    __syncthreads();

    // ---- flash attention over 8 key chunks ----
    int rb[2][2], rid[2][2];
#pragma unroll
    for (int mt=0; mt<2; mt++)
#pragma unroll
        for (int h=0; h<2; h++) {
            int q = qb + mt*16 + tg + 8*h;
            rb[mt][h] = ((q>>4)+15)*31 + ((q&15)+15);
            rid[mt][h] = sh_meta[q] >> 16;
        }
    float rmax[2][2] = {{-1e30f,-1e30f},{-1e30f,-1e30f}};
    float rsum[2][2] = {{0.f,0.f},{0.f,0.f}};
    float o[2][4][4];
#pragma unroll
    for (int mt=0; mt<2; mt++)
#pragma unroll
        for (int nt=0; nt<4; nt++)
#pragma unroll
            for (int r=0; r<4; r++) o[mt][nt][r] = 0.f;

    float* shp = sh_h + warp * 1152;   // 32 x 36 warp-private P

    for (int kc = 0; kc < 8; kc++) {
        int kb = kc * 32;
        float s[2][4][4];
#pragma unroll
        for (int mt=0; mt<2; mt++)
#pragma unroll
            for (int nt=0; nt<4; nt++)
#pragma unroll
                for (int r=0; r<4; r++) s[mt][nt][r] = 0.f;
#pragma unroll
        for (int k0 = 0; k0 < 32; k0 += 8) {
            unsigned A[2][4];
#pragma unroll
            for (int mt=0; mt<2; mt++) {
                int r = qb + mt*16 + tg;
                A[mt][0]=__float_as_uint(sh_q[r*QS+k0+tq]);
                A[mt][1]=__float_as_uint(sh_q[(r+8)*QS+k0+tq]);
                A[mt][2]=__float_as_uint(sh_q[r*QS+k0+tq+4]);
                A[mt][3]=__float_as_uint(sh_q[(r+8)*QS+k0+tq+4]);
            }
#pragma unroll
            for (int nt=0; nt<4; nt++) {
                unsigned B[2];
                int kr = kb + nt*8 + tg;
                B[0]=__float_as_uint(sh_k[kr*QS+k0+tq]);
                B[1]=__float_as_uint(sh_k[kr*QS+k0+tq+4]);
                mma_tf32(s[0][nt], A[0], B);
                mma_tf32(s[1][nt], A[1], B);
            }
        }
#pragma unroll
        for (int nt=0; nt<4; nt++) {
            int k0i = kb + nt*8 + 2*tq;
            int me0 = sh_meta[k0i], me1 = sh_meta[k0i+1];
            int kf0 = me0 & 0xffff, kr0 = me0 >> 16;
            int kf1 = me1 & 0xffff, kr1 = me1 >> 16;
#pragma unroll
            for (int mt=0; mt<2; mt++) {
                s[mt][nt][0] += sh_rpb[rb[mt][0]-kf0] + (kr0 != rid[mt][0] ? -100.f : 0.f);
                s[mt][nt][1] += sh_rpb[rb[mt][0]-kf1] + (kr1 != rid[mt][0] ? -100.f : 0.f);
                s[mt][nt][2] += sh_rpb[rb[mt][1]-kf0] + (kr0 != rid[mt][1] ? -100.f : 0.f);
                s[mt][nt][3] += sh_rpb[rb[mt][1]-kf1] + (kr1 != rid[mt][1] ? -100.f : 0.f);
            }
        }
#pragma unroll
        for (int mt=0; mt<2; mt++)
#pragma unroll
        for (int h=0; h<2; h++) {
            float m = s[mt][0][2*h];
            m = fmaxf(m, s[mt][0][2*h+1]);
#pragma unroll
            for (int nt=1; nt<4; nt++) {
                m = fmaxf(m, s[mt][nt][2*h]); m = fmaxf(m, s[mt][nt][2*h+1]);
            }
            m = fmaxf(m, __shfl_xor_sync(0xffffffffu, m, 1));
            m = fmaxf(m, __shfl_xor_sync(0xffffffffu, m, 2));
            float nm = fmaxf(rmax[mt][h], m);
            float f = __expf(rmax[mt][h] - nm);
            rmax[mt][h] = nm;
            float ps = 0.f;
#pragma unroll
            for (int nt=0; nt<4; nt++) {
                float p0 = __expf(s[mt][nt][2*h]   - nm);
                float p1 = __expf(s[mt][nt][2*h+1] - nm);
                s[mt][nt][2*h] = p0; s[mt][nt][2*h+1] = p1;
                ps += p0 + p1;
            }
            ps += __shfl_xor_sync(0xffffffffu, ps, 1);
            ps += __shfl_xor_sync(0xffffffffu, ps, 2);
            rsum[mt][h] = rsum[mt][h] * f + ps;
#pragma unroll
            for (int nt=0; nt<4; nt++) { o[mt][nt][2*h] *= f; o[mt][nt][2*h+1] *= f; }
        }
#pragma unroll
        for (int mt=0; mt<2; mt++)
#pragma unroll
        for (int nt=0; nt<4; nt++) {
            int ql = mt*16 + tg, kl = nt*8 + 2*tq;
            *(float2*)(shp + ql*36 + kl)     = make_float2(tf32r(s[mt][nt][0]), tf32r(s[mt][nt][1]));
            *(float2*)(shp + (ql+8)*36 + kl) = make_float2(tf32r(s[mt][nt][2]), tf32r(s[mt][nt][3]));
        }
        __syncwarp();
#pragma unroll
        for (int k0 = 0; k0 < 32; k0 += 8) {
            unsigned A[2][4];
#pragma unroll
            for (int mt=0; mt<2; mt++) {
                int ql = mt*16 + tg;
                A[mt][0]=__float_as_uint(shp[ql*36+k0+tq]);
                A[mt][1]=__float_as_uint(shp[(ql+8)*36+k0+tq]);
                A[mt][2]=__float_as_uint(shp[ql*36+k0+tq+4]);
                A[mt][3]=__float_as_uint(shp[(ql+8)*36+k0+tq+4]);
            }
#pragma unroll
            for (int nt=0; nt<4; nt++) {
                unsigned B[2];
                int vr = kb + k0 + tq;
                B[0]=__float_as_uint(sh_v[vr*VS + nt*8+tg]);
                B[1]=__float_as_uint(sh_v[(vr+4)*VS + nt*8+tg]);
                mma_tf32(o[0][nt], A[0], B);
                mma_tf32(o[1][nt], A[1], B);
            }
        }
        __syncwarp();
    }
#pragma unroll
    for (int mt=0; mt<2; mt++) {
        float i0 = 1.f/rsum[mt][0], i1 = 1.f/rsum[mt][1];
        int q = qb + mt*16 + tg;
        float* d0 = g_oheads + ((size_t)w*256 + q)*256 + hh*32;
        float* d1 = d0 + 8*256;
#pragma unroll
        for (int nt=0; nt<4; nt++) {
            int dc = nt*8 + 2*tq;
            *(float2*)(d0+dc) = make_float2(o[mt][nt][0]*i0, o[mt][nt][1]*i0);
            *(float2*)(d1+dc) = make_float2(o[mt][nt][2]*i1, o[mt][nt][3]*i1);
        }
    }
}

// ============ K3: rev projection + window reverse + residual ============
__global__ void k_rev(const float* __restrict__ x, const float* __restrict__ revw,
                      const float* __restrict__ revb) {
    __shared__ float sh_w[256*32];
    __shared__ float sh_o[8][256];
    int tid = threadIdx.x;
    for (int i = tid; i < 8192; i += 256) sh_w[i] = revw[i];
    int warp = tid >> 5, lane = tid & 31;
    long t = (long)blockIdx.x * 8 + warp;
    {
        int b = (int)(t >> 14), p = (int)(t & 16383);
        int ry = ((p>>7) + 120) & 127, rx = ((p&127) + 120) & 127;
        int w = b*64 + (ry>>4)*8 + (rx>>4);
        int n = (ry&15)*16 + (rx&15);
        const float4* op4 = (const float4*)(g_oheads + ((size_t)w*NTOK + n)*256);
        ((float4*)sh_o[warp])[lane]    = op4[lane];
        ((float4*)sh_o[warp])[lane+32] = op4[lane+32];
    }
    __syncthreads();
    float accv = revb[lane];
    const float* orow = sh_o[warp];
#pragma unroll 8
    for (int k = 0; k < 256; k++) accv += orow[k] * sh_w[k*32 + lane];
    g_xres[(size_t)t*32 + lane] = x[(size_t)t*32 + lane] + accv;
}

// ============ K4: LN2 + lp1 (32->128) + GELU ============================
__global__ void k_lp1(const float* __restrict__ n2g, const float* __restrict__ n2b,
                      const float* __restrict__ w1, const float* __restrict__ bb1) {
    __shared__ float sh_w[32*128];
    __shared__ float sh_b[128];
    int tid = threadIdx.x;
    for (int i = tid; i < 4096; i += 256) sh_w[i] = w1[i];
    if (tid < 128) sh_b[tid] = bb1[tid];
    __syncthreads();
    int warp = tid >> 5, lane = tid & 31;
    long t = (long)blockIdx.x * 8 + warp;
    float v = g_xres[(size_t)t*32 + lane];
    float s = v;
#pragma unroll
    for (int o = 16; o; o >>= 1) s += __shfl_xor_sync(0xffffffffu, s, o);
    float mean = s * (1.0f/32.0f);
    float d = v - mean, ss = d*d;
#pragma unroll
    for (int o = 16; o; o >>= 1) ss += __shfl_xor_sync(0xffffffffu, ss, o);
    float rstd = rsqrtf(ss*(1.0f/32.0f) + 1e-5f);
    float hn = d*rstd*n2g[lane] + n2b[lane];
    float4 acc = ((const float4*)sh_b)[lane];
#pragma unroll
    for (int c = 0; c < 32; c++) {
        float hc = __shfl_sync(0xffffffffu, hn, c);
        float4 wv = ((const float4*)sh_w)[c*32 + lane];
        acc.x += hc*wv.x; acc.y += hc*wv.y; acc.z += hc*wv.z; acc.w += hc*wv.w;
    }
    float4 r;
    r.x=gelu_exact(acc.x); r.y=gelu_exact(acc.y); r.z=gelu_exact(acc.z); r.w=gelu_exact(acc.w);
    ((float4*)(g_y1 + (size_t)t*128))[lane] = r;
}

// ============ K5: 3x3 conv 128->128 implicit GEMM (tf32) ================
#define CIS 184
#define CWS 136
#define CONV_SMEM ((32*CIS + 32*CWS)*4)
__global__ void __launch_bounds__(256) k_conv(const float* __restrict__ cw,
                                              const float* __restrict__ cb) {
    extern __shared__ float sm[];
    float* sh_in = sm;            // [ci 32][pixel 180] stride 184
    float* sh_w  = sm + 32*CIS;   // [ci 32][co 128] stride 136
    int bz = blockIdx.x;
    int b = bz >> 7;
    int y0 = ((bz >> 3) & 15) * 8;
    int x0 = (bz & 7) * 16;
    int tid = threadIdx.x, lane = tid & 31, warp = tid >> 5;
    int tg = lane >> 2, tq = lane & 3;
    int wm = warp >> 1, wn = warp & 1;

    float acc[2][8][4];
#pragma unroll
    for (int mt=0; mt<2; mt++)
#pragma unroll
        for (int nt=0; nt<8; nt++)
#pragma unroll
            for (int r=0; r<4; r++) acc[mt][nt][r] = 0.f;

    for (int ci0 = 0; ci0 < 128; ci0 += 32) {
        __syncthreads();
        for (int j = tid; j < 1440; j += 256) {
            int pix = j >> 3, q = j & 7;
            int py = pix / 18, px = pix - py*18;
            int gy = y0 - 1 + py, gx = x0 - 1 + px;
            float4 v = make_float4(0.f,0.f,0.f,0.f);
            if ((unsigned)gy < 128u && (unsigned)gx < 128u)
                v = *(const float4*)(g_y1 + ((size_t)(b*16384 + gy*128 + gx)*128 + ci0 + q*4));
            sh_in[(q*4+0)*CIS+pix]=tf32r(v.x); sh_in[(q*4+1)*CIS+pix]=tf32r(v.y);
            sh_in[(q*4+2)*CIS+pix]=tf32r(v.z); sh_in[(q*4+3)*CIS+pix]=tf32r(v.w);
        }
#pragma unroll
        for (int tap = 0; tap < 9; tap++) {
            int ky = tap / 3, kx = tap % 3;
            __syncthreads();
            for (int j = tid; j < 1024; j += 256) {
                int ci = j >> 5, f4 = j & 31;
                float4 v = *(const float4*)(cw + (size_t)(tap*128 + ci0 + ci)*128 + f4*4);
                sh_w[ci*CWS+f4*4+0]=tf32r(v.x); sh_w[ci*CWS+f4*4+1]=tf32r(v.y);
                sh_w[ci*CWS+f4*4+2]=tf32r(v.z); sh_w[ci*CWS+f4*4+3]=tf32r(v.w);
            }
            __syncthreads();
#pragma unroll
            for (int k0 = 0; k0 < 32; k0 += 8) {
                unsigned A[2][4];
#pragma unroll
                for (int mt=0; mt<2; mt++) {
                    int m0 = wm*32 + mt*16 + tg;
                    int py = m0 >> 4;
                    int pixL = (py+ky)*18 + (m0&15) + kx;
                    int pixH = (py+ky)*18 + tg + 8 + kx;
                    A[mt][0]=__float_as_uint(sh_in[(k0+tq)*CIS + pixL]);
                    A[mt][1]=__float_as_uint(sh_in[(k0+tq)*CIS + pixH]);
                    A[mt][2]=__float_as_uint(sh_in[(k0+tq+4)*CIS + pixL]);
                    A[mt][3]=__float_as_uint(sh_in[(k0+tq+4)*CIS + pixH]);
                }
#pragma unroll
                for (int nt=0; nt<8; nt++) {
                    unsigned B[2];
                    int co = wn*64 + nt*8 + tg;
                    B[0]=__float_as_uint(sh_w[(k0+tq)*CWS + co]);
                    B[1]=__float_as_uint(sh_w[(k0+tq+4)*CWS + co]);
                    mma_tf32(acc[0][nt], A[0], B);
                    mma_tf32(acc[1][nt], A[1], B);
                }
            }
        }
    }
#pragma unroll
    for (int mt=0; mt<2; mt++) {
        int m0 = wm*32 + mt*16 + tg;
        int py = m0 >> 4, px = m0 & 15;
        float* d0 = g_y2 + ((size_t)(b*16384 + (y0+py)*128 + x0+px)*128);
        float* d1 = g_y2 + ((size_t)(b*16384 + (y0+py)*128 + x0+tg+8)*128);
#pragma unroll
        for (int nt=0; nt<8; nt++) {
            int col = wn*64 + nt*8 + 2*tq;
            float b0 = cb[col], b1 = cb[col+1];
            *(float2*)(d0+col) = make_float2(gelu_exact(acc[mt][nt][0]+b0),
                                             gelu_exact(acc[mt][nt][1]+b1));
            *(float2*)(d1+col) = make_float2(gelu_exact(acc[mt][nt][2]+b0),
                                             gelu_exact(acc[mt][nt][3]+b1));
        }
    }
}

// ============ K6: lp2 (128->32) + GELU + residual =======================
__global__ void k_lp2(const float* __restrict__ w2, const float* __restrict__ b2,
                      float* __restrict__ out) {
    __shared__ float sh_w[128*32];
    __shared__ float sh_row[8][132];
    int tid = threadIdx.x;
    for (int i = tid; i < 4096; i += 256) sh_w[i] = w2[i];
    int warp = tid >> 5, lane = tid & 31;
    long t = (long)blockIdx.x * 8 + warp;
    float4 v = ((const float4*)(g_y2 + (size_t)t*128))[lane];
    sh_row[warp][lane*4+0]=v.x; sh_row[warp][lane*4+1]=v.y;
    sh_row[warp][lane*4+2]=v.z; sh_row[warp][lane*4+3]=v.w;
    __syncthreads();
    float accv = b2[lane];
    const float* row = sh_row[warp];
#pragma unroll 16
    for (int c = 0; c < 128; c++) accv += row[c] * sh_w[c*32 + lane];
    float g = gelu_exact(accv);
    out[(size_t)t*32 + lane] = g + g_xres[(size_t)t*32 + lane];
}

extern "C" void kernel_launch(void* const* d_in, const int* in_sizes, int n_in,
                              void* d_out, int out_size) {
    const float* x    = (const float*)d_in[0];
    const float* n1g  = (const float*)d_in[1];
    const float* n1b  = (const float*)d_in[2];
    const float* modw = (const float*)d_in[3];
    const float* qkvw = (const float*)d_in[4];
    const float* qkvb = (const float*)d_in[5];
    const float* rpbt = (const float*)d_in[6];
    const float* revw = (const float*)d_in[7];
    const float* revb = (const float*)d_in[8];
    const float* n2g  = (const float*)d_in[9];
    const float* n2b  = (const float*)d_in[10];
    const float* lp1w = (const float*)d_in[11];
    const float* lp1b = (const float*)d_in[12];
    const float* convw= (const float*)d_in[13];
    const float* convb= (const float*)d_in[14];
    const float* lp2w = (const float*)d_in[15];
    const float* lp2b = (const float*)d_in[16];
    float* out = (float*)d_out;

    cudaFuncSetAttribute(k_attn, cudaFuncAttributeMaxDynamicSharedMemorySize, ATTN_SMEM);
    cudaFuncSetAttribute(k_conv, cudaFuncAttributeMaxDynamicSharedMemorySize, CONV_SMEM);

    k_ln1 <<<NWIN, 256>>>(x, n1g, n1b, modw);
    k_attn<<<NWIN * HH, 256, ATTN_SMEM>>>(qkvw, qkvb, rpbt);
    k_rev <<<NTOKENS / 8, 256>>>(x, revw, revb);
    k_lp1 <<<NTOKENS / 8, 256>>>(n2g, n2b, lp1w, lp1b);
    k_conv<<<BQ * 16 * 8, 256, CONV_SMEM>>>(convw, convb);
    k_lp2 <<<NTOKENS / 8, 256>>>(lp2w, lp2b, out);
}

// round 4
// speedup vs baseline: 4.4862x; 2.0334x over previous
#include <cuda_runtime.h>
#include <cuda_bf16.h>
#include <math.h>

#define BQ 8
#define NTOK 256
#define HH 8
#define CC 32
#define INNER 128
#define NWIN 512
#define NTOKENS (BQ*128*128)

// packed bf16x2 intermediates
__device__ unsigned g_hwin[(size_t)NWIN*NTOK*16];     // [w][n][c2]
__device__ unsigned g_oheads[(size_t)NWIN*NTOK*128];  // [w][n][(h*32+a)/2]
__device__ float    g_xres[(size_t)NTOKENS*CC];       // fp32 (residual-critical)
__device__ unsigned g_y1[(size_t)NTOKENS*64];         // [t][c2]
__device__ unsigned g_y2[(size_t)NTOKENS*64];

__device__ __forceinline__ float gelu_exact(float x) {
    return 0.5f * x * (1.0f + erff(x * 0.70710678118654752440f));
}
__device__ __forceinline__ unsigned pk(float a, float b) {
    __nv_bfloat162 t = __floats2bfloat162_rn(a, b);
    return *reinterpret_cast<unsigned*>(&t);
}
__device__ __forceinline__ void mma_bf16(float* c, const unsigned* a, const unsigned* b) {
    asm volatile("mma.sync.aligned.m16n8k16.row.col.f32.bf16.bf16.f32 "
        "{%0,%1,%2,%3},{%4,%5,%6,%7},{%8,%9},{%0,%1,%2,%3};"
        : "+f"(c[0]), "+f"(c[1]), "+f"(c[2]), "+f"(c[3])
        : "r"(a[0]), "r"(a[1]), "r"(a[2]), "r"(a[3]), "r"(b[0]), "r"(b[1]));
}

// ============ K1: LN1 + shift + window partition + modulator (-> bf16) ==
__global__ void k_ln1(const float* __restrict__ x, const float* __restrict__ g1,
                      const float* __restrict__ b1, const float* __restrict__ modw) {
    int w = blockIdx.x, n = threadIdx.x;
    int b = w >> 6, ww = w & 63;
    int ry = (ww >> 3) * 16 + (n >> 4), rx = (ww & 7) * 16 + (n & 15);
    int y = (ry + 8) & 127, xx = (rx + 8) & 127;
    const float* xp = x + ((size_t)b * 16384 + (size_t)y * 128 + xx) * CC;
    float v[CC];
#pragma unroll
    for (int i = 0; i < 8; i++) {
        float4 t = ((const float4*)xp)[i];
        v[4*i]=t.x; v[4*i+1]=t.y; v[4*i+2]=t.z; v[4*i+3]=t.w;
    }
    float mean = 0.f;
#pragma unroll
    for (int c = 0; c < CC; c++) mean += v[c];
    mean *= (1.0f/CC);
    float var = 0.f;
#pragma unroll
    for (int c = 0; c < CC; c++) { float d = v[c]-mean; var += d*d; }
    float rstd = rsqrtf(var*(1.0f/CC) + 1e-5f);
    unsigned* op = g_hwin + ((size_t)w * NTOK + n) * 16;
#pragma unroll
    for (int i = 0; i < 16; i++) {
        int c = 2*i;
        float h0 = (v[c+0]-mean)*rstd*g1[c+0]+b1[c+0]+modw[n*CC+c+0];
        float h1 = (v[c+1]-mean)*rstd*g1[c+1]+b1[c+1]+modw[n*CC+c+1];
        op[i] = pk(h0, h1);
    }
}

// ============ K2: QKV mma + flash window attention (bf16) ===============
#define ATTN_SMEM (22561*4)
__global__ void __launch_bounds__(256) k_attn(const float* __restrict__ qkvw,
                                              const float* __restrict__ qkvb,
                                              const float* __restrict__ rpbt) {
    extern __shared__ unsigned smu[];
    unsigned* sh_h  = smu;              // 256*20 (later: per-warp P, 8*640)
    unsigned* sh_q  = sh_h + 5120;      // 256*20
    unsigned* sh_kT = sh_q + 5120;      // 16*264  [a2][key]
    unsigned* sh_v  = sh_kT + 4224;     // 128*40  [key2][dim]
    unsigned* sh_w  = sh_v + 5120;      // 16*104  [c2][96]
    float* sh_b   = (float*)(sh_w + 1664);  // 96
    float* sh_rpb = sh_b + 96;              // 961
    int*   sh_meta= (int*)(sh_rpb + 961);   // 256

    int w = blockIdx.x >> 3, hh = blockIdx.x & 7;
    int tid = threadIdx.x, lane = tid & 31, warp = tid >> 5;
    int tg = lane >> 2, tq = lane & 3;
    int qb = warp * 32;

    for (int j = tid; j < 1536; j += 256) {
        int c2 = j / 96, col = j - c2 * 96;
        int gcol = (col >> 5) * 256 + hh * 32 + (col & 31);
        sh_w[c2*104 + col] = pk(qkvw[(2*c2)*768 + gcol], qkvw[(2*c2+1)*768 + gcol]);
    }
    if (tid < 96) sh_b[tid] = qkvb[(tid>>5)*256 + hh*32 + (tid&31)];
    for (int j = tid; j < 961; j += 256) sh_rpb[j] = rpbt[j*8 + hh];
    {
        int n = tid, ww = w & 63;
        int ry = (ww>>3)*16 + (n>>4), rx = (ww&7)*16 + (n&15);
        int hr = ry < 112 ? 0 : (ry < 120 ? 1 : 2);
        int wr = rx < 112 ? 0 : (rx < 120 ? 1 : 2);
        sh_meta[n] = ((n>>4)*31 + (n&15)) | ((hr*3+wr) << 16);
    }
    for (int j = tid; j < 4096; j += 256) {
        int tok = j >> 4, c2 = j & 15;
        sh_h[tok*20 + c2] = g_hwin[((size_t)w*NTOK + tok)*16 + c2];
    }
    __syncthreads();

    // ---- QKV projection: 32 rows x 96 cols, K=32 ----
    {
        float acc[2][12][4];
#pragma unroll
        for (int mt=0; mt<2; mt++)
#pragma unroll
            for (int nt=0; nt<12; nt++)
#pragma unroll
                for (int r=0; r<4; r++) acc[mt][nt][r] = 0.f;
#pragma unroll
        for (int ks = 0; ks < 2; ks++) {
            int k2b = ks * 8;
            unsigned A[2][4];
#pragma unroll
            for (int mt=0; mt<2; mt++) {
                int r = qb + mt*16 + tg;
                A[mt][0]=sh_h[r*20 + k2b+tq];
                A[mt][1]=sh_h[(r+8)*20 + k2b+tq];
                A[mt][2]=sh_h[r*20 + k2b+tq+4];
                A[mt][3]=sh_h[(r+8)*20 + k2b+tq+4];
            }
#pragma unroll
            for (int nt=0; nt<12; nt++) {
                unsigned B[2];
                B[0]=sh_w[(k2b+tq)*104 + nt*8+tg];
                B[1]=sh_w[(k2b+tq+4)*104 + nt*8+tg];
                mma_bf16(acc[0][nt], A[0], B);
                mma_bf16(acc[1][nt], A[1], B);
            }
        }
        __nv_bfloat16* vb = (__nv_bfloat16*)sh_v;
#pragma unroll
        for (int mt=0; mt<2; mt++)
#pragma unroll
        for (int nt=0; nt<12; nt++) {
            int sec = nt >> 2, col = (nt&3)*8 + 2*tq;
            int r0 = qb + mt*16 + tg;
            float bb0 = sh_b[sec*32+col], bb1 = sh_b[sec*32+col+1];
            float v0=acc[mt][nt][0]+bb0, v1=acc[mt][nt][1]+bb1;
            float v2=acc[mt][nt][2]+bb0, v3=acc[mt][nt][3]+bb1;
            if (sec == 0) {
                const float SC = 0.17677669529663688f;
                sh_q[r0*20 + (col>>1)]     = pk(v0*SC, v1*SC);
                sh_q[(r0+8)*20 + (col>>1)] = pk(v2*SC, v3*SC);
            } else if (sec == 1) {
                sh_kT[(col>>1)*264 + r0]   = pk(v0, v1);
                sh_kT[(col>>1)*264 + r0+8] = pk(v2, v3);
            } else {
                int r1 = r0 + 8, par = r0 & 1;
                vb[(r0>>1)*80 + col*2     + par] = __float2bfloat16(v0);
                vb[(r0>>1)*80 + (col+1)*2 + par] = __float2bfloat16(v1);
                vb[(r1>>1)*80 + col*2     + par] = __float2bfloat16(v2);
                vb[(r1>>1)*80 + (col+1)*2 + par] = __float2bfloat16(v3);
            }
        }
    }
    __syncthreads();

    // ---- flash attention over 8 key chunks of 32 ----
    int rb[2][2], rid[2][2];
#pragma unroll
    for (int mt=0; mt<2; mt++)
#pragma unroll
        for (int h=0; h<2; h++) {
            int q = qb + mt*16 + tg + 8*h;
            rb[mt][h] = ((q>>4)+15)*31 + ((q&15)+15);
            rid[mt][h] = sh_meta[q] >> 16;
        }
    float rmax[2][2] = {{-1e30f,-1e30f},{-1e30f,-1e30f}};
    float rsum[2][2] = {{0.f,0.f},{0.f,0.f}};
    float o[2][4][4];
#pragma unroll
    for (int mt=0; mt<2; mt++)
#pragma unroll
        for (int nt=0; nt<4; nt++)
#pragma unroll
            for (int r=0; r<4; r++) o[mt][nt][r] = 0.f;

    unsigned* shp = sh_h + warp * 640;   // 32 x 20 warp-private P (bf16x2)

    for (int kc = 0; kc < 8; kc++) {
        int kb = kc * 32;
        float s[2][4][4];
#pragma unroll
        for (int mt=0; mt<2; mt++)
#pragma unroll
            for (int nt=0; nt<4; nt++)
#pragma unroll
                for (int r=0; r<4; r++) s[mt][nt][r] = 0.f;
#pragma unroll
        for (int ks = 0; ks < 2; ks++) {
            int k2b = ks * 8;
            unsigned A[2][4];
#pragma unroll
            for (int mt=0; mt<2; mt++) {
                int r = qb + mt*16 + tg;
                A[mt][0]=sh_q[r*20 + k2b+tq];
                A[mt][1]=sh_q[(r+8)*20 + k2b+tq];
                A[mt][2]=sh_q[r*20 + k2b+tq+4];
                A[mt][3]=sh_q[(r+8)*20 + k2b+tq+4];
            }
#pragma unroll
            for (int nt=0; nt<4; nt++) {
                unsigned B[2];
                int key = kb + nt*8 + tg;
                B[0]=sh_kT[(k2b+tq)*264 + key];
                B[1]=sh_kT[(k2b+tq+4)*264 + key];
                mma_bf16(s[0][nt], A[0], B);
                mma_bf16(s[1][nt], A[1], B);
            }
        }
#pragma unroll
        for (int nt=0; nt<4; nt++) {
            int k0i = kb + nt*8 + 2*tq;
            int me0 = sh_meta[k0i], me1 = sh_meta[k0i+1];
            int kf0 = me0 & 0xffff, kr0 = me0 >> 16;
            int kf1 = me1 & 0xffff, kr1 = me1 >> 16;
#pragma unroll
            for (int mt=0; mt<2; mt++) {
                s[mt][nt][0] += sh_rpb[rb[mt][0]-kf0] + (kr0 != rid[mt][0] ? -100.f : 0.f);
                s[mt][nt][1] += sh_rpb[rb[mt][0]-kf1] + (kr1 != rid[mt][0] ? -100.f : 0.f);
                s[mt][nt][2] += sh_rpb[rb[mt][1]-kf0] + (kr0 != rid[mt][1] ? -100.f : 0.f);
                s[mt][nt][3] += sh_rpb[rb[mt][1]-kf1] + (kr1 != rid[mt][1] ? -100.f : 0.f);
            }
        }
#pragma unroll
        for (int mt=0; mt<2; mt++)
#pragma unroll
        for (int h=0; h<2; h++) {
            float m = s[mt][0][2*h];
            m = fmaxf(m, s[mt][0][2*h+1]);
#pragma unroll
            for (int nt=1; nt<4; nt++) {
                m = fmaxf(m, s[mt][nt][2*h]); m = fmaxf(m, s[mt][nt][2*h+1]);
            }
            m = fmaxf(m, __shfl_xor_sync(0xffffffffu, m, 1));
            m = fmaxf(m, __shfl_xor_sync(0xffffffffu, m, 2));
            float nm = fmaxf(rmax[mt][h], m);
            float f = __expf(rmax[mt][h] - nm);
            rmax[mt][h] = nm;
            float ps = 0.f;
#pragma unroll
            for (int nt=0; nt<4; nt++) {
                float p0 = __expf(s[mt][nt][2*h]   - nm);
                float p1 = __expf(s[mt][nt][2*h+1] - nm);
                s[mt][nt][2*h] = p0; s[mt][nt][2*h+1] = p1;
                ps += p0 + p1;
            }
            ps += __shfl_xor_sync(0xffffffffu, ps, 1);
            ps += __shfl_xor_sync(0xffffffffu, ps, 2);
            rsum[mt][h] = rsum[mt][h] * f + ps;
#pragma unroll
            for (int nt=0; nt<4; nt++) { o[mt][nt][2*h] *= f; o[mt][nt][2*h+1] *= f; }
        }
#pragma unroll
        for (int mt=0; mt<2; mt++)
#pragma unroll
        for (int nt=0; nt<4; nt++) {
            int ql = mt*16 + tg, k2 = nt*4 + tq;
            shp[ql*20 + k2]     = pk(s[mt][nt][0], s[mt][nt][1]);
            shp[(ql+8)*20 + k2] = pk(s[mt][nt][2], s[mt][nt][3]);
        }
        __syncwarp();
#pragma unroll
        for (int ks = 0; ks < 2; ks++) {
            int k2b = ks * 8;
            unsigned A[2][4];
#pragma unroll
            for (int mt=0; mt<2; mt++) {
                int ql = mt*16 + tg;
                A[mt][0]=shp[ql*20 + k2b+tq];
                A[mt][1]=shp[(ql+8)*20 + k2b+tq];
                A[mt][2]=shp[ql*20 + k2b+tq+4];
                A[mt][3]=shp[(ql+8)*20 + k2b+tq+4];
            }
#pragma unroll
            for (int nt=0; nt<4; nt++) {
                unsigned B[2];
                int vr = kc*16 + k2b + tq;
                B[0]=sh_v[vr*40 + nt*8+tg];
                B[1]=sh_v[(vr+4)*40 + nt*8+tg];
                mma_bf16(o[0][nt], A[0], B);
                mma_bf16(o[1][nt], A[1], B);
            }
        }
        __syncwarp();
    }
#pragma unroll
    for (int mt=0; mt<2; mt++) {
        float i0 = 1.f/rsum[mt][0], i1 = 1.f/rsum[mt][1];
        int q = qb + mt*16 + tg;
        unsigned* d0 = g_oheads + ((size_t)w*256 + q)*128 + hh*16;
        unsigned* d1 = d0 + 8*128;
#pragma unroll
        for (int nt=0; nt<4; nt++) {
            int k2 = nt*4 + tq;
            d0[k2] = pk(o[mt][nt][0]*i0, o[mt][nt][1]*i0);
            d1[k2] = pk(o[mt][nt][2]*i1, o[mt][nt][3]*i1);
        }
    }
}

// ============ K3: rev mma + window reverse + residual ====================
#define REV_SMEM (22016*4)
__global__ void __launch_bounds__(256) k_rev(const float* __restrict__ x,
                                             const float* __restrict__ revw,
                                             const float* __restrict__ revb) {
    extern __shared__ unsigned smu[];
    unsigned* sh_o = smu;            // 128*132 [tok][k2]
    unsigned* sh_w = smu + 16896;    // 128*40  [k2][n]
    int tid = threadIdx.x, lane = tid & 31, warp = tid >> 5;
    int tg = lane >> 2, tq = lane & 3;
    long base = (long)blockIdx.x * 128;

    for (int j = tid; j < 4096; j += 256) {
        int k2 = j >> 5, n = j & 31;
        sh_w[k2*40 + n] = pk(revw[(2*k2)*32 + n], revw[(2*k2+1)*32 + n]);
    }
    for (int j = tid; j < 16384; j += 256) {
        int row = j >> 7, k2 = j & 127;
        long t = base + row;
        int b = (int)(t >> 14), p = (int)(t & 16383);
        int ry = ((p>>7) + 120) & 127, rx = ((p&127) + 120) & 127;
        int w = b*64 + (ry>>4)*8 + (rx>>4);
        int n = (ry&15)*16 + (rx&15);
        sh_o[row*132 + k2] = g_oheads[((size_t)w*NTOK + n)*128 + k2];
    }
    __syncthreads();

    float acc[4][4];
#pragma unroll
    for (int nt=0; nt<4; nt++)
#pragma unroll
        for (int r=0; r<4; r++) acc[nt][r] = 0.f;
    int r = warp*16 + tg;
#pragma unroll 4
    for (int ks = 0; ks < 16; ks++) {
        int k2b = ks * 8;
        unsigned A[4];
        A[0]=sh_o[r*132 + k2b+tq];
        A[1]=sh_o[(r+8)*132 + k2b+tq];
        A[2]=sh_o[r*132 + k2b+tq+4];
        A[3]=sh_o[(r+8)*132 + k2b+tq+4];
#pragma unroll
        for (int nt=0; nt<4; nt++) {
            unsigned B[2];
            B[0]=sh_w[(k2b+tq)*40 + nt*8+tg];
            B[1]=sh_w[(k2b+tq+4)*40 + nt*8+tg];
            mma_bf16(acc[nt], A, B);
        }
    }
    long t0 = base + warp*16 + tg;
#pragma unroll
    for (int nt=0; nt<4; nt++) {
        int col = nt*8 + 2*tq;
        float b0 = revb[col], b1 = revb[col+1];
        float2 x0 = *(const float2*)(x + t0*32 + col);
        float2 x1 = *(const float2*)(x + (t0+8)*32 + col);
        *(float2*)(g_xres + t0*32 + col)     = make_float2(x0.x+acc[nt][0]+b0, x0.y+acc[nt][1]+b1);
        *(float2*)(g_xres + (t0+8)*32 + col) = make_float2(x1.x+acc[nt][2]+b0, x1.y+acc[nt][3]+b1);
    }
}

// ============ K4: LN2 + lp1 mma (32->128) + GELU =========================
__global__ void __launch_bounds__(256) k_lp1(const float* __restrict__ n2g,
                                             const float* __restrict__ n2b,
                                             const float* __restrict__ w1,
                                             const float* __restrict__ bb1) {
    __shared__ unsigned sh_a[256*20];
    __shared__ unsigned sh_w[16*136];
    __shared__ float sh_b[128];
    int tid = threadIdx.x, lane = tid & 31, warp = tid >> 5;
    int tg = lane >> 2, tq = lane & 3;
    long base = (long)blockIdx.x * 256;

    for (int j = tid; j < 2048; j += 256) {
        int c2 = j >> 7, n = j & 127;
        sh_w[c2*136 + n] = pk(w1[(2*c2)*128 + n], w1[(2*c2+1)*128 + n]);
    }
    if (tid < 128) sh_b[tid] = bb1[tid];
    {
        long t = base + tid;
        float v[32];
        const float4* xp = (const float4*)(g_xres + t*32);
#pragma unroll
        for (int i = 0; i < 8; i++) {
            float4 q = xp[i];
            v[4*i]=q.x; v[4*i+1]=q.y; v[4*i+2]=q.z; v[4*i+3]=q.w;
        }
        float mean = 0.f;
#pragma unroll
        for (int c = 0; c < 32; c++) mean += v[c];
        mean *= (1.0f/32.0f);
        float var = 0.f;
#pragma unroll
        for (int c = 0; c < 32; c++) { float d = v[c]-mean; var += d*d; }
        float rstd = rsqrtf(var*(1.0f/32.0f) + 1e-5f);
#pragma unroll
        for (int i = 0; i < 16; i++) {
            float h0 = (v[2*i]-mean)*rstd*n2g[2*i] + n2b[2*i];
            float h1 = (v[2*i+1]-mean)*rstd*n2g[2*i+1] + n2b[2*i+1];
            sh_a[tid*20 + i] = pk(h0, h1);
        }
    }
    __syncthreads();

    float acc[2][16][4];
#pragma unroll
    for (int mt=0; mt<2; mt++)
#pragma unroll
        for (int nt=0; nt<16; nt++)
#pragma unroll
            for (int r=0; r<4; r++) acc[mt][nt][r] = 0.f;
#pragma unroll
    for (int ks = 0; ks < 2; ks++) {
        int k2b = ks * 8;
        unsigned A[2][4];
#pragma unroll
        for (int mt=0; mt<2; mt++) {
            int r = warp*32 + mt*16 + tg;
            A[mt][0]=sh_a[r*20 + k2b+tq];
            A[mt][1]=sh_a[(r+8)*20 + k2b+tq];
            A[mt][2]=sh_a[r*20 + k2b+tq+4];
            A[mt][3]=sh_a[(r+8)*20 + k2b+tq+4];
        }
#pragma unroll
        for (int nt=0; nt<16; nt++) {
            unsigned B[2];
            B[0]=sh_w[(k2b+tq)*136 + nt*8+tg];
            B[1]=sh_w[(k2b+tq+4)*136 + nt*8+tg];
            mma_bf16(acc[0][nt], A[0], B);
            mma_bf16(acc[1][nt], A[1], B);
        }
    }
#pragma unroll
    for (int mt=0; mt<2; mt++) {
        long t0 = base + warp*32 + mt*16 + tg;
#pragma unroll
        for (int nt=0; nt<16; nt++) {
            int col = nt*8 + 2*tq;
            float b0 = sh_b[col], b1 = sh_b[col+1];
            g_y1[t0*64 + (col>>1)]     = pk(gelu_exact(acc[mt][nt][0]+b0), gelu_exact(acc[mt][nt][1]+b1));
            g_y1[(t0+8)*64 + (col>>1)] = pk(gelu_exact(acc[mt][nt][2]+b0), gelu_exact(acc[mt][nt][3]+b1));
        }
    }
}

// ============ K5: 3x3 conv 128->128 implicit GEMM (bf16) ================
#define CIS 328
#define CONV_SMEM ((16*CIS + 144*136)*4)
__global__ void __launch_bounds__(256) k_conv(const float* __restrict__ cw,
                                              const float* __restrict__ cb) {
    extern __shared__ unsigned smu[];
    unsigned* sh_in = smu;             // [c2 16][pix 324] stride 328
    unsigned* sh_w  = smu + 16*CIS;    // [tap*16+c2][co 128] stride 136
    int bz = blockIdx.x;
    int b = bz >> 6;
    int y0 = ((bz >> 3) & 7) * 16;
    int x0 = (bz & 7) * 16;
    int tid = threadIdx.x, lane = tid & 31, warp = tid >> 5;
    int tg = lane >> 2, tq = lane & 3;
    int wm = warp >> 1, wn = warp & 1;

    float acc[4][8][4];
#pragma unroll
    for (int mt=0; mt<4; mt++)
#pragma unroll
        for (int nt=0; nt<8; nt++)
#pragma unroll
            for (int r=0; r<4; r++) acc[mt][nt][r] = 0.f;

    for (int ci0 = 0; ci0 < 128; ci0 += 32) {
        __syncthreads();
        int c2base = ci0 >> 1;
        for (int j = tid; j < 5184; j += 256) {
            int pix = j >> 4, c2 = j & 15;
            int py = pix / 18, px = pix - py*18;
            int gy = y0 - 1 + py, gx = x0 - 1 + px;
            unsigned v = 0;
            if ((unsigned)gy < 128u && (unsigned)gx < 128u)
                v = g_y1[((size_t)(b*16384 + gy*128 + gx))*64 + c2base + c2];
            sh_in[c2*CIS + pix] = v;
        }
        for (int j = tid; j < 18432; j += 256) {
            int row = j >> 7, co = j & 127;
            int tap = row >> 4, c2 = row & 15;
            int ci = ci0 + 2*c2;
            sh_w[row*136 + co] = pk(cw[((size_t)tap*128 + ci)*128 + co],
                                    cw[((size_t)tap*128 + ci + 1)*128 + co]);
        }
        __syncthreads();
#pragma unroll
        for (int tap = 0; tap < 9; tap++) {
            int ky = tap / 3, kx = tap % 3;
#pragma unroll
            for (int ks = 0; ks < 2; ks++) {
                int k2b = ks * 8;
                unsigned A[4][4];
#pragma unroll
                for (int mt=0; mt<4; mt++) {
                    int py = wm*4 + mt;
                    int pixL = (py+ky)*18 + tg + kx;
                    A[mt][0]=sh_in[(k2b+tq)*CIS + pixL];
                    A[mt][1]=sh_in[(k2b+tq)*CIS + pixL + 8];
                    A[mt][2]=sh_in[(k2b+tq+4)*CIS + pixL];
                    A[mt][3]=sh_in[(k2b+tq+4)*CIS + pixL + 8];
                }
#pragma unroll
                for (int nt=0; nt<8; nt++) {
                    unsigned B[2];
                    B[0]=sh_w[(tap*16 + k2b+tq)*136 + wn*64 + nt*8+tg];
                    B[1]=sh_w[(tap*16 + k2b+tq+4)*136 + wn*64 + nt*8+tg];
#pragma unroll
                    for (int mt=0; mt<4; mt++) mma_bf16(acc[mt][nt], A[mt], B);
                }
            }
        }
    }
#pragma unroll
    for (int mt=0; mt<4; mt++) {
        int gy = y0 + wm*4 + mt;
        unsigned* d0 = g_y2 + ((size_t)(b*16384 + gy*128 + x0 + tg))*64;
        unsigned* d1 = g_y2 + ((size_t)(b*16384 + gy*128 + x0 + tg + 8))*64;
#pragma unroll
        for (int nt=0; nt<8; nt++) {
            int col = wn*64 + nt*8 + 2*tq;
            float b0 = cb[col], b1 = cb[col+1];
            d0[col>>1] = pk(gelu_exact(acc[mt][nt][0]+b0), gelu_exact(acc[mt][nt][1]+b1));
            d1[col>>1] = pk(gelu_exact(acc[mt][nt][2]+b0), gelu_exact(acc[mt][nt][3]+b1));
        }
    }
}

// ============ K6: lp2 mma (128->32) + GELU + residual ===================
__global__ void __launch_bounds__(256) k_lp2(const float* __restrict__ w2,
                                             const float* __restrict__ b2,
                                             float* __restrict__ out) {
    __shared__ unsigned sh_a[128*68];
    __shared__ unsigned sh_w[64*40];
    int tid = threadIdx.x, lane = tid & 31, warp = tid >> 5;
    int tg = lane >> 2, tq = lane & 3;
    long base = (long)blockIdx.x * 128;

    for (int j = tid; j < 2048; j += 256) {
        int k2 = j >> 5, n = j & 31;
        sh_w[k2*40 + n] = pk(w2[(2*k2)*32 + n], w2[(2*k2+1)*32 + n]);
    }
    for (int j = tid; j < 8192; j += 256) {
        int row = j >> 6, k2 = j & 63;
        sh_a[row*68 + k2] = g_y2[(base + row)*64 + k2];
    }
    __syncthreads();

    float acc[4][4];
#pragma unroll
    for (int nt=0; nt<4; nt++)
#pragma unroll
        for (int r=0; r<4; r++) acc[nt][r] = 0.f;
    int r = warp*16 + tg;
#pragma unroll
    for (int ks = 0; ks < 8; ks++) {
        int k2b = ks * 8;
        unsigned A[4];
        A[0]=sh_a[r*68 + k2b+tq];
        A[1]=sh_a[(r+8)*68 + k2b+tq];
        A[2]=sh_a[r*68 + k2b+tq+4];
        A[3]=sh_a[(r+8)*68 + k2b+tq+4];
#pragma unroll
        for (int nt=0; nt<4; nt++) {
            unsigned B[2];
            B[0]=sh_w[(k2b+tq)*40 + nt*8+tg];
            B[1]=sh_w[(k2b+tq+4)*40 + nt*8+tg];
            mma_bf16(acc[nt], A, B);
        }
    }
    long t0 = base + warp*16 + tg;
#pragma unroll
    for (int nt=0; nt<4; nt++) {
        int col = nt*8 + 2*tq;
        float b0 = b2[col], b1 = b2[col+1];
        float2 x0 = *(const float2*)(g_xres + t0*32 + col);
        float2 x1 = *(const float2*)(g_xres + (t0+8)*32 + col);
        *(float2*)(out + t0*32 + col) =
            make_float2(gelu_exact(acc[nt][0]+b0)+x0.x, gelu_exact(acc[nt][1]+b1)+x0.y);
        *(float2*)(out + (t0+8)*32 + col) =
            make_float2(gelu_exact(acc[nt][2]+b0)+x1.x, gelu_exact(acc[nt][3]+b1)+x1.y);
    }
}

extern "C" void kernel_launch(void* const* d_in, const int* in_sizes, int n_in,
                              void* d_out, int out_size) {
    const float* x    = (const float*)d_in[0];
    const float* n1g  = (const float*)d_in[1];
    const float* n1b  = (const float*)d_in[2];
    const float* modw = (const float*)d_in[3];
    const float* qkvw = (const float*)d_in[4];
    const float* qkvb = (const float*)d_in[5];
    const float* rpbt = (const float*)d_in[6];
    const float* revw = (const float*)d_in[7];
    const float* revb = (const float*)d_in[8];
    const float* n2g  = (const float*)d_in[9];
    const float* n2b  = (const float*)d_in[10];
    const float* lp1w = (const float*)d_in[11];
    const float* lp1b = (const float*)d_in[12];
    const float* convw= (const float*)d_in[13];
    const float* convb= (const float*)d_in[14];
    const float* lp2w = (const float*)d_in[15];
    const float* lp2b = (const float*)d_in[16];
    float* out = (float*)d_out;

    cudaFuncSetAttribute(k_attn, cudaFuncAttributeMaxDynamicSharedMemorySize, ATTN_SMEM);
    cudaFuncSetAttribute(k_rev,  cudaFuncAttributeMaxDynamicSharedMemorySize, REV_SMEM);
    cudaFuncSetAttribute(k_conv, cudaFuncAttributeMaxDynamicSharedMemorySize, CONV_SMEM);

    k_ln1 <<<NWIN, 256>>>(x, n1g, n1b, modw);
    k_attn<<<NWIN * HH, 256, ATTN_SMEM>>>(qkvw, qkvb, rpbt);
    k_rev <<<NTOKENS / 128, 256, REV_SMEM>>>(x, revw, revb);
    k_lp1 <<<NTOKENS / 256, 256>>>(n2g, n2b, lp1w, lp1b);
    k_conv<<<8 * 8 * 8, 256, CONV_SMEM>>>(convw, convb);
    k_lp2 <<<NTOKENS / 128, 256>>>(lp2w, lp2b, out);
}

// round 5
// speedup vs baseline: 5.5108x; 1.2284x over previous
#include <cuda_runtime.h>
#include <cuda_bf16.h>
#include <math.h>

#define BQ 8
#define NTOK 256
#define HH 8
#define CC 32
#define INNER 128
#define NWIN 512
#define NTOKENS (BQ*128*128)

// packed bf16x2 intermediates
__device__ unsigned g_hwin[(size_t)NWIN*NTOK*16];
__device__ unsigned g_oheads[(size_t)NWIN*NTOK*128];
__device__ float    g_xres[(size_t)NTOKENS*CC];
__device__ unsigned g_y1[(size_t)NTOKENS*64];
__device__ unsigned g_y2[(size_t)NTOKENS*64];
// packed weights (zero-init pads)
__device__ unsigned g_pw_qkv[8*16*104];
__device__ unsigned g_pw_rev[128*40];
__device__ unsigned g_pw_w1[16*136];
__device__ unsigned g_pw_w2[64*40];
__device__ unsigned g_pw_cw[9*64*128];
__device__ float    g_rpbp[8*964];

__device__ __forceinline__ float gelu_exact(float x) {
    return 0.5f * x * (1.0f + erff(x * 0.70710678118654752440f));
}
__device__ __forceinline__ unsigned pk(float a, float b) {
    __nv_bfloat162 t = __floats2bfloat162_rn(a, b);
    return *reinterpret_cast<unsigned*>(&t);
}
__device__ __forceinline__ void mma_bf16(float* c, const unsigned* a, const unsigned* b) {
    asm volatile("mma.sync.aligned.m16n8k16.row.col.f32.bf16.bf16.f32 "
        "{%0,%1,%2,%3},{%4,%5,%6,%7},{%8,%9},{%0,%1,%2,%3};"
        : "+f"(c[0]), "+f"(c[1]), "+f"(c[2]), "+f"(c[3])
        : "r"(a[0]), "r"(a[1]), "r"(a[2]), "r"(a[3]), "r"(b[0]), "r"(b[1]));
}

// ============ K0: one-time weight packing ================================
__global__ void k_pack(const float* __restrict__ qkvw, const float* __restrict__ revw,
                       const float* __restrict__ w1, const float* __restrict__ w2,
                       const float* __restrict__ cw, const float* __restrict__ rpbt) {
    int i = blockIdx.x * 256 + threadIdx.x;
    if (i < 73728) {
        int tap = i >> 13, r = i & 8191;
        int c2 = r >> 7, co = r & 127;
        g_pw_cw[i] = pk(cw[((size_t)tap*128 + 2*c2)*128 + co],
                        cw[((size_t)tap*128 + 2*c2 + 1)*128 + co]);
    }
    if (i < 12288) {
        int hh = i / 1536, r = i % 1536;
        int c2 = r / 96, col = r % 96;
        int gcol = (col >> 5)*256 + hh*32 + (col & 31);
        g_pw_qkv[(hh*16 + c2)*104 + col] = pk(qkvw[2*c2*768 + gcol], qkvw[(2*c2+1)*768 + gcol]);
    }
    if (i < 7688) {
        int hh = i / 961, j = i % 961;
        g_rpbp[hh*964 + j] = rpbt[j*8 + hh];
    }
    if (i < 4096) {
        int k2 = i >> 5, n = i & 31;
        g_pw_rev[k2*40 + n] = pk(revw[2*k2*32 + n], revw[(2*k2+1)*32 + n]);
    }
    if (i < 2048) {
        int c2 = i >> 7, n = i & 127;
        g_pw_w1[c2*136 + n] = pk(w1[2*c2*128 + n], w1[(2*c2+1)*128 + n]);
    }
    if (i < 2048) {
        int k2 = i >> 5, n = i & 31;
        g_pw_w2[k2*40 + n] = pk(w2[2*k2*32 + n], w2[(2*k2+1)*32 + n]);
    }
}

// ============ K1: LN1 + shift + window partition + modulator =============
__global__ void k_ln1(const float* __restrict__ x, const float* __restrict__ g1,
                      const float* __restrict__ b1, const float* __restrict__ modw) {
    int w = blockIdx.x, n = threadIdx.x;
    int b = w >> 6, ww = w & 63;
    int ry = (ww >> 3)*16 + (n >> 4), rx = (ww & 7)*16 + (n & 15);
    int y = (ry + 8) & 127, xx = (rx + 8) & 127;
    const float* xp = x + ((size_t)b*16384 + (size_t)y*128 + xx)*CC;
    float v[CC];
#pragma unroll
    for (int i = 0; i < 8; i++) {
        float4 t = ((const float4*)xp)[i];
        v[4*i]=t.x; v[4*i+1]=t.y; v[4*i+2]=t.z; v[4*i+3]=t.w;
    }
    float mean = 0.f;
#pragma unroll
    for (int c = 0; c < CC; c++) mean += v[c];
    mean *= (1.0f/CC);
    float var = 0.f;
#pragma unroll
    for (int c = 0; c < CC; c++) { float d = v[c]-mean; var += d*d; }
    float rstd = rsqrtf(var*(1.0f/CC) + 1e-5f);
    unsigned* op = g_hwin + ((size_t)w*NTOK + n)*16;
#pragma unroll
    for (int i = 0; i < 16; i++) {
        int c = 2*i;
        op[i] = pk((v[c]-mean)*rstd*g1[c]+b1[c]+modw[n*CC+c],
                   (v[c+1]-mean)*rstd*g1[c+1]+b1[c+1]+modw[n*CC+c+1]);
    }
}

// ============ K2: QKV mma + flash window attention (bf16) ===============
#define ATTN_SMEM (22561*4)
__global__ void __launch_bounds__(256,2) k_attn(const float* __restrict__ qkvb) {
    extern __shared__ unsigned smu[];
    unsigned* sh_h  = smu;              // 256*20 (later per-warp P: 8*640)
    unsigned* sh_q  = sh_h + 5120;
    unsigned* sh_kT = sh_q + 5120;      // 16*264
    unsigned* sh_v  = sh_kT + 4224;     // 128*40
    unsigned* sh_w  = sh_v + 5120;      // 16*104
    float* sh_b   = (float*)(sh_w + 1664);  // 96
    float* sh_rpb = sh_b + 96;              // 961
    int*   sh_meta= (int*)(sh_rpb + 961);   // 256

    int w = blockIdx.x >> 3, hh = blockIdx.x & 7;
    int tid = threadIdx.x, lane = tid & 31, warp = tid >> 5;
    int tg = lane >> 2, tq = lane & 3;
    int qb = warp * 32;

    {   // copy-only staging
        const uint4* src = (const uint4*)(g_pw_qkv + hh*1664);
        uint4* dst = (uint4*)sh_w;
        for (int j = tid; j < 416; j += 256) dst[j] = src[j];
    }
    if (tid < 96) sh_b[tid] = qkvb[(tid>>5)*256 + hh*32 + (tid&31)];
    for (int j = tid; j < 961; j += 256) sh_rpb[j] = g_rpbp[hh*964 + j];
    {
        int n = tid, ww = w & 63;
        int ry = (ww>>3)*16 + (n>>4), rx = (ww&7)*16 + (n&15);
        int hr = ry < 112 ? 0 : (ry < 120 ? 1 : 2);
        int wr = rx < 112 ? 0 : (rx < 120 ? 1 : 2);
        sh_meta[n] = ((n>>4)*31 + (n&15)) | ((hr*3+wr) << 16);
    }
    for (int j = tid; j < 1024; j += 256) {
        int tok = j >> 2, q = j & 3;
        ((uint4*)(sh_h + tok*20))[q] = ((const uint4*)(g_hwin + ((size_t)w*NTOK + tok)*16))[q];
    }
    __syncthreads();

    // ---- QKV projection, section by section (Q, K, V) ----
    __nv_bfloat16* vb = (__nv_bfloat16*)sh_v;
#pragma unroll
    for (int sec = 0; sec < 3; sec++) {
        float acc[2][4][4];
#pragma unroll
        for (int mt=0; mt<2; mt++)
#pragma unroll
            for (int nt=0; nt<4; nt++)
#pragma unroll
                for (int r=0; r<4; r++) acc[mt][nt][r] = 0.f;
#pragma unroll
        for (int ks = 0; ks < 2; ks++) {
            int k2b = ks*8;
            unsigned A[2][4];
#pragma unroll
            for (int mt=0; mt<2; mt++) {
                int r = qb + mt*16 + tg;
                A[mt][0]=sh_h[r*20 + k2b+tq];
                A[mt][1]=sh_h[(r+8)*20 + k2b+tq];
                A[mt][2]=sh_h[r*20 + k2b+tq+4];
                A[mt][3]=sh_h[(r+8)*20 + k2b+tq+4];
            }
#pragma unroll
            for (int nt=0; nt<4; nt++) {
                unsigned B[2];
                B[0]=sh_w[(k2b+tq)*104 + sec*32 + nt*8+tg];
                B[1]=sh_w[(k2b+tq+4)*104 + sec*32 + nt*8+tg];
                mma_bf16(acc[0][nt], A[0], B);
                mma_bf16(acc[1][nt], A[1], B);
            }
        }
#pragma unroll
        for (int mt=0; mt<2; mt++)
#pragma unroll
        for (int nt=0; nt<4; nt++) {
            int col = nt*8 + 2*tq;
            int r0 = qb + mt*16 + tg;
            float bb0 = sh_b[sec*32+col], bb1 = sh_b[sec*32+col+1];
            float v0=acc[mt][nt][0]+bb0, v1=acc[mt][nt][1]+bb1;
            float v2=acc[mt][nt][2]+bb0, v3=acc[mt][nt][3]+bb1;
            if (sec == 0) {
                const float SC = 0.17677669529663688f;
                sh_q[r0*20 + (col>>1)]     = pk(v0*SC, v1*SC);
                sh_q[(r0+8)*20 + (col>>1)] = pk(v2*SC, v3*SC);
            } else if (sec == 1) {
                sh_kT[(col>>1)*264 + r0]   = pk(v0, v1);
                sh_kT[(col>>1)*264 + r0+8] = pk(v2, v3);
            } else {
                int r1 = r0 + 8, par = r0 & 1;
                vb[(r0>>1)*80 + col*2     + par] = __float2bfloat16(v0);
                vb[(r0>>1)*80 + (col+1)*2 + par] = __float2bfloat16(v1);
                vb[(r1>>1)*80 + col*2     + par] = __float2bfloat16(v2);
                vb[(r1>>1)*80 + (col+1)*2 + par] = __float2bfloat16(v3);
            }
        }
    }
    __syncthreads();

    // ---- flash attention over 8 key chunks of 32 ----
    int rb[2][2], rid[2][2];
#pragma unroll
    for (int mt=0; mt<2; mt++)
#pragma unroll
        for (int h=0; h<2; h++) {
            int q = qb + mt*16 + tg + 8*h;
            rb[mt][h] = ((q>>4)+15)*31 + ((q&15)+15);
            rid[mt][h] = sh_meta[q] >> 16;
        }
    float rmax[2][2] = {{-1e30f,-1e30f},{-1e30f,-1e30f}};
    float rsum[2][2] = {{0.f,0.f},{0.f,0.f}};
    float o[2][4][4];
#pragma unroll
    for (int mt=0; mt<2; mt++)
#pragma unroll
        for (int nt=0; nt<4; nt++)
#pragma unroll
            for (int r=0; r<4; r++) o[mt][nt][r] = 0.f;

    unsigned* shp = sh_h + warp * 640;

    for (int kc = 0; kc < 8; kc++) {
        int kb = kc * 32;
        float s[2][4][4];
#pragma unroll
        for (int mt=0; mt<2; mt++)
#pragma unroll
            for (int nt=0; nt<4; nt++)
#pragma unroll
                for (int r=0; r<4; r++) s[mt][nt][r] = 0.f;
#pragma unroll
        for (int ks = 0; ks < 2; ks++) {
            int k2b = ks*8;
            unsigned A[2][4];
#pragma unroll
            for (int mt=0; mt<2; mt++) {
                int r = qb + mt*16 + tg;
                A[mt][0]=sh_q[r*20 + k2b+tq];
                A[mt][1]=sh_q[(r+8)*20 + k2b+tq];
                A[mt][2]=sh_q[r*20 + k2b+tq+4];
                A[mt][3]=sh_q[(r+8)*20 + k2b+tq+4];
            }
#pragma unroll
            for (int nt=0; nt<4; nt++) {
                unsigned B[2];
                int key = kb + nt*8 + tg;
                B[0]=sh_kT[(k2b+tq)*264 + key];
                B[1]=sh_kT[(k2b+tq+4)*264 + key];
                mma_bf16(s[0][nt], A[0], B);
                mma_bf16(s[1][nt], A[1], B);
            }
        }
#pragma unroll
        for (int nt=0; nt<4; nt++) {
            int k0i = kb + nt*8 + 2*tq;
            int me0 = sh_meta[k0i], me1 = sh_meta[k0i+1];
            int kf0 = me0 & 0xffff, kr0 = me0 >> 16;
            int kf1 = me1 & 0xffff, kr1 = me1 >> 16;
#pragma unroll
            for (int mt=0; mt<2; mt++) {
                s[mt][nt][0] += sh_rpb[rb[mt][0]-kf0] + (kr0 != rid[mt][0] ? -100.f : 0.f);
                s[mt][nt][1] += sh_rpb[rb[mt][0]-kf1] + (kr1 != rid[mt][0] ? -100.f : 0.f);
                s[mt][nt][2] += sh_rpb[rb[mt][1]-kf0] + (kr0 != rid[mt][1] ? -100.f : 0.f);
                s[mt][nt][3] += sh_rpb[rb[mt][1]-kf1] + (kr1 != rid[mt][1] ? -100.f : 0.f);
            }
        }
#pragma unroll
        for (int mt=0; mt<2; mt++)
#pragma unroll
        for (int h=0; h<2; h++) {
            float m = s[mt][0][2*h];
            m = fmaxf(m, s[mt][0][2*h+1]);
#pragma unroll
            for (int nt=1; nt<4; nt++) {
                m = fmaxf(m, s[mt][nt][2*h]); m = fmaxf(m, s[mt][nt][2*h+1]);
            }
            m = fmaxf(m, __shfl_xor_sync(0xffffffffu, m, 1));
            m = fmaxf(m, __shfl_xor_sync(0xffffffffu, m, 2));
            float nm = fmaxf(rmax[mt][h], m);
            float f = __expf(rmax[mt][h] - nm);
            rmax[mt][h] = nm;
            float ps = 0.f;
#pragma unroll
            for (int nt=0; nt<4; nt++) {
                float p0 = __expf(s[mt][nt][2*h]   - nm);
                float p1 = __expf(s[mt][nt][2*h+1] - nm);
                s[mt][nt][2*h] = p0; s[mt][nt][2*h+1] = p1;
                ps += p0 + p1;
            }
            ps += __shfl_xor_sync(0xffffffffu, ps, 1);
            ps += __shfl_xor_sync(0xffffffffu, ps, 2);
            rsum[mt][h] = rsum[mt][h] * f + ps;
#pragma unroll
            for (int nt=0; nt<4; nt++) { o[mt][nt][2*h] *= f; o[mt][nt][2*h+1] *= f; }
        }
#pragma unroll
        for (int mt=0; mt<2; mt++)
#pragma unroll
        for (int nt=0; nt<4; nt++) {
            int ql = mt*16 + tg, k2 = nt*4 + tq;
            shp[ql*20 + k2]     = pk(s[mt][nt][0], s[mt][nt][1]);
            shp[(ql+8)*20 + k2] = pk(s[mt][nt][2], s[mt][nt][3]);
        }
        __syncwarp();
#pragma unroll
        for (int ks = 0; ks < 2; ks++) {
            int k2b = ks*8;
            unsigned A[2][4];
#pragma unroll
            for (int mt=0; mt<2; mt++) {
                int ql = mt*16 + tg;
                A[mt][0]=shp[ql*20 + k2b+tq];
                A[mt][1]=shp[(ql+8)*20 + k2b+tq];
                A[mt][2]=shp[ql*20 + k2b+tq+4];
                A[mt][3]=shp[(ql+8)*20 + k2b+tq+4];
            }
#pragma unroll
            for (int nt=0; nt<4; nt++) {
                unsigned B[2];
                int vr = kc*16 + k2b + tq;
                B[0]=sh_v[vr*40 + nt*8+tg];
                B[1]=sh_v[(vr+4)*40 + nt*8+tg];
                mma_bf16(o[0][nt], A[0], B);
                mma_bf16(o[1][nt], A[1], B);
            }
        }
        __syncwarp();
    }
#pragma unroll
    for (int mt=0; mt<2; mt++) {
        float i0 = 1.f/rsum[mt][0], i1 = 1.f/rsum[mt][1];
        int q = qb + mt*16 + tg;
        unsigned* d0 = g_oheads + ((size_t)w*256 + q)*128 + hh*16;
        unsigned* d1 = d0 + 8*128;
#pragma unroll
        for (int nt=0; nt<4; nt++) {
            int k2 = nt*4 + tq;
            d0[k2] = pk(o[mt][nt][0]*i0, o[mt][nt][1]*i0);
            d1[k2] = pk(o[mt][nt][2]*i1, o[mt][nt][3]*i1);
        }
    }
}

// ============ K3: rev mma + residual + LN2 + lp1 mma + GELU (fused) =====
#define RL_SMEM ((26752 + 256)*4)
__global__ void __launch_bounds__(256,2) k_rev_lp1(const float* __restrict__ x,
        const float* __restrict__ revb, const float* __restrict__ n2g,
        const float* __restrict__ n2b, const float* __restrict__ bb1) {
    extern __shared__ unsigned smu[];
    unsigned* sh_o  = smu;           // 128*132
    unsigned* sh_wr = smu + 16896;   // 128*40
    unsigned* sh_a  = smu + 22016;   // 128*20
    unsigned* sh_w1 = smu + 24576;   // 16*136
    float* sh_f = (float*)(smu + 26752); // rb32, g32, bt32, b1 128
    int tid = threadIdx.x, lane = tid & 31, warp = tid >> 5;
    int tg = lane >> 2, tq = lane & 3;
    long base = (long)blockIdx.x * 128;

    for (int j = tid; j < 1280; j += 256) ((uint4*)sh_wr)[j] = ((const uint4*)g_pw_rev)[j];
    for (int j = tid; j < 544; j += 256)  ((uint4*)sh_w1)[j] = ((const uint4*)g_pw_w1)[j];
    if (tid < 32) { sh_f[tid] = revb[tid]; sh_f[32+tid] = n2g[tid]; sh_f[64+tid] = n2b[tid]; }
    if (tid < 128) sh_f[96+tid] = bb1[tid];
    for (int j = tid; j < 4096; j += 256) {
        int row = j >> 5, q = j & 31;
        long t = base + row;
        int b = (int)(t >> 14), p = (int)(t & 16383);
        int ry = ((p>>7) + 120) & 127, rx = ((p&127) + 120) & 127;
        int w = b*64 + (ry>>4)*8 + (rx>>4);
        int n = (ry&15)*16 + (rx&15);
        *(uint4*)(sh_o + row*132 + q*4) =
            ((const uint4*)(g_oheads + ((size_t)w*NTOK + n)*128))[q];
    }
    __syncthreads();

    // rev projection 128x32, K=256
    float acc[4][4];
#pragma unroll
    for (int nt=0; nt<4; nt++)
#pragma unroll
        for (int r=0; r<4; r++) acc[nt][r] = 0.f;
    int rr = warp*16 + tg;
#pragma unroll 4
    for (int ks = 0; ks < 16; ks++) {
        int k2b = ks*8;
        unsigned A[4];
        A[0]=sh_o[rr*132 + k2b+tq];
        A[1]=sh_o[(rr+8)*132 + k2b+tq];
        A[2]=sh_o[rr*132 + k2b+tq+4];
        A[3]=sh_o[(rr+8)*132 + k2b+tq+4];
#pragma unroll
        for (int nt=0; nt<4; nt++) {
            unsigned B[2];
            B[0]=sh_wr[(k2b+tq)*40 + nt*8+tg];
            B[1]=sh_wr[(k2b+tq+4)*40 + nt*8+tg];
            mma_bf16(acc[nt], A, B);
        }
    }
    // residual + write g_xres + LN on fragments
    long t0 = base + rr;
    float v0[4], v1[4], v2[4], v3[4];
#pragma unroll
    for (int nt=0; nt<4; nt++) {
        int col = nt*8 + 2*tq;
        float b0 = sh_f[col], b1 = sh_f[col+1];
        float2 x0 = *(const float2*)(x + t0*32 + col);
        float2 x1 = *(const float2*)(x + (t0+8)*32 + col);
        v0[nt]=acc[nt][0]+b0+x0.x; v1[nt]=acc[nt][1]+b1+x0.y;
        v2[nt]=acc[nt][2]+b0+x1.x; v3[nt]=acc[nt][3]+b1+x1.y;
        *(float2*)(g_xres + t0*32 + col)     = make_float2(v0[nt], v1[nt]);
        *(float2*)(g_xres + (t0+8)*32 + col) = make_float2(v2[nt], v3[nt]);
    }
    float sL=0.f, qL=0.f, sH=0.f, qH=0.f;
#pragma unroll
    for (int nt=0; nt<4; nt++) {
        sL += v0[nt]+v1[nt]; qL += v0[nt]*v0[nt]+v1[nt]*v1[nt];
        sH += v2[nt]+v3[nt]; qH += v2[nt]*v2[nt]+v3[nt]*v3[nt];
    }
    sL += __shfl_xor_sync(0xffffffffu, sL, 1); sL += __shfl_xor_sync(0xffffffffu, sL, 2);
    qL += __shfl_xor_sync(0xffffffffu, qL, 1); qL += __shfl_xor_sync(0xffffffffu, qL, 2);
    sH += __shfl_xor_sync(0xffffffffu, sH, 1); sH += __shfl_xor_sync(0xffffffffu, sH, 2);
    qH += __shfl_xor_sync(0xffffffffu, qH, 1); qH += __shfl_xor_sync(0xffffffffu, qH, 2);
    float mL = sL*(1.f/32.f), mH = sH*(1.f/32.f);
    float rL = rsqrtf(qL*(1.f/32.f) - mL*mL + 1e-5f);
    float rH = rsqrtf(qH*(1.f/32.f) - mH*mH + 1e-5f);
#pragma unroll
    for (int nt=0; nt<4; nt++) {
        int col = nt*8 + 2*tq;
        float g0 = sh_f[32+col], g1 = sh_f[33+col], bt0 = sh_f[64+col], bt1 = sh_f[65+col];
        sh_a[rr*20 + nt*4+tq]     = pk((v0[nt]-mL)*rL*g0+bt0, (v1[nt]-mL)*rL*g1+bt1);
        sh_a[(rr+8)*20 + nt*4+tq] = pk((v2[nt]-mH)*rH*g0+bt0, (v3[nt]-mH)*rH*g1+bt1);
    }
    __syncthreads();

    // lp1: 128x128, K=32
    float acc2[16][4];
#pragma unroll
    for (int nt=0; nt<16; nt++)
#pragma unroll
        for (int r=0; r<4; r++) acc2[nt][r] = 0.f;
#pragma unroll
    for (int ks = 0; ks < 2; ks++) {
        int k2b = ks*8;
        unsigned A[4];
        A[0]=sh_a[rr*20 + k2b+tq];
        A[1]=sh_a[(rr+8)*20 + k2b+tq];
        A[2]=sh_a[rr*20 + k2b+tq+4];
        A[3]=sh_a[(rr+8)*20 + k2b+tq+4];
#pragma unroll
        for (int nt=0; nt<16; nt++) {
            unsigned B[2];
            B[0]=sh_w1[(k2b+tq)*136 + nt*8+tg];
            B[1]=sh_w1[(k2b+tq+4)*136 + nt*8+tg];
            mma_bf16(acc2[nt], A, B);
        }
    }
#pragma unroll
    for (int nt=0; nt<16; nt++) {
        int col = nt*8 + 2*tq;
        float b0 = sh_f[96+col], b1 = sh_f[97+col];
        g_y1[t0*64 + (col>>1)]     = pk(gelu_exact(acc2[nt][0]+b0), gelu_exact(acc2[nt][1]+b1));
        g_y1[(t0+8)*64 + (col>>1)] = pk(gelu_exact(acc2[nt][2]+b0), gelu_exact(acc2[nt][3]+b1));
    }
}

// ============ K5: 3x3 conv 128->128 implicit GEMM (bf16) ================
#define CIS 184
#define CONV_SMEM ((16*CIS + 144*136)*4)
__global__ void __launch_bounds__(256,2) k_conv(const float* __restrict__ cb) {
    extern __shared__ unsigned smu[];
    unsigned* sh_in = smu;             // [c2 16][pix 180] stride 184
    unsigned* sh_w  = smu + 16*CIS;    // [tap*16+c2][co 128] stride 136
    int bz = blockIdx.x;
    int b = bz >> 7;
    int y0 = ((bz >> 3) & 15) * 8;
    int x0 = (bz & 7) * 16;
    int tid = threadIdx.x, lane = tid & 31, warp = tid >> 5;
    int tg = lane >> 2, tq = lane & 3;
    int wm = warp & 1, wn = warp >> 1;

    float acc[4][4][4];
#pragma unroll
    for (int mt=0; mt<4; mt++)
#pragma unroll
        for (int nt=0; nt<4; nt++)
#pragma unroll
            for (int r=0; r<4; r++) acc[mt][nt][r] = 0.f;

    for (int ci0 = 0; ci0 < 128; ci0 += 32) {
        int c2b = ci0 >> 1;
        __syncthreads();
        for (int j = tid; j < 720; j += 256) {
            int pix = j >> 2, q = j & 3;
            int py = pix / 18, px = pix - py*18;
            int gy = y0 - 1 + py, gx = x0 - 1 + px;
            uint4 v = make_uint4(0,0,0,0);
            if ((unsigned)gy < 128u && (unsigned)gx < 128u)
                v = *(const uint4*)(g_y1 + ((size_t)(b*16384 + gy*128 + gx))*64 + c2b + q*4);
            sh_in[(q*4+0)*CIS + pix] = v.x;
            sh_in[(q*4+1)*CIS + pix] = v.y;
            sh_in[(q*4+2)*CIS + pix] = v.z;
            sh_in[(q*4+3)*CIS + pix] = v.w;
        }
        for (int j = tid; j < 4608; j += 256) {
            int row = j >> 5, q = j & 31;
            int tap = row >> 4, c2l = row & 15;
            *(uint4*)(sh_w + row*136 + q*4) =
                *(const uint4*)(g_pw_cw + ((size_t)tap*64 + c2b + c2l)*128 + q*4);
        }
        __syncthreads();
#pragma unroll
        for (int tap = 0; tap < 9; tap++) {
            int ky = tap / 3, kx = tap % 3;
#pragma unroll
            for (int ks = 0; ks < 2; ks++) {
                int k2b = ks*8;
                unsigned A[4][4];
#pragma unroll
                for (int mt=0; mt<4; mt++) {
                    int pixL = (wm*4 + mt + ky)*18 + tg + kx;
                    A[mt][0]=sh_in[(k2b+tq)*CIS + pixL];
                    A[mt][1]=sh_in[(k2b+tq)*CIS + pixL + 8];
                    A[mt][2]=sh_in[(k2b+tq+4)*CIS + pixL];
                    A[mt][3]=sh_in[(k2b+tq+4)*CIS + pixL + 8];
                }
#pragma unroll
                for (int nt=0; nt<4; nt++) {
                    unsigned B[2];
                    B[0]=sh_w[(tap*16 + k2b+tq)*136 + wn*32 + nt*8+tg];
                    B[1]=sh_w[(tap*16 + k2b+tq+4)*136 + wn*32 + nt*8+tg];
#pragma unroll
                    for (int mt=0; mt<4; mt++) mma_bf16(acc[mt][nt], A[mt], B);
                }
            }
        }
    }
#pragma unroll
    for (int mt=0; mt<4; mt++) {
        int gy = y0 + wm*4 + mt;
        unsigned* d0 = g_y2 + ((size_t)(b*16384 + gy*128 + x0 + tg))*64;
        unsigned* d1 = g_y2 + ((size_t)(b*16384 + gy*128 + x0 + tg + 8))*64;
#pragma unroll
        for (int nt=0; nt<4; nt++) {
            int col = wn*32 + nt*8 + 2*tq;
            float b0 = cb[col], b1 = cb[col+1];
            d0[col>>1] = pk(gelu_exact(acc[mt][nt][0]+b0), gelu_exact(acc[mt][nt][1]+b1));
            d1[col>>1] = pk(gelu_exact(acc[mt][nt][2]+b0), gelu_exact(acc[mt][nt][3]+b1));
        }
    }
}

// ============ K6: lp2 mma (128->32) + GELU + residual ===================
__global__ void __launch_bounds__(256) k_lp2(const float* __restrict__ b2,
                                             float* __restrict__ out) {
    __shared__ unsigned sh_a[128*68];
    __shared__ unsigned sh_w[64*40];
    int tid = threadIdx.x, lane = tid & 31, warp = tid >> 5;
    int tg = lane >> 2, tq = lane & 3;
    long base = (long)blockIdx.x * 128;

    for (int j = tid; j < 640; j += 256) ((uint4*)sh_w)[j] = ((const uint4*)g_pw_w2)[j];
    for (int j = tid; j < 2048; j += 256) {
        int row = j >> 4, q = j & 15;
        *(uint4*)(sh_a + row*68 + q*4) = ((const uint4*)(g_y2 + (base + row)*64))[q];
    }
    __syncthreads();

    float acc[4][4];
#pragma unroll
    for (int nt=0; nt<4; nt++)
#pragma unroll
        for (int r=0; r<4; r++) acc[nt][r] = 0.f;
    int r = warp*16 + tg;
#pragma unroll
    for (int ks = 0; ks < 8; ks++) {
        int k2b = ks*8;
        unsigned A[4];
        A[0]=sh_a[r*68 + k2b+tq];
        A[1]=sh_a[(r+8)*68 + k2b+tq];
        A[2]=sh_a[r*68 + k2b+tq+4];
        A[3]=sh_a[(r+8)*68 + k2b+tq+4];
#pragma unroll
        for (int nt=0; nt<4; nt++) {
            unsigned B[2];
            B[0]=sh_w[(k2b+tq)*40 + nt*8+tg];
            B[1]=sh_w[(k2b+tq+4)*40 + nt*8+tg];
            mma_bf16(acc[nt], A, B);
        }
    }
    long t0 = base + warp*16 + tg;
#pragma unroll
    for (int nt=0; nt<4; nt++) {
        int col = nt*8 + 2*tq;
        float b0 = b2[col], b1 = b2[col+1];
        float2 x0 = *(const float2*)(g_xres + t0*32 + col);
        float2 x1 = *(const float2*)(g_xres + (t0+8)*32 + col);
        *(float2*)(out + t0*32 + col) =
            make_float2(gelu_exact(acc[nt][0]+b0)+x0.x, gelu_exact(acc[nt][1]+b1)+x0.y);
        *(float2*)(out + (t0+8)*32 + col) =
            make_float2(gelu_exact(acc[nt][2]+b0)+x1.x, gelu_exact(acc[nt][3]+b1)+x1.y);
    }
}

extern "C" void kernel_launch(void* const* d_in, const int* in_sizes, int n_in,
                              void* d_out, int out_size) {
    const float* x    = (const float*)d_in[0];
    const float* n1g  = (const float*)d_in[1];
    const float* n1b  = (const float*)d_in[2];
    const float* modw = (const float*)d_in[3];
    const float* qkvw = (const float*)d_in[4];
    const float* qkvb = (const float*)d_in[5];
    const float* rpbt = (const float*)d_in[6];
    const float* revw = (const float*)d_in[7];
    const float* revb = (const float*)d_in[8];
    const float* n2g  = (const float*)d_in[9];
    const float* n2b  = (const float*)d_in[10];
    const float* lp1w = (const float*)d_in[11];
    const float* lp1b = (const float*)d_in[12];
    const float* convw= (const float*)d_in[13];
    const float* convb= (const float*)d_in[14];
    const float* lp2w = (const float*)d_in[15];
    const float* lp2b = (const float*)d_in[16];
    float* out = (float*)d_out;

    cudaFuncSetAttribute(k_attn, cudaFuncAttributeMaxDynamicSharedMemorySize, ATTN_SMEM);
    cudaFuncSetAttribute(k_rev_lp1, cudaFuncAttributeMaxDynamicSharedMemorySize, RL_SMEM);
    cudaFuncSetAttribute(k_conv, cudaFuncAttributeMaxDynamicSharedMemorySize, CONV_SMEM);

    k_pack<<<288, 256>>>(qkvw, revw, lp1w, lp2w, convw, rpbt);
    k_ln1 <<<NWIN, 256>>>(x, n1g, n1b, modw);
    k_attn<<<NWIN * HH, 256, ATTN_SMEM>>>(qkvb);
    k_rev_lp1<<<NTOKENS / 128, 256, RL_SMEM>>>(x, revb, n2g, n2b, lp1b);
    k_conv<<<BQ * 16 * 8, 256, CONV_SMEM>>>(convb);
    k_lp2 <<<NTOKENS / 128, 256>>>(lp2b, out);
}

// round 6
// speedup vs baseline: 5.9349x; 1.0770x over previous
#include <cuda_runtime.h>
#include <cuda_bf16.h>
#include <math.h>

#define BQ 8
#define NTOK 256
#define HH 8
#define CC 32
#define INNER 128
#define NWIN 512
#define NTOKENS (BQ*128*128)

// packed bf16x2 intermediates
__device__ unsigned g_hwin[(size_t)NWIN*NTOK*16];
__device__ unsigned g_oheads[(size_t)NWIN*NTOK*128];
__device__ float    g_xres[(size_t)NTOKENS*CC];
__device__ unsigned g_y1[(size_t)NTOKENS*64];
// packed weights (zero-init pads)
__device__ unsigned g_pw_qkv[8*16*104];
__device__ unsigned g_pw_rev[128*40];
__device__ unsigned g_pw_w1[16*136];
__device__ unsigned g_pw_w2[64*40];
__device__ unsigned g_pw_cw[9*64*128];
__device__ float    g_rpbp[8*964];

__device__ __forceinline__ float gelu_exact(float x) {
    return 0.5f * x * (1.0f + erff(x * 0.70710678118654752440f));
}
__device__ __forceinline__ unsigned pk(float a, float b) {
    __nv_bfloat162 t = __floats2bfloat162_rn(a, b);
    return *reinterpret_cast<unsigned*>(&t);
}
__device__ __forceinline__ void mma_bf16(float* c, const unsigned* a, const unsigned* b) {
    asm volatile("mma.sync.aligned.m16n8k16.row.col.f32.bf16.bf16.f32 "
        "{%0,%1,%2,%3},{%4,%5,%6,%7},{%8,%9},{%0,%1,%2,%3};"
        : "+f"(c[0]), "+f"(c[1]), "+f"(c[2]), "+f"(c[3])
        : "r"(a[0]), "r"(a[1]), "r"(a[2]), "r"(a[3]), "r"(b[0]), "r"(b[1]));
}

// ============ K0: one-time weight packing ================================
__global__ void k_pack(const float* __restrict__ qkvw, const float* __restrict__ revw,
                       const float* __restrict__ w1, const float* __restrict__ w2,
                       const float* __restrict__ cw, const float* __restrict__ rpbt) {
    int i = blockIdx.x * 256 + threadIdx.x;
    if (i < 73728) {
        int tap = i >> 13, r = i & 8191;
        int c2 = r >> 7, co = r & 127;
        g_pw_cw[i] = pk(cw[((size_t)tap*128 + 2*c2)*128 + co],
                        cw[((size_t)tap*128 + 2*c2 + 1)*128 + co]);
    }
    if (i < 12288) {
        int hh = i / 1536, r = i % 1536;
        int c2 = r / 96, col = r % 96;
        int gcol = (col >> 5)*256 + hh*32 + (col & 31);
        g_pw_qkv[(hh*16 + c2)*104 + col] = pk(qkvw[2*c2*768 + gcol], qkvw[(2*c2+1)*768 + gcol]);
    }
    if (i < 7688) {
        int hh = i / 961, j = i % 961;
        g_rpbp[hh*964 + j] = rpbt[j*8 + hh];
    }
    if (i < 4096) {
        int k2 = i >> 5, n = i & 31;
        g_pw_rev[k2*40 + n] = pk(revw[2*k2*32 + n], revw[(2*k2+1)*32 + n]);
    }
    if (i < 2048) {
        int c2 = i >> 7, n = i & 127;
        g_pw_w1[c2*136 + n] = pk(w1[2*c2*128 + n], w1[(2*c2+1)*128 + n]);
    }
    if (i < 2048) {
        int k2 = i >> 5, n = i & 31;
        g_pw_w2[k2*40 + n] = pk(w2[2*k2*32 + n], w2[(2*k2+1)*32 + n]);
    }
}

// ============ K1: LN1 + shift + window partition + modulator =============
__global__ void k_ln1(const float* __restrict__ x, const float* __restrict__ g1,
                      const float* __restrict__ b1, const float* __restrict__ modw) {
    int w = blockIdx.x, n = threadIdx.x;
    int b = w >> 6, ww = w & 63;
    int ry = (ww >> 3)*16 + (n >> 4), rx = (ww & 7)*16 + (n & 15);
    int y = (ry + 8) & 127, xx = (rx + 8) & 127;
    const float* xp = x + ((size_t)b*16384 + (size_t)y*128 + xx)*CC;
    float v[CC];
#pragma unroll
    for (int i = 0; i < 8; i++) {
        float4 t = ((const float4*)xp)[i];
        v[4*i]=t.x; v[4*i+1]=t.y; v[4*i+2]=t.z; v[4*i+3]=t.w;
    }
    float mean = 0.f;
#pragma unroll
    for (int c = 0; c < CC; c++) mean += v[c];
    mean *= (1.0f/CC);
    float var = 0.f;
#pragma unroll
    for (int c = 0; c < CC; c++) { float d = v[c]-mean; var += d*d; }
    float rstd = rsqrtf(var*(1.0f/CC) + 1e-5f);
    unsigned* op = g_hwin + ((size_t)w*NTOK + n)*16;
#pragma unroll
    for (int i = 0; i < 16; i++) {
        int c = 2*i;
        op[i] = pk((v[c]-mean)*rstd*g1[c]+b1[c]+modw[n*CC+c],
                   (v[c+1]-mean)*rstd*g1[c+1]+b1[c+1]+modw[n*CC+c+1]);
    }
}

// ============ K2: QKV mma + flash window attention (frag passthrough) ===
#define ATTN_SMEM (12324*4)
__global__ void __launch_bounds__(256,3) k_attn(const float* __restrict__ qkvb) {
    extern __shared__ unsigned smu[];
    unsigned* sh_kT = smu;              // 16*264 [a2][key]
    unsigned* sh_v  = smu + 4224;       // 128*40 [key2][dim]
    unsigned* sh_w  = sh_v + 5120;      // 16*104
    float* sh_b   = (float*)(sh_w + 1664);  // 96
    float* sh_rpb = sh_b + 96;              // 964
    int*   sh_meta= (int*)(sh_rpb + 964);   // 256

    int w = blockIdx.x >> 3, hh = blockIdx.x & 7;
    int tid = threadIdx.x, lane = tid & 31, warp = tid >> 5;
    int tg = lane >> 2, tq = lane & 3;
    int qb = warp * 32;

    {
        const uint4* src = (const uint4*)(g_pw_qkv + hh*1664);
        uint4* dst = (uint4*)sh_w;
        for (int j = tid; j < 416; j += 256) dst[j] = src[j];
    }
    if (tid < 96) sh_b[tid] = qkvb[(tid>>5)*256 + hh*32 + (tid&31)];
    for (int j = tid; j < 961; j += 256) sh_rpb[j] = g_rpbp[hh*964 + j];
    {
        int n = tid, ww = w & 63;
        int ry = (ww>>3)*16 + (n>>4), rx = (ww&7)*16 + (n&15);
        int hr = ry < 112 ? 0 : (ry < 120 ? 1 : 2);
        int wr = rx < 112 ? 0 : (rx < 120 ? 1 : 2);
        sh_meta[n] = ((n>>4)*31 + (n&15)) | ((hr*3+wr) << 16);
    }
    // h A-fragments straight from global
    unsigned ha[2][8];
#pragma unroll
    for (int mt = 0; mt < 2; mt++) {
        const unsigned* h0 = g_hwin + ((size_t)w*256 + qb + mt*16 + tg)*16;
        const unsigned* h1 = h0 + 8*16;
        ha[mt][0]=h0[tq];    ha[mt][1]=h1[tq];
        ha[mt][2]=h0[tq+4];  ha[mt][3]=h1[tq+4];
        ha[mt][4]=h0[tq+8];  ha[mt][5]=h1[tq+8];
        ha[mt][6]=h0[tq+12]; ha[mt][7]=h1[tq+12];
    }
    __syncthreads();

    // ---- QKV projection; Q stays in fragments ----
    unsigned qrl[2][4], qrh[2][4];
    __nv_bfloat16* vb = (__nv_bfloat16*)sh_v;
#pragma unroll
    for (int sec = 0; sec < 3; sec++) {
        float acc[2][4][4];
#pragma unroll
        for (int mt=0; mt<2; mt++)
#pragma unroll
            for (int nt=0; nt<4; nt++)
#pragma unroll
                for (int r=0; r<4; r++) acc[mt][nt][r] = 0.f;
#pragma unroll
        for (int ks = 0; ks < 2; ks++) {
#pragma unroll
            for (int nt=0; nt<4; nt++) {
                unsigned B[2];
                B[0]=sh_w[(8*ks+tq)*104 + sec*32 + nt*8+tg];
                B[1]=sh_w[(8*ks+tq+4)*104 + sec*32 + nt*8+tg];
                mma_bf16(acc[0][nt], &ha[0][ks*4], B);
                mma_bf16(acc[1][nt], &ha[1][ks*4], B);
            }
        }
#pragma unroll
        for (int mt=0; mt<2; mt++)
#pragma unroll
        for (int nt=0; nt<4; nt++) {
            int col = nt*8 + 2*tq;
            int r0 = qb + mt*16 + tg;
            float bb0 = sh_b[sec*32+col], bb1 = sh_b[sec*32+col+1];
            float v0=acc[mt][nt][0]+bb0, v1=acc[mt][nt][1]+bb1;
            float v2=acc[mt][nt][2]+bb0, v3=acc[mt][nt][3]+bb1;
            if (sec == 0) {
                const float SC = 0.17677669529663688f;
                qrl[mt][nt] = pk(v0*SC, v1*SC);
                qrh[mt][nt] = pk(v2*SC, v3*SC);
            } else if (sec == 1) {
                sh_kT[(col>>1)*264 + r0]   = pk(v0, v1);
                sh_kT[(col>>1)*264 + r0+8] = pk(v2, v3);
            } else {
                int r1 = r0 + 8, par = r0 & 1;
                vb[(r0>>1)*80 + col*2     + par] = __float2bfloat16(v0);
                vb[(r0>>1)*80 + (col+1)*2 + par] = __float2bfloat16(v1);
                vb[(r1>>1)*80 + col*2     + par] = __float2bfloat16(v2);
                vb[(r1>>1)*80 + (col+1)*2 + par] = __float2bfloat16(v3);
            }
        }
    }
    __syncthreads();

    // ---- flash attention, no running max (scores bounded), P in frags ----
    int rb[2][2], rid[2][2];
#pragma unroll
    for (int mt=0; mt<2; mt++)
#pragma unroll
        for (int h=0; h<2; h++) {
            int q = qb + mt*16 + tg + 8*h;
            rb[mt][h] = ((q>>4)+15)*31 + ((q&15)+15);
            rid[mt][h] = sh_meta[q] >> 16;
        }
    float psL[2] = {0.f,0.f}, psH[2] = {0.f,0.f};
    float o[2][4][4];
#pragma unroll
    for (int mt=0; mt<2; mt++)
#pragma unroll
        for (int nt=0; nt<4; nt++)
#pragma unroll
            for (int r=0; r<4; r++) o[mt][nt][r] = 0.f;

    for (int kc = 0; kc < 8; kc++) {
        int kb = kc * 32;
        float s[2][4][4];
#pragma unroll
        for (int mt=0; mt<2; mt++)
#pragma unroll
            for (int nt=0; nt<4; nt++)
#pragma unroll
                for (int r=0; r<4; r++) s[mt][nt][r] = 0.f;
#pragma unroll
        for (int ks = 0; ks < 2; ks++) {
            unsigned A0[4] = {qrl[0][2*ks], qrh[0][2*ks], qrl[0][2*ks+1], qrh[0][2*ks+1]};
            unsigned A1[4] = {qrl[1][2*ks], qrh[1][2*ks], qrl[1][2*ks+1], qrh[1][2*ks+1]};
#pragma unroll
            for (int nt=0; nt<4; nt++) {
                unsigned B[2];
                int key = kb + nt*8 + tg;
                B[0]=sh_kT[(8*ks+tq)*264 + key];
                B[1]=sh_kT[(8*ks+tq+4)*264 + key];
                mma_bf16(s[0][nt], A0, B);
                mma_bf16(s[1][nt], A1, B);
            }
        }
        unsigned pl[2][4], ph[2][4];
#pragma unroll
        for (int nt=0; nt<4; nt++) {
            int k0i = kb + nt*8 + 2*tq;
            int me0 = sh_meta[k0i], me1 = sh_meta[k0i+1];
            int kf0 = me0 & 0xffff, kr0 = me0 >> 16;
            int kf1 = me1 & 0xffff, kr1 = me1 >> 16;
#pragma unroll
            for (int mt=0; mt<2; mt++) {
                float p0 = __expf(s[mt][nt][0] + sh_rpb[rb[mt][0]-kf0] + (kr0 != rid[mt][0] ? -100.f : 0.f));
                float p1 = __expf(s[mt][nt][1] + sh_rpb[rb[mt][0]-kf1] + (kr1 != rid[mt][0] ? -100.f : 0.f));
                float p2 = __expf(s[mt][nt][2] + sh_rpb[rb[mt][1]-kf0] + (kr0 != rid[mt][1] ? -100.f : 0.f));
                float p3 = __expf(s[mt][nt][3] + sh_rpb[rb[mt][1]-kf1] + (kr1 != rid[mt][1] ? -100.f : 0.f));
                psL[mt] += p0 + p1;
                psH[mt] += p2 + p3;
                pl[mt][nt] = pk(p0, p1);
                ph[mt][nt] = pk(p2, p3);
            }
        }
#pragma unroll
        for (int ks = 0; ks < 2; ks++) {
            unsigned A0[4] = {pl[0][2*ks], ph[0][2*ks], pl[0][2*ks+1], ph[0][2*ks+1]};
            unsigned A1[4] = {pl[1][2*ks], ph[1][2*ks], pl[1][2*ks+1], ph[1][2*ks+1]};
#pragma unroll
            for (int nt=0; nt<4; nt++) {
                unsigned B[2];
                int vr = kc*16 + ks*8 + tq;
                B[0]=sh_v[vr*40 + nt*8+tg];
                B[1]=sh_v[(vr+4)*40 + nt*8+tg];
                mma_bf16(o[0][nt], A0, B);
                mma_bf16(o[1][nt], A1, B);
            }
        }
    }
#pragma unroll
    for (int mt=0; mt<2; mt++) {
        float sL = psL[mt], sH = psH[mt];
        sL += __shfl_xor_sync(0xffffffffu, sL, 1); sL += __shfl_xor_sync(0xffffffffu, sL, 2);
        sH += __shfl_xor_sync(0xffffffffu, sH, 1); sH += __shfl_xor_sync(0xffffffffu, sH, 2);
        float i0 = 1.f/sL, i1 = 1.f/sH;
        int q = qb + mt*16 + tg;
        unsigned* d0 = g_oheads + ((size_t)w*256 + q)*128 + hh*16;
        unsigned* d1 = d0 + 8*128;
#pragma unroll
        for (int nt=0; nt<4; nt++) {
            int k2 = nt*4 + tq;
            d0[k2] = pk(o[mt][nt][0]*i0, o[mt][nt][1]*i0);
            d1[k2] = pk(o[mt][nt][2]*i1, o[mt][nt][3]*i1);
        }
    }
}

// ============ K3: rev mma + residual + LN2 + lp1 mma + GELU (fused) =====
#define RL_SMEM ((26752 + 256)*4)
__global__ void __launch_bounds__(256,2) k_rev_lp1(const float* __restrict__ x,
        const float* __restrict__ revb, const float* __restrict__ n2g,
        const float* __restrict__ n2b, const float* __restrict__ bb1) {
    extern __shared__ unsigned smu[];
    unsigned* sh_o  = smu;           // 128*132
    unsigned* sh_wr = smu + 16896;   // 128*40
    unsigned* sh_a  = smu + 22016;   // 128*20
    unsigned* sh_w1 = smu + 24576;   // 16*136
    float* sh_f = (float*)(smu + 26752);
    int tid = threadIdx.x, lane = tid & 31, warp = tid >> 5;
    int tg = lane >> 2, tq = lane & 3;
    long base = (long)blockIdx.x * 128;

    for (int j = tid; j < 1280; j += 256) ((uint4*)sh_wr)[j] = ((const uint4*)g_pw_rev)[j];
    for (int j = tid; j < 544; j += 256)  ((uint4*)sh_w1)[j] = ((const uint4*)g_pw_w1)[j];
    if (tid < 32) { sh_f[tid] = revb[tid]; sh_f[32+tid] = n2g[tid]; sh_f[64+tid] = n2b[tid]; }
    if (tid < 128) sh_f[96+tid] = bb1[tid];
    for (int j = tid; j < 4096; j += 256) {
        int row = j >> 5, q = j & 31;
        long t = base + row;
        int b = (int)(t >> 14), p = (int)(t & 16383);
        int ry = ((p>>7) + 120) & 127, rx = ((p&127) + 120) & 127;
        int w = b*64 + (ry>>4)*8 + (rx>>4);
        int n = (ry&15)*16 + (rx&15);
        *(uint4*)(sh_o + row*132 + q*4) =
            ((const uint4*)(g_oheads + ((size_t)w*NTOK + n)*128))[q];
    }
    __syncthreads();

    float acc[4][4];
#pragma unroll
    for (int nt=0; nt<4; nt++)
#pragma unroll
        for (int r=0; r<4; r++) acc[nt][r] = 0.f;
    int rr = warp*16 + tg;
#pragma unroll 4
    for (int ks = 0; ks < 16; ks++) {
        int k2b = ks*8;
        unsigned A[4];
        A[0]=sh_o[rr*132 + k2b+tq];
        A[1]=sh_o[(rr+8)*132 + k2b+tq];
        A[2]=sh_o[rr*132 + k2b+tq+4];
        A[3]=sh_o[(rr+8)*132 + k2b+tq+4];
#pragma unroll
        for (int nt=0; nt<4; nt++) {
            unsigned B[2];
            B[0]=sh_wr[(k2b+tq)*40 + nt*8+tg];
            B[1]=sh_wr[(k2b+tq+4)*40 + nt*8+tg];
            mma_bf16(acc[nt], A, B);
        }
    }
    long t0 = base + rr;
    float v0[4], v1[4], v2[4], v3[4];
#pragma unroll
    for (int nt=0; nt<4; nt++) {
        int col = nt*8 + 2*tq;
        float b0 = sh_f[col], b1 = sh_f[col+1];
        float2 x0 = *(const float2*)(x + t0*32 + col);
        float2 x1 = *(const float2*)(x + (t0+8)*32 + col);
        v0[nt]=acc[nt][0]+b0+x0.x; v1[nt]=acc[nt][1]+b1+x0.y;
        v2[nt]=acc[nt][2]+b0+x1.x; v3[nt]=acc[nt][3]+b1+x1.y;
        *(float2*)(g_xres + t0*32 + col)     = make_float2(v0[nt], v1[nt]);
        *(float2*)(g_xres + (t0+8)*32 + col) = make_float2(v2[nt], v3[nt]);
    }
    float sL=0.f, qL=0.f, sH=0.f, qH=0.f;
#pragma unroll
    for (int nt=0; nt<4; nt++) {
        sL += v0[nt]+v1[nt]; qL += v0[nt]*v0[nt]+v1[nt]*v1[nt];
        sH += v2[nt]+v3[nt]; qH += v2[nt]*v2[nt]+v3[nt]*v3[nt];
    }
    sL += __shfl_xor_sync(0xffffffffu, sL, 1); sL += __shfl_xor_sync(0xffffffffu, sL, 2);
    qL += __shfl_xor_sync(0xffffffffu, qL, 1); qL += __shfl_xor_sync(0xffffffffu, qL, 2);
    sH += __shfl_xor_sync(0xffffffffu, sH, 1); sH += __shfl_xor_sync(0xffffffffu, sH, 2);
    qH += __shfl_xor_sync(0xffffffffu, qH, 1); qH += __shfl_xor_sync(0xffffffffu, qH, 2);
    float mL = sL*(1.f/32.f), mH = sH*(1.f/32.f);
    float rL = rsqrtf(qL*(1.f/32.f) - mL*mL + 1e-5f);
    float rH = rsqrtf(qH*(1.f/32.f) - mH*mH + 1e-5f);
#pragma unroll
    for (int nt=0; nt<4; nt++) {
        int col = nt*8 + 2*tq;
        float g0 = sh_f[32+col], g1 = sh_f[33+col], bt0 = sh_f[64+col], bt1 = sh_f[65+col];
        sh_a[rr*20 + nt*4+tq]     = pk((v0[nt]-mL)*rL*g0+bt0, (v1[nt]-mL)*rL*g1+bt1);
        sh_a[(rr+8)*20 + nt*4+tq] = pk((v2[nt]-mH)*rH*g0+bt0, (v3[nt]-mH)*rH*g1+bt1);
    }
    __syncthreads();

    float acc2[16][4];
#pragma unroll
    for (int nt=0; nt<16; nt++)
#pragma unroll
        for (int r=0; r<4; r++) acc2[nt][r] = 0.f;
#pragma unroll
    for (int ks = 0; ks < 2; ks++) {
        int k2b = ks*8;
        unsigned A[4];
        A[0]=sh_a[rr*20 + k2b+tq];
        A[1]=sh_a[(rr+8)*20 + k2b+tq];
        A[2]=sh_a[rr*20 + k2b+tq+4];
        A[3]=sh_a[(rr+8)*20 + k2b+tq+4];
#pragma unroll
        for (int nt=0; nt<16; nt++) {
            unsigned B[2];
            B[0]=sh_w1[(k2b+tq)*136 + nt*8+tg];
            B[1]=sh_w1[(k2b+tq+4)*136 + nt*8+tg];
            mma_bf16(acc2[nt], A, B);
        }
    }
#pragma unroll
    for (int nt=0; nt<16; nt++) {
        int col = nt*8 + 2*tq;
        float b0 = sh_f[96+col], b1 = sh_f[97+col];
        g_y1[t0*64 + (col>>1)]     = pk(gelu_exact(acc2[nt][0]+b0), gelu_exact(acc2[nt][1]+b1));
        g_y1[(t0+8)*64 + (col>>1)] = pk(gelu_exact(acc2[nt][2]+b0), gelu_exact(acc2[nt][3]+b1));
    }
}

// ============ K5: 3x3 conv implicit GEMM + fused lp2 + residual =========
#define CIS 184
#define CONV_SMEM (25088*4)
__global__ void __launch_bounds__(256,2) k_conv(const float* __restrict__ cb,
                                                const float* __restrict__ b2,
                                                float* __restrict__ out) {
    extern __shared__ unsigned smu[];
    unsigned* sh_in = smu;               // [c2 16][pix 180] stride 184
    unsigned* sh_w  = smu + 16*CIS;      // [tap*16+c2][co 128] stride 136 (reused as sh_t)
    unsigned* sh_w2 = sh_w + 144*136;    // 64*40
    int bz = blockIdx.x;
    int b = bz >> 7;
    int y0 = ((bz >> 3) & 15) * 8;
    int x0 = (bz & 7) * 16;
    int tid = threadIdx.x, lane = tid & 31, warp = tid >> 5;
    int tg = lane >> 2, tq = lane & 3;
    int wm = warp & 1, wn = warp >> 1;

    for (int j = tid; j < 640; j += 256) ((uint4*)sh_w2)[j] = ((const uint4*)g_pw_w2)[j];

    float acc[4][4][4];
#pragma unroll
    for (int mt=0; mt<4; mt++)
#pragma unroll
        for (int nt=0; nt<4; nt++)
#pragma unroll
            for (int r=0; r<4; r++) acc[mt][nt][r] = 0.f;

    for (int ci0 = 0; ci0 < 128; ci0 += 32) {
        int c2b = ci0 >> 1;
        __syncthreads();
        for (int j = tid; j < 720; j += 256) {
            int pix = j >> 2, q = j & 3;
            int py = pix / 18, px = pix - py*18;
            int gy = y0 - 1 + py, gx = x0 - 1 + px;
            uint4 v = make_uint4(0,0,0,0);
            if ((unsigned)gy < 128u && (unsigned)gx < 128u)
                v = *(const uint4*)(g_y1 + ((size_t)(b*16384 + gy*128 + gx))*64 + c2b + q*4);
            sh_in[(q*4+0)*CIS + pix] = v.x;
            sh_in[(q*4+1)*CIS + pix] = v.y;
            sh_in[(q*4+2)*CIS + pix] = v.z;
            sh_in[(q*4+3)*CIS + pix] = v.w;
        }
        for (int j = tid; j < 4608; j += 256) {
            int row = j >> 5, q = j & 31;
            int tap = row >> 4, c2l = row & 15;
            *(uint4*)(sh_w + row*136 + q*4) =
                *(const uint4*)(g_pw_cw + ((size_t)tap*64 + c2b + c2l)*128 + q*4);
        }
        __syncthreads();
#pragma unroll
        for (int tap = 0; tap < 9; tap++) {
            int ky = tap / 3, kx = tap % 3;
#pragma unroll
            for (int ks = 0; ks < 2; ks++) {
                int k2b = ks*8;
                unsigned A[4][4];
#pragma unroll
                for (int mt=0; mt<4; mt++) {
                    int pixL = (wm*4 + mt + ky)*18 + tg + kx;
                    A[mt][0]=sh_in[(k2b+tq)*CIS + pixL];
                    A[mt][1]=sh_in[(k2b+tq)*CIS + pixL + 8];
                    A[mt][2]=sh_in[(k2b+tq+4)*CIS + pixL];
                    A[mt][3]=sh_in[(k2b+tq+4)*CIS + pixL + 8];
                }
#pragma unroll
                for (int nt=0; nt<4; nt++) {
                    unsigned B[2];
                    B[0]=sh_w[(tap*16 + k2b+tq)*136 + wn*32 + nt*8+tg];
                    B[1]=sh_w[(tap*16 + k2b+tq+4)*136 + wn*32 + nt*8+tg];
#pragma unroll
                    for (int mt=0; mt<4; mt++) mma_bf16(acc[mt][nt], A[mt], B);
                }
            }
        }
    }
    // gelu -> bf16 tile in (now-free) sh_w region
    __syncthreads();
    unsigned* sh_t = sh_w;  // [pix 128][k2 64] stride 68
#pragma unroll
    for (int mt=0; mt<4; mt++) {
        int pix0 = (wm*4 + mt)*16 + tg;
#pragma unroll
        for (int nt=0; nt<4; nt++) {
            int col = wn*32 + nt*8 + 2*tq;
            int k2 = col >> 1;
            float b0 = cb[col], b1 = cb[col+1];
            sh_t[pix0*68 + k2]     = pk(gelu_exact(acc[mt][nt][0]+b0), gelu_exact(acc[mt][nt][1]+b1));
            sh_t[(pix0+8)*68 + k2] = pk(gelu_exact(acc[mt][nt][2]+b0), gelu_exact(acc[mt][nt][3]+b1));
        }
    }
    __syncthreads();
    // lp2: 128 x 32, K=128
    float acc3[4][4];
#pragma unroll
    for (int nt=0; nt<4; nt++)
#pragma unroll
        for (int r=0; r<4; r++) acc3[nt][r] = 0.f;
    int rr = warp*16 + tg;
#pragma unroll
    for (int ks = 0; ks < 8; ks++) {
        int k2b = ks*8;
        unsigned A[4];
        A[0]=sh_t[rr*68 + k2b+tq];
        A[1]=sh_t[(rr+8)*68 + k2b+tq];
        A[2]=sh_t[rr*68 + k2b+tq+4];
        A[3]=sh_t[(rr+8)*68 + k2b+tq+4];
#pragma unroll
        for (int nt=0; nt<4; nt++) {
            unsigned B[2];
            B[0]=sh_w2[(k2b+tq)*40 + nt*8+tg];
            B[1]=sh_w2[(k2b+tq+4)*40 + nt*8+tg];
            mma_bf16(acc3[nt], A, B);
        }
    }
    long t0 = (long)b*16384 + (long)(y0 + warp)*128 + x0 + tg;
    long t1 = t0 + 8;
#pragma unroll
    for (int nt=0; nt<4; nt++) {
        int col = nt*8 + 2*tq;
        float b0 = b2[col], b1 = b2[col+1];
        float2 x0v = *(const float2*)(g_xres + t0*32 + col);
        float2 x1v = *(const float2*)(g_xres + t1*32 + col);
        *(float2*)(out + t0*32 + col) =
            make_float2(gelu_exact(acc3[nt][0]+b0)+x0v.x, gelu_exact(acc3[nt][1]+b1)+x0v.y);
        *(float2*)(out + t1*32 + col) =
            make_float2(gelu_exact(acc3[nt][2]+b0)+x1v.x, gelu_exact(acc3[nt][3]+b1)+x1v.y);
    }
}

extern "C" void kernel_launch(void* const* d_in, const int* in_sizes, int n_in,
                              void* d_out, int out_size) {
    const float* x    = (const float*)d_in[0];
    const float* n1g  = (const float*)d_in[1];
    const float* n1b  = (const float*)d_in[2];
    const float* modw = (const float*)d_in[3];
    const float* qkvw = (const float*)d_in[4];
    const float* qkvb = (const float*)d_in[5];
    const float* rpbt = (const float*)d_in[6];
    const float* revw = (const float*)d_in[7];
    const float* revb = (const float*)d_in[8];
    const float* n2g  = (const float*)d_in[9];
    const float* n2b  = (const float*)d_in[10];
    const float* lp1w = (const float*)d_in[11];
    const float* lp1b = (const float*)d_in[12];
    const float* convw= (const float*)d_in[13];
    const float* convb= (const float*)d_in[14];
    const float* lp2w = (const float*)d_in[15];
    const float* lp2b = (const float*)d_in[16];
    float* out = (float*)d_out;

    cudaFuncSetAttribute(k_attn, cudaFuncAttributeMaxDynamicSharedMemorySize, ATTN_SMEM);
    cudaFuncSetAttribute(k_rev_lp1, cudaFuncAttributeMaxDynamicSharedMemorySize, RL_SMEM);
    cudaFuncSetAttribute(k_conv, cudaFuncAttributeMaxDynamicSharedMemorySize, CONV_SMEM);

    k_pack<<<288, 256>>>(qkvw, revw, lp1w, lp2w, convw, rpbt);
    k_ln1 <<<NWIN, 256>>>(x, n1g, n1b, modw);
    k_attn<<<NWIN * HH, 256, ATTN_SMEM>>>(qkvb);
    k_rev_lp1<<<NTOKENS / 128, 256, RL_SMEM>>>(x, revb, n2g, n2b, lp1b);
    k_conv<<<BQ * 16 * 8, 256, CONV_SMEM>>>(convb, lp2b, out);
}

// round 7
// speedup vs baseline: 6.2029x; 1.0452x over previous
#include <cuda_runtime.h>
#include <cuda_bf16.h>
#include <math.h>

#define BQ 8
#define NTOK 256
#define HH 8
#define CC 32
#define INNER 128
#define NWIN 512
#define NTOKENS (BQ*128*128)

// packed bf16x2 intermediates
__device__ unsigned g_hwin[(size_t)NWIN*NTOK*16];
__device__ unsigned g_oheads[(size_t)NTOKENS*128];   // row-contiguous in global token t
__device__ float    g_xres[(size_t)NTOKENS*CC];
__device__ unsigned g_y1[(size_t)NTOKENS*64];
// packed weights (zero-init pads)
__device__ unsigned g_pw_qkv[8*16*104];
__device__ unsigned g_pw_rev[128*40];
__device__ unsigned g_pw_w1[16*136];
__device__ unsigned g_pw_w2[64*40];
__device__ unsigned g_pw_cw[9*64*128];
__device__ float    g_rpbp[8*964];

__device__ __forceinline__ float gelu_exact(float x) {
    return 0.5f * x * (1.0f + erff(x * 0.70710678118654752440f));
}
__device__ __forceinline__ unsigned pk(float a, float b) {
    __nv_bfloat162 t = __floats2bfloat162_rn(a, b);
    return *reinterpret_cast<unsigned*>(&t);
}
__device__ __forceinline__ void mma_bf16(float* c, const unsigned* a, const unsigned* b) {
    asm volatile("mma.sync.aligned.m16n8k16.row.col.f32.bf16.bf16.f32 "
        "{%0,%1,%2,%3},{%4,%5,%6,%7},{%8,%9},{%0,%1,%2,%3};"
        : "+f"(c[0]), "+f"(c[1]), "+f"(c[2]), "+f"(c[3])
        : "r"(a[0]), "r"(a[1]), "r"(a[2]), "r"(a[3]), "r"(b[0]), "r"(b[1]));
}

// ============ K0: one-time weight packing ================================
__global__ void k_pack(const float* __restrict__ qkvw, const float* __restrict__ revw,
                       const float* __restrict__ w1, const float* __restrict__ w2,
                       const float* __restrict__ cw, const float* __restrict__ rpbt) {
    int i = blockIdx.x * 256 + threadIdx.x;
    if (i < 73728) {
        int tap = i >> 13, r = i & 8191;
        int c2 = r >> 7, co = r & 127;
        g_pw_cw[i] = pk(cw[((size_t)tap*128 + 2*c2)*128 + co],
                        cw[((size_t)tap*128 + 2*c2 + 1)*128 + co]);
    }
    if (i < 12288) {
        int hh = i / 1536, r = i % 1536;
        int c2 = r / 96, col = r % 96;
        int gcol = (col >> 5)*256 + hh*32 + (col & 31);
        g_pw_qkv[(hh*16 + c2)*104 + col] = pk(qkvw[2*c2*768 + gcol], qkvw[(2*c2+1)*768 + gcol]);
    }
    if (i < 7688) {
        int hh = i / 961, j = i % 961;
        g_rpbp[hh*964 + j] = rpbt[j*8 + hh];
    }
    if (i < 4096) {
        int k2 = i >> 5, n = i & 31;
        g_pw_rev[k2*40 + n] = pk(revw[2*k2*32 + n], revw[(2*k2+1)*32 + n]);
    }
    if (i < 2048) {
        int c2 = i >> 7, n = i & 127;
        g_pw_w1[c2*136 + n] = pk(w1[2*c2*128 + n], w1[(2*c2+1)*128 + n]);
    }
    if (i < 2048) {
        int k2 = i >> 5, n = i & 31;
        g_pw_w2[k2*40 + n] = pk(w2[2*k2*32 + n], w2[(2*k2+1)*32 + n]);
    }
}

// ============ K1: LN1 + shift + window partition + modulator =============
__global__ void k_ln1(const float* __restrict__ x, const float* __restrict__ g1,
                      const float* __restrict__ b1, const float* __restrict__ modw) {
    int w = blockIdx.x, n = threadIdx.x;
    int b = w >> 6, ww = w & 63;
    int ry = (ww >> 3)*16 + (n >> 4), rx = (ww & 7)*16 + (n & 15);
    int y = (ry + 8) & 127, xx = (rx + 8) & 127;
    const float* xp = x + ((size_t)b*16384 + (size_t)y*128 + xx)*CC;
    float v[CC];
#pragma unroll
    for (int i = 0; i < 8; i++) {
        float4 t = ((const float4*)xp)[i];
        v[4*i]=t.x; v[4*i+1]=t.y; v[4*i+2]=t.z; v[4*i+3]=t.w;
    }
    float mean = 0.f;
#pragma unroll
    for (int c = 0; c < CC; c++) mean += v[c];
    mean *= (1.0f/CC);
    float var = 0.f;
#pragma unroll
    for (int c = 0; c < CC; c++) { float d = v[c]-mean; var += d*d; }
    float rstd = rsqrtf(var*(1.0f/CC) + 1e-5f);
    unsigned* op = g_hwin + ((size_t)w*NTOK + n)*16;
#pragma unroll
    for (int i = 0; i < 16; i++) {
        int c = 2*i;
        op[i] = pk((v[c]-mean)*rstd*g1[c]+b1[c]+modw[n*CC+c],
                   (v[c+1]-mean)*rstd*g1[c+1]+b1[c+1]+modw[n*CC+c+1]);
    }
}

// ============ K2: QKV mma + flash window attention (frag passthrough) ===
#define ATTN_SMEM (12324*4)
__global__ void __launch_bounds__(256,3) k_attn(const float* __restrict__ qkvb) {
    extern __shared__ unsigned smu[];
    unsigned* sh_kT = smu;              // 16*264 [a2][key]
    unsigned* sh_v  = smu + 4224;       // 128*40 [key2][dim]
    unsigned* sh_w  = sh_v + 5120;      // 16*104
    float* sh_b   = (float*)(sh_w + 1664);  // 96
    float* sh_rpb = sh_b + 96;              // 964
    int*   sh_meta= (int*)(sh_rpb + 964);   // 256

    int w = blockIdx.x >> 3, hh = blockIdx.x & 7;
    int tid = threadIdx.x, lane = tid & 31, warp = tid >> 5;
    int tg = lane >> 2, tq = lane & 3;
    int qb = warp * 32;

    {
        const uint4* src = (const uint4*)(g_pw_qkv + hh*1664);
        uint4* dst = (uint4*)sh_w;
        for (int j = tid; j < 416; j += 256) dst[j] = src[j];
    }
    if (tid < 96) sh_b[tid] = qkvb[(tid>>5)*256 + hh*32 + (tid&31)];
    for (int j = tid; j < 961; j += 256) sh_rpb[j] = g_rpbp[hh*964 + j];
    {
        int n = tid, ww = w & 63;
        int ry = (ww>>3)*16 + (n>>4), rx = (ww&7)*16 + (n&15);
        int hr = ry < 112 ? 0 : (ry < 120 ? 1 : 2);
        int wr = rx < 112 ? 0 : (rx < 120 ? 1 : 2);
        sh_meta[n] = ((n>>4)*31 + (n&15)) | ((hr*3+wr) << 16);
    }
    // h A-fragments straight from global
    unsigned ha[2][8];
#pragma unroll
    for (int mt = 0; mt < 2; mt++) {
        const unsigned* h0 = g_hwin + ((size_t)w*256 + qb + mt*16 + tg)*16;
        const unsigned* h1 = h0 + 8*16;
        ha[mt][0]=h0[tq];    ha[mt][1]=h1[tq];
        ha[mt][2]=h0[tq+4];  ha[mt][3]=h1[tq+4];
        ha[mt][4]=h0[tq+8];  ha[mt][5]=h1[tq+8];
        ha[mt][6]=h0[tq+12]; ha[mt][7]=h1[tq+12];
    }
    __syncthreads();

    // ---- QKV projection; Q stays in fragments ----
    unsigned qrl[2][4], qrh[2][4];
    __nv_bfloat16* vb = (__nv_bfloat16*)sh_v;
#pragma unroll
    for (int sec = 0; sec < 3; sec++) {
        float acc[2][4][4];
#pragma unroll
        for (int mt=0; mt<2; mt++)
#pragma unroll
            for (int nt=0; nt<4; nt++)
#pragma unroll
                for (int r=0; r<4; r++) acc[mt][nt][r] = 0.f;
#pragma unroll
        for (int ks = 0; ks < 2; ks++) {
#pragma unroll
            for (int nt=0; nt<4; nt++) {
                unsigned B[2];
                B[0]=sh_w[(8*ks+tq)*104 + sec*32 + nt*8+tg];
                B[1]=sh_w[(8*ks+tq+4)*104 + sec*32 + nt*8+tg];
                mma_bf16(acc[0][nt], &ha[0][ks*4], B);
                mma_bf16(acc[1][nt], &ha[1][ks*4], B);
            }
        }
#pragma unroll
        for (int mt=0; mt<2; mt++)
#pragma unroll
        for (int nt=0; nt<4; nt++) {
            int col = nt*8 + 2*tq;
            int r0 = qb + mt*16 + tg;
            float bb0 = sh_b[sec*32+col], bb1 = sh_b[sec*32+col+1];
            float v0=acc[mt][nt][0]+bb0, v1=acc[mt][nt][1]+bb1;
            float v2=acc[mt][nt][2]+bb0, v3=acc[mt][nt][3]+bb1;
            if (sec == 0) {
                const float SC = 0.17677669529663688f;
                qrl[mt][nt] = pk(v0*SC, v1*SC);
                qrh[mt][nt] = pk(v2*SC, v3*SC);
            } else if (sec == 1) {
                sh_kT[(col>>1)*264 + r0]   = pk(v0, v1);
                sh_kT[(col>>1)*264 + r0+8] = pk(v2, v3);
            } else {
                int r1 = r0 + 8, par = r0 & 1;
                vb[(r0>>1)*80 + col*2     + par] = __float2bfloat16(v0);
                vb[(r0>>1)*80 + (col+1)*2 + par] = __float2bfloat16(v1);
                vb[(r1>>1)*80 + col*2     + par] = __float2bfloat16(v2);
                vb[(r1>>1)*80 + (col+1)*2 + par] = __float2bfloat16(v3);
            }
        }
    }
    __syncthreads();

    // ---- flash attention (bounded scores; P in fragments) ----
    int rb[2][2], rid[2][2];
#pragma unroll
    for (int mt=0; mt<2; mt++)
#pragma unroll
        for (int h=0; h<2; h++) {
            int q = qb + mt*16 + tg + 8*h;
            rb[mt][h] = ((q>>4)+15)*31 + ((q&15)+15);
            rid[mt][h] = sh_meta[q] >> 16;
        }
    float psL[2] = {0.f,0.f}, psH[2] = {0.f,0.f};
    float o[2][4][4];
#pragma unroll
    for (int mt=0; mt<2; mt++)
#pragma unroll
        for (int nt=0; nt<4; nt++)
#pragma unroll
            for (int r=0; r<4; r++) o[mt][nt][r] = 0.f;

    for (int kc = 0; kc < 8; kc++) {
        int kb = kc * 32;
        float s[2][4][4];
#pragma unroll
        for (int mt=0; mt<2; mt++)
#pragma unroll
            for (int nt=0; nt<4; nt++)
#pragma unroll
                for (int r=0; r<4; r++) s[mt][nt][r] = 0.f;
#pragma unroll
        for (int ks = 0; ks < 2; ks++) {
            unsigned A0[4] = {qrl[0][2*ks], qrh[0][2*ks], qrl[0][2*ks+1], qrh[0][2*ks+1]};
            unsigned A1[4] = {qrl[1][2*ks], qrh[1][2*ks], qrl[1][2*ks+1], qrh[1][2*ks+1]};
#pragma unroll
            for (int nt=0; nt<4; nt++) {
                unsigned B[2];
                int key = kb + nt*8 + tg;
                B[0]=sh_kT[(8*ks+tq)*264 + key];
                B[1]=sh_kT[(8*ks+tq+4)*264 + key];
                mma_bf16(s[0][nt], A0, B);
                mma_bf16(s[1][nt], A1, B);
            }
        }
        unsigned pl[2][4], ph[2][4];
#pragma unroll
        for (int nt=0; nt<4; nt++) {
            int k0i = kb + nt*8 + 2*tq;
            int me0 = sh_meta[k0i], me1 = sh_meta[k0i+1];
            int kf0 = me0 & 0xffff, kr0 = me0 >> 16;
            int kf1 = me1 & 0xffff, kr1 = me1 >> 16;
#pragma unroll
            for (int mt=0; mt<2; mt++) {
                float p0 = __expf(s[mt][nt][0] + sh_rpb[rb[mt][0]-kf0] + (kr0 != rid[mt][0] ? -100.f : 0.f));
                float p1 = __expf(s[mt][nt][1] + sh_rpb[rb[mt][0]-kf1] + (kr1 != rid[mt][0] ? -100.f : 0.f));
                float p2 = __expf(s[mt][nt][2] + sh_rpb[rb[mt][1]-kf0] + (kr0 != rid[mt][1] ? -100.f : 0.f));
                float p3 = __expf(s[mt][nt][3] + sh_rpb[rb[mt][1]-kf1] + (kr1 != rid[mt][1] ? -100.f : 0.f));
                psL[mt] += p0 + p1;
                psH[mt] += p2 + p3;
                pl[mt][nt] = pk(p0, p1);
                ph[mt][nt] = pk(p2, p3);
            }
        }
#pragma unroll
        for (int ks = 0; ks < 2; ks++) {
            unsigned A0[4] = {pl[0][2*ks], ph[0][2*ks], pl[0][2*ks+1], ph[0][2*ks+1]};
            unsigned A1[4] = {pl[1][2*ks], ph[1][2*ks], pl[1][2*ks+1], ph[1][2*ks+1]};
#pragma unroll
            for (int nt=0; nt<4; nt++) {
                unsigned B[2];
                int vr = kc*16 + ks*8 + tq;
                B[0]=sh_v[vr*40 + nt*8+tg];
                B[1]=sh_v[(vr+4)*40 + nt*8+tg];
                mma_bf16(o[0][nt], A0, B);
                mma_bf16(o[1][nt], A1, B);
            }
        }
    }
    // write at un-shifted global token index (absorbs window reverse + roll)
    {
        int b = w >> 6, ww = w & 63;
        int wy = (ww >> 3)*16, wx = (ww & 7)*16;
#pragma unroll
        for (int mt=0; mt<2; mt++) {
            float sL = psL[mt], sH = psH[mt];
            sL += __shfl_xor_sync(0xffffffffu, sL, 1); sL += __shfl_xor_sync(0xffffffffu, sL, 2);
            sH += __shfl_xor_sync(0xffffffffu, sH, 1); sH += __shfl_xor_sync(0xffffffffu, sH, 2);
            float i0 = 1.f/sL, i1 = 1.f/sH;
            int q = qb + mt*16 + tg;
            int y  = (wy + (q >> 4) + 8) & 127;
            int x0 = (wx + tg + 8) & 127;
            int x1 = (wx + tg + 16) & 127;
            unsigned* d0 = g_oheads + ((size_t)b*16384 + (size_t)y*128 + x0)*128 + hh*16;
            unsigned* d1 = g_oheads + ((size_t)b*16384 + (size_t)y*128 + x1)*128 + hh*16;
#pragma unroll
            for (int nt=0; nt<4; nt++) {
                int k2 = nt*4 + tq;
                d0[k2] = pk(o[mt][nt][0]*i0, o[mt][nt][1]*i0);
                d1[k2] = pk(o[mt][nt][2]*i1, o[mt][nt][3]*i1);
            }
        }
    }
}

// ============ K3: rev mma + residual + LN2 + lp1 mma + GELU (fused) =====
#define RL_SMEM ((9856 + 288)*4)
__global__ void __launch_bounds__(256,3) k_rev_lp1(const float* __restrict__ x,
        const float* __restrict__ revb, const float* __restrict__ n2g,
        const float* __restrict__ n2b, const float* __restrict__ bb1) {
    extern __shared__ unsigned smu[];
    unsigned* sh_wr = smu;           // 128*40 = 5120
    unsigned* sh_w1 = smu + 5120;    // 16*136 = 2176
    unsigned* sh_a  = smu + 7296;    // 128*20 = 2560
    float* sh_f = (float*)(smu + 9856);
    int tid = threadIdx.x, lane = tid & 31, warp = tid >> 5;
    int tg = lane >> 2, tq = lane & 3;
    long base = (long)blockIdx.x * 128;

    for (int j = tid; j < 1280; j += 256) ((uint4*)sh_wr)[j] = ((const uint4*)g_pw_rev)[j];
    for (int j = tid; j < 544; j += 256)  ((uint4*)sh_w1)[j] = ((const uint4*)g_pw_w1)[j];
    if (tid < 32) { sh_f[tid] = revb[tid]; sh_f[32+tid] = n2g[tid]; sh_f[64+tid] = n2b[tid]; }
    if (tid < 128) sh_f[96+tid] = bb1[tid];

    int rr = warp*16 + tg;
    long t0 = base + rr;
    const unsigned* ar0 = g_oheads + t0*128;
    const unsigned* ar1 = ar0 + 8*128;
    __syncthreads();

    // rev projection 128x32, K=256 — A frags straight from global
    float acc[4][4];
#pragma unroll
    for (int nt=0; nt<4; nt++)
#pragma unroll
        for (int r=0; r<4; r++) acc[nt][r] = 0.f;
#pragma unroll 4
    for (int ks = 0; ks < 16; ks++) {
        int k2b = ks*8;
        unsigned A[4];
        A[0]=__ldg(ar0 + k2b+tq);
        A[1]=__ldg(ar1 + k2b+tq);
        A[2]=__ldg(ar0 + k2b+tq+4);
        A[3]=__ldg(ar1 + k2b+tq+4);
#pragma unroll
        for (int nt=0; nt<4; nt++) {
            unsigned B[2];
            B[0]=sh_wr[(k2b+tq)*40 + nt*8+tg];
            B[1]=sh_wr[(k2b+tq+4)*40 + nt*8+tg];
            mma_bf16(acc[nt], A, B);
        }
    }
    float v0[4], v1[4], v2[4], v3[4];
#pragma unroll
    for (int nt=0; nt<4; nt++) {
        int col = nt*8 + 2*tq;
        float b0 = sh_f[col], b1 = sh_f[col+1];
        float2 x0 = *(const float2*)(x + t0*32 + col);
        float2 x1 = *(const float2*)(x + (t0+8)*32 + col);
        v0[nt]=acc[nt][0]+b0+x0.x; v1[nt]=acc[nt][1]+b1+x0.y;
        v2[nt]=acc[nt][2]+b0+x1.x; v3[nt]=acc[nt][3]+b1+x1.y;
        *(float2*)(g_xres + t0*32 + col)     = make_float2(v0[nt], v1[nt]);
        *(float2*)(g_xres + (t0+8)*32 + col) = make_float2(v2[nt], v3[nt]);
    }
    float sL=0.f, qL=0.f, sH=0.f, qH=0.f;
#pragma unroll
    for (int nt=0; nt<4; nt++) {
        sL += v0[nt]+v1[nt]; qL += v0[nt]*v0[nt]+v1[nt]*v1[nt];
        sH += v2[nt]+v3[nt]; qH += v2[nt]*v2[nt]+v3[nt]*v3[nt];
    }
    sL += __shfl_xor_sync(0xffffffffu, sL, 1); sL += __shfl_xor_sync(0xffffffffu, sL, 2);
    qL += __shfl_xor_sync(0xffffffffu, qL, 1); qL += __shfl_xor_sync(0xffffffffu, qL, 2);
    sH += __shfl_xor_sync(0xffffffffu, sH, 1); sH += __shfl_xor_sync(0xffffffffu, sH, 2);
    qH += __shfl_xor_sync(0xffffffffu, qH, 1); qH += __shfl_xor_sync(0xffffffffu, qH, 2);
    float mL = sL*(1.f/32.f), mH = sH*(1.f/32.f);
    float rL = rsqrtf(qL*(1.f/32.f) - mL*mL + 1e-5f);
    float rH = rsqrtf(qH*(1.f/32.f) - mH*mH + 1e-5f);
#pragma unroll
    for (int nt=0; nt<4; nt++) {
        int col = nt*8 + 2*tq;
        float g0 = sh_f[32+col], g1 = sh_f[33+col], bt0 = sh_f[64+col], bt1 = sh_f[65+col];
        sh_a[rr*20 + nt*4+tq]     = pk((v0[nt]-mL)*rL*g0+bt0, (v1[nt]-mL)*rL*g1+bt1);
        sh_a[(rr+8)*20 + nt*4+tq] = pk((v2[nt]-mH)*rH*g0+bt0, (v3[nt]-mH)*rH*g1+bt1);
    }
    __syncwarp();  // sh_a rows are warp-private

    // lp1: 128x128, K=32 — two 64-col passes (register diet)
#pragma unroll
    for (int h2 = 0; h2 < 2; h2++) {
        float acc2[8][4];
#pragma unroll
        for (int nt=0; nt<8; nt++)
#pragma unroll
            for (int r=0; r<4; r++) acc2[nt][r] = 0.f;
#pragma unroll
        for (int ks = 0; ks < 2; ks++) {
            int k2b = ks*8;
            unsigned A[4];
            A[0]=sh_a[rr*20 + k2b+tq];
            A[1]=sh_a[(rr+8)*20 + k2b+tq];
            A[2]=sh_a[rr*20 + k2b+tq+4];
            A[3]=sh_a[(rr+8)*20 + k2b+tq+4];
#pragma unroll
            for (int nt=0; nt<8; nt++) {
                unsigned B[2];
                B[0]=sh_w1[(k2b+tq)*136 + h2*64 + nt*8+tg];
                B[1]=sh_w1[(k2b+tq+4)*136 + h2*64 + nt*8+tg];
                mma_bf16(acc2[nt], A, B);
            }
        }
#pragma unroll
        for (int nt=0; nt<8; nt++) {
            int col = h2*64 + nt*8 + 2*tq;
            float b0 = sh_f[96+col], b1 = sh_f[97+col];
            g_y1[t0*64 + (col>>1)]     = pk(gelu_exact(acc2[nt][0]+b0), gelu_exact(acc2[nt][1]+b1));
            g_y1[(t0+8)*64 + (col>>1)] = pk(gelu_exact(acc2[nt][2]+b0), gelu_exact(acc2[nt][3]+b1));
        }
    }
}

// ============ K5: 3x3 conv implicit GEMM + fused lp2 + residual =========
#define CIS 184
#define CONV_SMEM (25088*4)
__global__ void __launch_bounds__(256,2) k_conv(const float* __restrict__ cb,
                                                const float* __restrict__ b2,
                                                float* __restrict__ out) {
    extern __shared__ unsigned smu[];
    unsigned* sh_in = smu;               // [c2 16][pix 180] stride 184
    unsigned* sh_w  = smu + 16*CIS;      // [tap*16+c2][co 128] stride 136 (reused as sh_t)
    unsigned* sh_w2 = sh_w + 144*136;    // 64*40
    int bz = blockIdx.x;
    int b = bz >> 7;
    int y0 = ((bz >> 3) & 15) * 8;
    int x0 = (bz & 7) * 16;
    int tid = threadIdx.x, lane = tid & 31, warp = tid >> 5;
    int tg = lane >> 2, tq = lane & 3;
    int wm = warp & 1, wn = warp >> 1;

    for (int j = tid; j < 640; j += 256) ((uint4*)sh_w2)[j] = ((const uint4*)g_pw_w2)[j];

    float acc[4][4][4];
#pragma unroll
    for (int mt=0; mt<4; mt++)
#pragma unroll
        for (int nt=0; nt<4; nt++)
#pragma unroll
            for (int r=0; r<4; r++) acc[mt][nt][r] = 0.f;

    for (int ci0 = 0; ci0 < 128; ci0 += 32) {
        int c2b = ci0 >> 1;
        __syncthreads();
        for (int j = tid; j < 720; j += 256) {
            int pix = j >> 2, q = j & 3;
            int py = pix / 18, px = pix - py*18;
            int gy = y0 - 1 + py, gx = x0 - 1 + px;
            uint4 v = make_uint4(0,0,0,0);
            if ((unsigned)gy < 128u && (unsigned)gx < 128u)
                v = *(const uint4*)(g_y1 + ((size_t)(b*16384 + gy*128 + gx))*64 + c2b + q*4);
            sh_in[(q*4+0)*CIS + pix] = v.x;
            sh_in[(q*4+1)*CIS + pix] = v.y;
            sh_in[(q*4+2)*CIS + pix] = v.z;
            sh_in[(q*4+3)*CIS + pix] = v.w;
        }
        for (int j = tid; j < 4608; j += 256) {
            int row = j >> 5, q = j & 31;
            int tap = row >> 4, c2l = row & 15;
            *(uint4*)(sh_w + row*136 + q*4) =
                *(const uint4*)(g_pw_cw + ((size_t)tap*64 + c2b + c2l)*128 + q*4);
        }
        __syncthreads();
#pragma unroll
        for (int tap = 0; tap < 9; tap++) {
            int ky = tap / 3, kx = tap % 3;
#pragma unroll
            for (int ks = 0; ks < 2; ks++) {
                int k2b = ks*8;
                unsigned A[4][4];
#pragma unroll
                for (int mt=0; mt<4; mt++) {
                    int pixL = (wm*4 + mt + ky)*18 + tg + kx;
                    A[mt][0]=sh_in[(k2b+tq)*CIS + pixL];
                    A[mt][1]=sh_in[(k2b+tq)*CIS + pixL + 8];
                    A[mt][2]=sh_in[(k2b+tq+4)*CIS + pixL];
                    A[mt][3]=sh_in[(k2b+tq+4)*CIS + pixL + 8];
                }
#pragma unroll
                for (int nt=0; nt<4; nt++) {
                    unsigned B[2];
                    B[0]=sh_w[(tap*16 + k2b+tq)*136 + wn*32 + nt*8+tg];
                    B[1]=sh_w[(tap*16 + k2b+tq+4)*136 + wn*32 + nt*8+tg];
#pragma unroll
                    for (int mt=0; mt<4; mt++) mma_bf16(acc[mt][nt], A[mt], B);
                }
            }
        }
    }
    __syncthreads();
    unsigned* sh_t = sh_w;  // [pix 128][k2 64] stride 68
#pragma unroll
    for (int mt=0; mt<4; mt++) {
        int pix0 = (wm*4 + mt)*16 + tg;
#pragma unroll
        for (int nt=0; nt<4; nt++) {
            int col = wn*32 + nt*8 + 2*tq;
            int k2 = col >> 1;
            float b0 = cb[col], b1 = cb[col+1];
            sh_t[pix0*68 + k2]     = pk(gelu_exact(acc[mt][nt][0]+b0), gelu_exact(acc[mt][nt][1]+b1));
            sh_t[(pix0+8)*68 + k2] = pk(gelu_exact(acc[mt][nt][2]+b0), gelu_exact(acc[mt][nt][3]+b1));
        }
    }
    __syncthreads();
    float acc3[4][4];
#pragma unroll
    for (int nt=0; nt<4; nt++)
#pragma unroll
        for (int r=0; r<4; r++) acc3[nt][r] = 0.f;
    int rr = warp*16 + tg;
#pragma unroll
    for (int ks = 0; ks < 8; ks++) {
        int k2b = ks*8;
        unsigned A[4];
        A[0]=sh_t[rr*68 + k2b+tq];
        A[1]=sh_t[(rr+8)*68 + k2b+tq];
        A[2]=sh_t[rr*68 + k2b+tq+4];
        A[3]=sh_t[(rr+8)*68 + k2b+tq+4];
#pragma unroll
        for (int nt=0; nt<4; nt++) {
            unsigned B[2];
            B[0]=sh_w2[(k2b+tq)*40 + nt*8+tg];
            B[1]=sh_w2[(k2b+tq+4)*40 + nt*8+tg];
            mma_bf16(acc3[nt], A, B);
        }
    }
    long t0 = (long)b*16384 + (long)(y0 + warp)*128 + x0 + tg;
    long t1 = t0 + 8;
#pragma unroll
    for (int nt=0; nt<4; nt++) {
        int col = nt*8 + 2*tq;
        float b0 = b2[col], b1 = b2[col+1];
        float2 x0v = *(const float2*)(g_xres + t0*32 + col);
        float2 x1v = *(const float2*)(g_xres + t1*32 + col);
        *(float2*)(out + t0*32 + col) =
            make_float2(gelu_exact(acc3[nt][0]+b0)+x0v.x, gelu_exact(acc3[nt][1]+b1)+x0v.y);
        *(float2*)(out + t1*32 + col) =
            make_float2(gelu_exact(acc3[nt][2]+b0)+x1v.x, gelu_exact(acc3[nt][3]+b1)+x1v.y);
    }
}

extern "C" void kernel_launch(void* const* d_in, const int* in_sizes, int n_in,
                              void* d_out, int out_size) {
    const float* x    = (const float*)d_in[0];
    const float* n1g  = (const float*)d_in[1];
    const float* n1b  = (const float*)d_in[2];
    const float* modw = (const float*)d_in[3];
    const float* qkvw = (const float*)d_in[4];
    const float* qkvb = (const float*)d_in[5];
    const float* rpbt = (const float*)d_in[6];
    const float* revw = (const float*)d_in[7];
    const float* revb = (const float*)d_in[8];
    const float* n2g  = (const float*)d_in[9];
    const float* n2b  = (const float*)d_in[10];
    const float* lp1w = (const float*)d_in[11];
    const float* lp1b = (const float*)d_in[12];
    const float* convw= (const float*)d_in[13];
    const float* convb= (const float*)d_in[14];
    const float* lp2w = (const float*)d_in[15];
    const float* lp2b = (const float*)d_in[16];
    float* out = (float*)d_out;

    cudaFuncSetAttribute(k_attn, cudaFuncAttributeMaxDynamicSharedMemorySize, ATTN_SMEM);
    cudaFuncSetAttribute(k_rev_lp1, cudaFuncAttributeMaxDynamicSharedMemorySize, RL_SMEM);
    cudaFuncSetAttribute(k_conv, cudaFuncAttributeMaxDynamicSharedMemorySize, CONV_SMEM);

    k_pack<<<288, 256>>>(qkvw, revw, lp1w, lp2w, convw, rpbt);
    k_ln1 <<<NWIN, 256>>>(x, n1g, n1b, modw);
    k_attn<<<NWIN * HH, 256, ATTN_SMEM>>>(qkvb);
    k_rev_lp1<<<NTOKENS / 128, 256, RL_SMEM>>>(x, revb, n2g, n2b, lp1b);
    k_conv<<<BQ * 16 * 8, 256, CONV_SMEM>>>(convb, lp2b, out);
}

// round 8
// speedup vs baseline: 6.2857x; 1.0133x over previous
#include <cuda_runtime.h>
#include <cuda_bf16.h>
#include <math.h>

#define BQ 8
#define NTOK 256
#define HH 8
#define CC 32
#define INNER 128
#define NWIN 512
#define NTOKENS (BQ*128*128)

// packed bf16x2 intermediates
__device__ unsigned g_hwin[(size_t)NWIN*NTOK*16];
__device__ float    g_xres[(size_t)NTOKENS*CC];
__device__ unsigned g_y1[(size_t)NTOKENS*64];
// packed weights (zero-init pads)
__device__ unsigned g_pw_qkv[8*16*104];
__device__ unsigned g_pw_rev[128*40];
__device__ unsigned g_pw_w1[16*136];
__device__ unsigned g_pw_w2[64*40];
__device__ unsigned g_pw_cw[9*64*128];
__device__ float    g_rpbp[8*964];

__device__ __forceinline__ float gelu_exact(float x) {
    return 0.5f * x * (1.0f + erff(x * 0.70710678118654752440f));
}
__device__ __forceinline__ unsigned pk(float a, float b) {
    __nv_bfloat162 t = __floats2bfloat162_rn(a, b);
    return *reinterpret_cast<unsigned*>(&t);
}
__device__ __forceinline__ void mma_bf16(float* c, const unsigned* a, const unsigned* b) {
    asm volatile("mma.sync.aligned.m16n8k16.row.col.f32.bf16.bf16.f32 "
        "{%0,%1,%2,%3},{%4,%5,%6,%7},{%8,%9},{%0,%1,%2,%3};"
        : "+f"(c[0]), "+f"(c[1]), "+f"(c[2]), "+f"(c[3])
        : "r"(a[0]), "r"(a[1]), "r"(a[2]), "r"(a[3]), "r"(b[0]), "r"(b[1]));
}

// ============ K0: one-time weight packing ================================
__global__ void k_pack(const float* __restrict__ qkvw, const float* __restrict__ revw,
                       const float* __restrict__ w1, const float* __restrict__ w2,
                       const float* __restrict__ cw, const float* __restrict__ rpbt) {
    int i = blockIdx.x * 256 + threadIdx.x;
    if (i < 73728) {
        int tap = i >> 13, r = i & 8191;
        int c2 = r >> 7, co = r & 127;
        g_pw_cw[i] = pk(cw[((size_t)tap*128 + 2*c2)*128 + co],
                        cw[((size_t)tap*128 + 2*c2 + 1)*128 + co]);
    }
    if (i < 12288) {
        int hh = i / 1536, r = i % 1536;
        int c2 = r / 96, col = r % 96;
        int gcol = (col >> 5)*256 + hh*32 + (col & 31);
        g_pw_qkv[(hh*16 + c2)*104 + col] = pk(qkvw[2*c2*768 + gcol], qkvw[(2*c2+1)*768 + gcol]);
    }
    if (i < 7688) {
        int hh = i / 961, j = i % 961;
        g_rpbp[hh*964 + j] = rpbt[j*8 + hh];
    }
    if (i < 4096) {
        int k2 = i >> 5, n = i & 31;
        g_pw_rev[k2*40 + n] = pk(revw[2*k2*32 + n], revw[(2*k2+1)*32 + n]);
    }
    if (i < 2048) {
        int c2 = i >> 7, n = i & 127;
        g_pw_w1[c2*136 + n] = pk(w1[2*c2*128 + n], w1[(2*c2+1)*128 + n]);
    }
    if (i < 2048) {
        int k2 = i >> 5, n = i & 31;
        g_pw_w2[k2*40 + n] = pk(w2[2*k2*32 + n], w2[(2*k2+1)*32 + n]);
    }
}

// ============ K1: LN1 + shift + window partition + modulator =============
__global__ void k_ln1(const float* __restrict__ x, const float* __restrict__ g1,
                      const float* __restrict__ b1, const float* __restrict__ modw) {
    int w = blockIdx.x, n = threadIdx.x;
    int b = w >> 6, ww = w & 63;
    int ry = (ww >> 3)*16 + (n >> 4), rx = (ww & 7)*16 + (n & 15);
    int y = (ry + 8) & 127, xx = (rx + 8) & 127;
    const float* xp = x + ((size_t)b*16384 + (size_t)y*128 + xx)*CC;
    float v[CC];
#pragma unroll
    for (int i = 0; i < 8; i++) {
        float4 t = ((const float4*)xp)[i];
        v[4*i]=t.x; v[4*i+1]=t.y; v[4*i+2]=t.z; v[4*i+3]=t.w;
    }
    float mean = 0.f;
#pragma unroll
    for (int c = 0; c < CC; c++) mean += v[c];
    mean *= (1.0f/CC);
    float var = 0.f;
#pragma unroll
    for (int c = 0; c < CC; c++) { float d = v[c]-mean; var += d*d; }
    float rstd = rsqrtf(var*(1.0f/CC) + 1e-5f);
    unsigned* op = g_hwin + ((size_t)w*NTOK + n)*16;
#pragma unroll
    for (int i = 0; i < 16; i++) {
        int c = 2*i;
        op[i] = pk((v[c]-mean)*rstd*g1[c]+b1[c]+modw[n*CC+c],
                   (v[c+1]-mean)*rstd*g1[c+1]+b1[c+1]+modw[n*CC+c+1]);
    }
}

// ============ K2: window megakernel: QKV + attn(8 heads) + rev + LN2 + lp1
#define ATTN_SMEM (20516*4)
__global__ void __launch_bounds__(256,2) k_attn(const float* __restrict__ x,
        const float* __restrict__ qkvb, const float* __restrict__ revb,
        const float* __restrict__ n2g, const float* __restrict__ n2b,
        const float* __restrict__ bb1) {
    extern __shared__ unsigned smu[];
    unsigned* sh_kT  = smu;                 // 4224 (reused as sh_a: 5120)
    unsigned* sh_v   = smu + 4224;          // 5120
    unsigned* sh_wq  = smu + 9344;          // 1664 (per head)
    unsigned* sh_rev = smu + 11008;         // 5120
    unsigned* sh_w1  = smu + 16128;         // 2176
    float* sh_rpb    = (float*)(smu + 18304);  // 964 (per head)
    int*   sh_meta   = (int*)(smu + 19268);    // 256
    float* sh_ball   = (float*)(smu + 19524);  // 768
    float* sh_f      = (float*)(smu + 20292);  // 224

    int w = blockIdx.x;
    int tid = threadIdx.x, lane = tid & 31, warp = tid >> 5;
    int tg = lane >> 2, tq = lane & 3;
    int qb = warp * 32;

    // ---- one-time staging ----
    for (int j = tid; j < 1280; j += 256) ((uint4*)sh_rev)[j] = ((const uint4*)g_pw_rev)[j];
    for (int j = tid; j < 544; j += 256)  ((uint4*)sh_w1)[j]  = ((const uint4*)g_pw_w1)[j];
    for (int j = tid; j < 768; j += 256)  sh_ball[j] = qkvb[j];
    if (tid < 32) { sh_f[tid] = revb[tid]; sh_f[32+tid] = n2g[tid]; sh_f[64+tid] = n2b[tid]; }
    if (tid < 128) sh_f[96+tid] = bb1[tid];
    {
        int n = tid, ww = w & 63;
        int ry = (ww>>3)*16 + (n>>4), rx = (ww&7)*16 + (n&15);
        int hr = ry < 112 ? 0 : (ry < 120 ? 1 : 2);
        int wr = rx < 112 ? 0 : (rx < 120 ? 1 : 2);
        sh_meta[n] = ((n>>4)*31 + (n&15)) | ((hr*3+wr) << 16);
    }
    // h A-fragments (once per block)
    unsigned ha[2][8];
#pragma unroll
    for (int mt = 0; mt < 2; mt++) {
        const unsigned* h0 = g_hwin + ((size_t)w*256 + qb + mt*16 + tg)*16;
        const unsigned* h1 = h0 + 8*16;
        ha[mt][0]=h0[tq];    ha[mt][1]=h1[tq];
        ha[mt][2]=h0[tq+4];  ha[mt][3]=h1[tq+4];
        ha[mt][4]=h0[tq+8];  ha[mt][5]=h1[tq+8];
        ha[mt][6]=h0[tq+12]; ha[mt][7]=h1[tq+12];
    }
    int rb[2][2], rid[2][2];
#pragma unroll
    for (int mt=0; mt<2; mt++)
#pragma unroll
        for (int h=0; h<2; h++) {
            int q = qb + mt*16 + tg + 8*h;
            rb[mt][h] = ((q>>4)+15)*31 + ((q&15)+15);
        }

    float acc_rev[2][4][4];
#pragma unroll
    for (int mt=0; mt<2; mt++)
#pragma unroll
        for (int nt=0; nt<4; nt++)
#pragma unroll
            for (int r=0; r<4; r++) acc_rev[mt][nt][r] = 0.f;

    // ================= head loop =================
    for (int hh = 0; hh < 8; hh++) {
        __syncthreads();   // prior flash reads done
        {
            const uint4* src = (const uint4*)(g_pw_qkv + hh*1664);
            uint4* dst = (uint4*)sh_wq;
            for (int j = tid; j < 416; j += 256) dst[j] = src[j];
        }
        for (int j = tid; j < 961; j += 256) sh_rpb[j] = g_rpbp[hh*964 + j];
        __syncthreads();

        // ---- QKV projection; Q stays in fragments ----
        unsigned qrl[2][4], qrh[2][4];
        __nv_bfloat16* vb = (__nv_bfloat16*)sh_v;
#pragma unroll
        for (int sec = 0; sec < 3; sec++) {
            float acc[2][4][4];
#pragma unroll
            for (int mt=0; mt<2; mt++)
#pragma unroll
                for (int nt=0; nt<4; nt++)
#pragma unroll
                    for (int r=0; r<4; r++) acc[mt][nt][r] = 0.f;
#pragma unroll
            for (int ks = 0; ks < 2; ks++) {
#pragma unroll
                for (int nt=0; nt<4; nt++) {
                    unsigned B[2];
                    B[0]=sh_wq[(8*ks+tq)*104 + sec*32 + nt*8+tg];
                    B[1]=sh_wq[(8*ks+tq+4)*104 + sec*32 + nt*8+tg];
                    mma_bf16(acc[0][nt], &ha[0][ks*4], B);
                    mma_bf16(acc[1][nt], &ha[1][ks*4], B);
                }
            }
#pragma unroll
            for (int mt=0; mt<2; mt++)
#pragma unroll
            for (int nt=0; nt<4; nt++) {
                int col = nt*8 + 2*tq;
                int r0 = qb + mt*16 + tg;
                float bb0 = sh_ball[sec*256 + hh*32 + col];
                float bb1v = sh_ball[sec*256 + hh*32 + col + 1];
                float v0=acc[mt][nt][0]+bb0, v1=acc[mt][nt][1]+bb1v;
                float v2=acc[mt][nt][2]+bb0, v3=acc[mt][nt][3]+bb1v;
                if (sec == 0) {
                    const float SC = 0.17677669529663688f;
                    qrl[mt][nt] = pk(v0*SC, v1*SC);
                    qrh[mt][nt] = pk(v2*SC, v3*SC);
                } else if (sec == 1) {
                    sh_kT[(col>>1)*264 + r0]   = pk(v0, v1);
                    sh_kT[(col>>1)*264 + r0+8] = pk(v2, v3);
                } else {
                    int r1 = r0 + 8, par = r0 & 1;
                    vb[(r0>>1)*80 + col*2     + par] = __float2bfloat16(v0);
                    vb[(r0>>1)*80 + (col+1)*2 + par] = __float2bfloat16(v1);
                    vb[(r1>>1)*80 + col*2     + par] = __float2bfloat16(v2);
                    vb[(r1>>1)*80 + (col+1)*2 + par] = __float2bfloat16(v3);
                }
            }
        }
#pragma unroll
        for (int mt=0; mt<2; mt++)
#pragma unroll
            for (int h=0; h<2; h++)
                rid[mt][h] = sh_meta[qb + mt*16 + tg + 8*h] >> 16;
        __syncthreads();

        // ---- flash attention (bounded scores; P in fragments) ----
        float psL[2] = {0.f,0.f}, psH[2] = {0.f,0.f};
        float o[2][4][4];
#pragma unroll
        for (int mt=0; mt<2; mt++)
#pragma unroll
            for (int nt=0; nt<4; nt++)
#pragma unroll
                for (int r=0; r<4; r++) o[mt][nt][r] = 0.f;

        for (int kc = 0; kc < 8; kc++) {
            int kb = kc * 32;
            float s[2][4][4];
#pragma unroll
            for (int mt=0; mt<2; mt++)
#pragma unroll
                for (int nt=0; nt<4; nt++)
#pragma unroll
                    for (int r=0; r<4; r++) s[mt][nt][r] = 0.f;
#pragma unroll
            for (int ks = 0; ks < 2; ks++) {
                unsigned A0[4] = {qrl[0][2*ks], qrh[0][2*ks], qrl[0][2*ks+1], qrh[0][2*ks+1]};
                unsigned A1[4] = {qrl[1][2*ks], qrh[1][2*ks], qrl[1][2*ks+1], qrh[1][2*ks+1]};
#pragma unroll
                for (int nt=0; nt<4; nt++) {
                    unsigned B[2];
                    int key = kb + nt*8 + tg;
                    B[0]=sh_kT[(8*ks+tq)*264 + key];
                    B[1]=sh_kT[(8*ks+tq+4)*264 + key];
                    mma_bf16(s[0][nt], A0, B);
                    mma_bf16(s[1][nt], A1, B);
                }
            }
            unsigned pl[2][4], ph[2][4];
#pragma unroll
            for (int nt=0; nt<4; nt++) {
                int k0i = kb + nt*8 + 2*tq;
                int me0 = sh_meta[k0i], me1 = sh_meta[k0i+1];
                int kf0 = me0 & 0xffff, kr0 = me0 >> 16;
                int kf1 = me1 & 0xffff, kr1 = me1 >> 16;
#pragma unroll
                for (int mt=0; mt<2; mt++) {
                    float p0 = __expf(s[mt][nt][0] + sh_rpb[rb[mt][0]-kf0] + (kr0 != rid[mt][0] ? -100.f : 0.f));
                    float p1 = __expf(s[mt][nt][1] + sh_rpb[rb[mt][0]-kf1] + (kr1 != rid[mt][0] ? -100.f : 0.f));
                    float p2 = __expf(s[mt][nt][2] + sh_rpb[rb[mt][1]-kf0] + (kr0 != rid[mt][1] ? -100.f : 0.f));
                    float p3 = __expf(s[mt][nt][3] + sh_rpb[rb[mt][1]-kf1] + (kr1 != rid[mt][1] ? -100.f : 0.f));
                    psL[mt] += p0 + p1;
                    psH[mt] += p2 + p3;
                    pl[mt][nt] = pk(p0, p1);
                    ph[mt][nt] = pk(p2, p3);
                }
            }
#pragma unroll
            for (int ks = 0; ks < 2; ks++) {
                unsigned A0[4] = {pl[0][2*ks], ph[0][2*ks], pl[0][2*ks+1], ph[0][2*ks+1]};
                unsigned A1[4] = {pl[1][2*ks], ph[1][2*ks], pl[1][2*ks+1], ph[1][2*ks+1]};
#pragma unroll
                for (int nt=0; nt<4; nt++) {
                    unsigned B[2];
                    int vr = kc*16 + ks*8 + tq;
                    B[0]=sh_v[vr*40 + nt*8+tg];
                    B[1]=sh_v[(vr+4)*40 + nt*8+tg];
                    mma_bf16(o[0][nt], A0, B);
                    mma_bf16(o[1][nt], A1, B);
                }
            }
        }
        // ---- normalize + accumulate rev projection (frag passthrough) ----
#pragma unroll
        for (int mt=0; mt<2; mt++) {
            float sL = psL[mt], sH = psH[mt];
            sL += __shfl_xor_sync(0xffffffffu, sL, 1); sL += __shfl_xor_sync(0xffffffffu, sL, 2);
            sH += __shfl_xor_sync(0xffffffffu, sH, 1); sH += __shfl_xor_sync(0xffffffffu, sH, 2);
            float i0 = 1.f/sL, i1 = 1.f/sH;
#pragma unroll
            for (int ks = 0; ks < 2; ks++) {
                unsigned A[4] = {pk(o[mt][2*ks][0]*i0,   o[mt][2*ks][1]*i0),
                                 pk(o[mt][2*ks][2]*i1,   o[mt][2*ks][3]*i1),
                                 pk(o[mt][2*ks+1][0]*i0, o[mt][2*ks+1][1]*i0),
                                 pk(o[mt][2*ks+1][2]*i1, o[mt][2*ks+1][3]*i1)};
#pragma unroll
                for (int nt=0; nt<4; nt++) {
                    unsigned B[2];
                    B[0]=sh_rev[(hh*16 + 8*ks+tq)*40 + nt*8+tg];
                    B[1]=sh_rev[(hh*16 + 8*ks+tq+4)*40 + nt*8+tg];
                    mma_bf16(acc_rev[mt][nt], A, B);
                }
            }
        }
    }
    __syncthreads();   // all heads done; kT/v dead -> reuse as sh_a

    // ---- residual + LN2 + lp1, written at un-shifted global positions ----
    unsigned* sh_a = sh_kT;   // 256 rows x stride 20
    int b = w >> 6, ww = w & 63;
    int wy = (ww >> 3)*16, wx = (ww & 7)*16;
    long tt0[2], tt1[2];
#pragma unroll
    for (int mt=0; mt<2; mt++) {
        int n0 = qb + mt*16 + tg;
        int y   = (wy + (n0 >> 4) + 8) & 127;
        int gx0 = (wx + tg + 8) & 127;
        int gx1 = (wx + tg + 16) & 127;
        long t0 = (long)b*16384 + (long)y*128 + gx0;
        long t1 = (long)b*16384 + (long)y*128 + gx1;
        tt0[mt] = t0; tt1[mt] = t1;
        float v0[4], v1[4], v2[4], v3[4];
#pragma unroll
        for (int nt=0; nt<4; nt++) {
            int col = nt*8 + 2*tq;
            float b0 = sh_f[col], b1v = sh_f[col+1];
            float2 x0 = *(const float2*)(x + t0*32 + col);
            float2 x1 = *(const float2*)(x + t1*32 + col);
            v0[nt]=acc_rev[mt][nt][0]+b0+x0.x; v1[nt]=acc_rev[mt][nt][1]+b1v+x0.y;
            v2[nt]=acc_rev[mt][nt][2]+b0+x1.x; v3[nt]=acc_rev[mt][nt][3]+b1v+x1.y;
            *(float2*)(g_xres + t0*32 + col) = make_float2(v0[nt], v1[nt]);
            *(float2*)(g_xres + t1*32 + col) = make_float2(v2[nt], v3[nt]);
        }
        float sL=0.f, qL=0.f, sH=0.f, qH=0.f;
#pragma unroll
        for (int nt=0; nt<4; nt++) {
            sL += v0[nt]+v1[nt]; qL += v0[nt]*v0[nt]+v1[nt]*v1[nt];
            sH += v2[nt]+v3[nt]; qH += v2[nt]*v2[nt]+v3[nt]*v3[nt];
        }
        sL += __shfl_xor_sync(0xffffffffu, sL, 1); sL += __shfl_xor_sync(0xffffffffu, sL, 2);
        qL += __shfl_xor_sync(0xffffffffu, qL, 1); qL += __shfl_xor_sync(0xffffffffu, qL, 2);
        sH += __shfl_xor_sync(0xffffffffu, sH, 1); sH += __shfl_xor_sync(0xffffffffu, sH, 2);
        qH += __shfl_xor_sync(0xffffffffu, qH, 1); qH += __shfl_xor_sync(0xffffffffu, qH, 2);
        float mL = sL*(1.f/32.f), mH = sH*(1.f/32.f);
        float rL = rsqrtf(qL*(1.f/32.f) - mL*mL + 1e-5f);
        float rH = rsqrtf(qH*(1.f/32.f) - mH*mH + 1e-5f);
#pragma unroll
        for (int nt=0; nt<4; nt++) {
            int col = nt*8 + 2*tq;
            float g0 = sh_f[32+col], g1 = sh_f[33+col], bt0 = sh_f[64+col], bt1 = sh_f[65+col];
            sh_a[n0*20 + nt*4+tq]     = pk((v0[nt]-mL)*rL*g0+bt0, (v1[nt]-mL)*rL*g1+bt1);
            sh_a[(n0+8)*20 + nt*4+tq] = pk((v2[nt]-mH)*rH*g0+bt0, (v3[nt]-mH)*rH*g1+bt1);
        }
    }
    __syncwarp();   // sh_a rows are warp-private

#pragma unroll
    for (int mt=0; mt<2; mt++) {
        int n0 = qb + mt*16 + tg;
        long t0 = tt0[mt], t1 = tt1[mt];
#pragma unroll
        for (int h2 = 0; h2 < 2; h2++) {
            float acc2[8][4];
#pragma unroll
            for (int nt=0; nt<8; nt++)
#pragma unroll
                for (int r=0; r<4; r++) acc2[nt][r] = 0.f;
#pragma unroll
            for (int ks = 0; ks < 2; ks++) {
                int k2b = ks*8;
                unsigned A[4];
                A[0]=sh_a[n0*20 + k2b+tq];
                A[1]=sh_a[(n0+8)*20 + k2b+tq];
                A[2]=sh_a[n0*20 + k2b+tq+4];
                A[3]=sh_a[(n0+8)*20 + k2b+tq+4];
#pragma unroll
                for (int nt=0; nt<8; nt++) {
                    unsigned B[2];
                    B[0]=sh_w1[(k2b+tq)*136 + h2*64 + nt*8+tg];
                    B[1]=sh_w1[(k2b+tq+4)*136 + h2*64 + nt*8+tg];
                    mma_bf16(acc2[nt], A, B);
                }
            }
#pragma unroll
            for (int nt=0; nt<8; nt++) {
                int col = h2*64 + nt*8 + 2*tq;
                float b0 = sh_f[96+col], b1v = sh_f[97+col];
                g_y1[t0*64 + (col>>1)] = pk(gelu_exact(acc2[nt][0]+b0), gelu_exact(acc2[nt][1]+b1v));
                g_y1[t1*64 + (col>>1)] = pk(gelu_exact(acc2[nt][2]+b0), gelu_exact(acc2[nt][3]+b1v));
            }
        }
    }
}

// ============ K5: 3x3 conv implicit GEMM + fused lp2 + residual =========
#define CIS 184
#define CONV_SMEM (25088*4)
__global__ void __launch_bounds__(256,2) k_conv(const float* __restrict__ cb,
                                                const float* __restrict__ b2,
                                                float* __restrict__ out) {
    extern __shared__ unsigned smu[];
    unsigned* sh_in = smu;               // [c2 16][pix 180] stride 184
    unsigned* sh_w  = smu + 16*CIS;      // [tap*16+c2][co 128] stride 136 (reused as sh_t)
    unsigned* sh_w2 = sh_w + 144*136;    // 64*40
    int bz = blockIdx.x;
    int b = bz >> 7;
    int y0 = ((bz >> 3) & 15) * 8;
    int x0 = (bz & 7) * 16;
    int tid = threadIdx.x, lane = tid & 31, warp = tid >> 5;
    int tg = lane >> 2, tq = lane & 3;
    int wm = warp & 1, wn = warp >> 1;

    for (int j = tid; j < 640; j += 256) ((uint4*)sh_w2)[j] = ((const uint4*)g_pw_w2)[j];

    float acc[4][4][4];
#pragma unroll
    for (int mt=0; mt<4; mt++)
#pragma unroll
        for (int nt=0; nt<4; nt++)
#pragma unroll
            for (int r=0; r<4; r++) acc[mt][nt][r] = 0.f;

    for (int ci0 = 0; ci0 < 128; ci0 += 32) {
        int c2b = ci0 >> 1;
        __syncthreads();
        for (int j = tid; j < 720; j += 256) {
            int pix = j >> 2, q = j & 3;
            int py = pix / 18, px = pix - py*18;
            int gy = y0 - 1 + py, gx = x0 - 1 + px;
            uint4 v = make_uint4(0,0,0,0);
            if ((unsigned)gy < 128u && (unsigned)gx < 128u)
                v = *(const uint4*)(g_y1 + ((size_t)(b*16384 + gy*128 + gx))*64 + c2b + q*4);
            sh_in[(q*4+0)*CIS + pix] = v.x;
            sh_in[(q*4+1)*CIS + pix] = v.y;
            sh_in[(q*4+2)*CIS + pix] = v.z;
            sh_in[(q*4+3)*CIS + pix] = v.w;
        }
        for (int j = tid; j < 4608; j += 256) {
            int row = j >> 5, q = j & 31;
            int tap = row >> 4, c2l = row & 15;
            *(uint4*)(sh_w + row*136 + q*4) =
                *(const uint4*)(g_pw_cw + ((size_t)tap*64 + c2b + c2l)*128 + q*4);
        }
        __syncthreads();
#pragma unroll
        for (int tap = 0; tap < 9; tap++) {
            int ky = tap / 3, kx = tap % 3;
#pragma unroll
            for (int ks = 0; ks < 2; ks++) {
                int k2b = ks*8;
                unsigned A[4][4];
#pragma unroll
                for (int mt=0; mt<4; mt++) {
                    int pixL = (wm*4 + mt + ky)*18 + tg + kx;
                    A[mt][0]=sh_in[(k2b+tq)*CIS + pixL];
                    A[mt][1]=sh_in[(k2b+tq)*CIS + pixL + 8];
                    A[mt][2]=sh_in[(k2b+tq+4)*CIS + pixL];
                    A[mt][3]=sh_in[(k2b+tq+4)*CIS + pixL + 8];
                }
#pragma unroll
                for (int nt=0; nt<4; nt++) {
                    unsigned B[2];
                    B[0]=sh_w[(tap*16 + k2b+tq)*136 + wn*32 + nt*8+tg];
                    B[1]=sh_w[(tap*16 + k2b+tq+4)*136 + wn*32 + nt*8+tg];
#pragma unroll
                    for (int mt=0; mt<4; mt++) mma_bf16(acc[mt][nt], A[mt], B);
                }
            }
        }
    }
    __syncthreads();
    unsigned* sh_t = sh_w;  // [pix 128][k2 64] stride 68
#pragma unroll
    for (int mt=0; mt<4; mt++) {
        int pix0 = (wm*4 + mt)*16 + tg;
#pragma unroll
        for (int nt=0; nt<4; nt++) {
            int col = wn*32 + nt*8 + 2*tq;
            int k2 = col >> 1;
            float b0 = cb[col], b1 = cb[col+1];
            sh_t[pix0*68 + k2]     = pk(gelu_exact(acc[mt][nt][0]+b0), gelu_exact(acc[mt][nt][1]+b1));
            sh_t[(pix0+8)*68 + k2] = pk(gelu_exact(acc[mt][nt][2]+b0), gelu_exact(acc[mt][nt][3]+b1));
        }
    }
    __syncthreads();
    float acc3[4][4];
#pragma unroll
    for (int nt=0; nt<4; nt++)
#pragma unroll
        for (int r=0; r<4; r++) acc3[nt][r] = 0.f;
    int rr = warp*16 + tg;
#pragma unroll
    for (int ks = 0; ks < 8; ks++) {
        int k2b = ks*8;
        unsigned A[4];
        A[0]=sh_t[rr*68 + k2b+tq];
        A[1]=sh_t[(rr+8)*68 + k2b+tq];
        A[2]=sh_t[rr*68 + k2b+tq+4];
        A[3]=sh_t[(rr+8)*68 + k2b+tq+4];
#pragma unroll
        for (int nt=0; nt<4; nt++) {
            unsigned B[2];
            B[0]=sh_w2[(k2b+tq)*40 + nt*8+tg];
            B[1]=sh_w2[(k2b+tq+4)*40 + nt*8+tg];
            mma_bf16(acc3[nt], A, B);
        }
    }
    long t0 = (long)b*16384 + (long)(y0 + warp)*128 + x0 + tg;
    long t1 = t0 + 8;
#pragma unroll
    for (int nt=0; nt<4; nt++) {
        int col = nt*8 + 2*tq;
        float b0 = b2[col], b1 = b2[col+1];
        float2 x0v = *(const float2*)(g_xres + t0*32 + col);
        float2 x1v = *(const float2*)(g_xres + t1*32 + col);
        *(float2*)(out + t0*32 + col) =
            make_float2(gelu_exact(acc3[nt][0]+b0)+x0v.x, gelu_exact(acc3[nt][1]+b1)+x0v.y);
        *(float2*)(out + t1*32 + col) =
            make_float2(gelu_exact(acc3[nt][2]+b0)+x1v.x, gelu_exact(acc3[nt][3]+b1)+x1v.y);
    }
}

extern "C" void kernel_launch(void* const* d_in, const int* in_sizes, int n_in,
                              void* d_out, int out_size) {
    const float* x    = (const float*)d_in[0];
    const float* n1g  = (const float*)d_in[1];
    const float* n1b  = (const float*)d_in[2];
    const float* modw = (const float*)d_in[3];
    const float* qkvw = (const float*)d_in[4];
    const float* qkvb = (const float*)d_in[5];
    const float* rpbt = (const float*)d_in[6];
    const float* revw = (const float*)d_in[7];
    const float* revb = (const float*)d_in[8];
    const float* n2g  = (const float*)d_in[9];
    const float* n2b  = (const float*)d_in[10];
    const float* lp1w = (const float*)d_in[11];
    const float* lp1b = (const float*)d_in[12];
    const float* convw= (const float*)d_in[13];
    const float* convb= (const float*)d_in[14];
    const float* lp2w = (const float*)d_in[15];
    const float* lp2b = (const float*)d_in[16];
    float* out = (float*)d_out;

    cudaFuncSetAttribute(k_attn, cudaFuncAttributeMaxDynamicSharedMemorySize, ATTN_SMEM);
    cudaFuncSetAttribute(k_conv, cudaFuncAttributeMaxDynamicSharedMemorySize, CONV_SMEM);

    k_pack<<<288, 256>>>(qkvw, revw, lp1w, lp2w, convw, rpbt);
    k_ln1 <<<NWIN, 256>>>(x, n1g, n1b, modw);
    k_attn<<<NWIN, 256, ATTN_SMEM>>>(x, qkvb, revb, n2g, n2b, lp1b);
    k_conv<<<BQ * 16 * 8, 256, CONV_SMEM>>>(convb, lp2b, out);
}